// round 8
// baseline (speedup 1.0000x reference)
#include <cuda_runtime.h>
#include <cuda_bf16.h>
#include <cuda_fp16.h>
#include <math.h>
#include <stdint.h>

// ---------------- scratch (uint4 => 16B alignment for cp.async) ----------------
__device__ uint4 g_attn4 [16777216];   // fp32 attn  [4][4096][4096]
__device__ uint4 g_S4    [8388608];    // half  S    [4][4096][4096]
__device__ uint4 g_xth4  [2097152];    // bf16 XT hi, 2 inputs x [4][4096][512] (style_key, style)
__device__ uint4 g_xtl4  [2097152];    // bf16 XT lo
__device__ uint4 g_Xcat4 [3145728];    // bf16 Xcat [4][4096][1536] = [Xh|Xl|Xh] (content_key)
__device__ uint4 g_Gcat4 [3145728];    // bf16 Gcat [4][4096][1536] = [G'h|G'h|G'l]
__device__ uint4 g_M4    [65536];      // fp32 M = Wf^T Wg [512][512]
__device__ uint4 g_Mh4   [32768];      // bf16 M hi/lo
__device__ uint4 g_Ml4   [32768];
__device__ uint4 g_Wh24  [32768];      // bf16 h_w hi/lo
__device__ uint4 g_Wl24  [32768];
__device__ uint4 g_HmT4  [2097152];    // fp32 Hm [4][4096][512] ([n][c])
__device__ uint4 g_Hcat4 [2097152];    // half Hcat [4][1024][4096]
__device__ uint4 g_Ccat4 [4194304];    // fp32 Ccat [4][4096][1024]
__device__ uint4 g_meanT4[2097152];    // fp32 [4][512][4096]
__device__ uint4 g_stdT4 [2097152];
__device__ uint4 g_rn4   [4096];       // fp32 rn [4][4096]
__device__ uint4 g_cm4   [4096];       // fp32 cm [4][4096]
__device__ uint4 g_wfb4  [128];        // fp32 Wf^T bg [512]
__device__ uint4 g_wgb4  [128];        // fp32 Wg^T bf [512]
__device__ uint4 g_d4    [1];          // fp32 bf.bg

// ---------------- helpers ----------------
__device__ __forceinline__ uint32_t smem_u32(const void* p) {
    uint32_t a;
    asm("{ .reg .u64 t; cvta.to.shared.u64 t, %1; cvt.u32.u64 %0, t; }" : "=r"(a) : "l"(p));
    return a;
}
__device__ __forceinline__ void cp16(uint32_t dst, const void* src) {
    asm volatile("cp.async.ca.shared.global [%0], [%1], 16;" :: "r"(dst), "l"(src));
}
__device__ __forceinline__ void ldsm4(uint32_t* r, uint32_t addr) {
    asm volatile("ldmatrix.sync.aligned.m8n8.x4.shared.b16 {%0,%1,%2,%3}, [%4];"
        : "=r"(r[0]), "=r"(r[1]), "=r"(r[2]), "=r"(r[3]) : "r"(addr));
}
__device__ __forceinline__ void mma16(float* d, const uint32_t* a, const uint32_t* b,
                                      const __nv_bfloat16*) {
    asm volatile("mma.sync.aligned.m16n8k16.row.col.f32.bf16.bf16.f32 "
        "{%0,%1,%2,%3}, {%4,%5,%6,%7}, {%8,%9}, {%0,%1,%2,%3};"
        : "+f"(d[0]), "+f"(d[1]), "+f"(d[2]), "+f"(d[3])
        : "r"(a[0]), "r"(a[1]), "r"(a[2]), "r"(a[3]), "r"(b[0]), "r"(b[1]));
}
__device__ __forceinline__ void mma16(float* d, const uint32_t* a, const uint32_t* b,
                                      const half*) {
    asm volatile("mma.sync.aligned.m16n8k16.row.col.f32.f16.f16.f32 "
        "{%0,%1,%2,%3}, {%4,%5,%6,%7}, {%8,%9}, {%0,%1,%2,%3};"
        : "+f"(d[0]), "+f"(d[1]), "+f"(d[2]), "+f"(d[3])
        : "r"(a[0]), "r"(a[1]), "r"(a[2]), "r"(a[3]), "r"(b[0]), "r"(b[1]));
}

// FMA-only exp (Schraudolph round + deg-6 Taylor of 2^f), rel err ~1.5e-7.
__device__ __forceinline__ float fast_exp(float x) {
    x = fmaxf(x, -80.f);
    float t = x * 1.44269504088896f;
    float z = t + 12582912.f;
    int   i = __float_as_int(z) - 0x4B400000;
    float f = t - (z - 12582912.f);
    float p = 1.53989037e-4f;
    p = fmaf(p, f, 1.33335581e-3f);
    p = fmaf(p, f, 9.61812910e-3f);
    p = fmaf(p, f, 5.55041087e-2f);
    p = fmaf(p, f, 2.40226507e-1f);
    p = fmaf(p, f, 6.93147181e-1f);
    p = fmaf(p, f, 1.0f);
    return __int_as_float(__float_as_int(p) + (i << 23));
}

// FMA-only sqrt via bit-hack rsqrt + 2 Newton iters.
__device__ __forceinline__ float fast_sqrt(float v) {
    float x = fmaxf(v, 1e-30f);
    float xh = 0.5f * x;
    float y = __int_as_float(0x5f375a86 - (__float_as_int(x) >> 1));
    y = y * fmaf(-xh, y * y, 1.5f);
    y = y * fmaf(-xh, y * y, 1.5f);
    return v * y;
}

// ---------------- GEMM: C[b][m][n] = sum_k A[m][k]*B[n][k] ----------------
// TERMS=3: AhBh+AlBh+AhBl (error-compensated); TERMS=1: hi only.
// Block 128x128xKCH, 8 warps (2m x 4n), warp tile 64x32, cp.async double buffer,
// ldmatrix loads. OUTM: 0=fp32, 2=bf16 cat [hi|hi|lo] stride 1536.
// RK1: add rvec[b][m] + cvec[b][n] in epilogue (rank-1 bias fold).
template<typename T, int TERMS, int KCH, int OUTM, int HAS_BIAS, int RK1>
__global__ __launch_bounds__(256, 2) void gemm16(
    const T* __restrict__ Ah, const T* __restrict__ Al,
    const T* __restrict__ Bh, const T* __restrict__ Bl,
    const float* __restrict__ bias,
    const float* __restrict__ rvec, const float* __restrict__ cvec,
    float* __restrict__ Cf, T* __restrict__ Ch,
    int M, int N, int K, size_t sA, size_t sB)
{
    extern __shared__ char smem[];
    const int tid = threadIdx.x, lane = tid & 31, wid = tid >> 5;
    const int b = blockIdx.z;
    const int n0 = blockIdx.x * 128, m0 = blockIdx.y * 128;
    const T* Agh = Ah + (size_t)b * sA + (size_t)m0 * K;
    const T* Bgh = Bh + (size_t)b * sB + (size_t)n0 * K;
    const T* Agl = (TERMS == 3) ? (Al + (size_t)b * sA + (size_t)m0 * K) : nullptr;
    const T* Bgl = (TERMS == 3) ? (Bl + (size_t)b * sB + (size_t)n0 * K) : nullptr;

    const uint32_t sb = smem_u32(smem);
    constexpr uint32_t ST  = KCH * 2 + 16;
    constexpr uint32_t TL  = 128u * ST;
    constexpr uint32_t BUF = (TERMS == 3 ? 4u : 2u) * TL;
    constexpr int LPR = KCH / 8;
    constexpr int PP  = (128 * LPR) / 256;

    const int wm = (wid >> 2) * 64, wn = (wid & 3) * 32;

    float acc[4][4][4];
    #pragma unroll
    for (int i = 0; i < 4; i++)
        #pragma unroll
        for (int j = 0; j < 4; j++)
            #pragma unroll
            for (int r = 0; r < 4; r++) acc[i][j][r] = 0.f;

    auto stage = [&](int ch, int buf) {
        uint32_t base = sb + buf * BUF;
        #pragma unroll
        for (int it = 0; it < PP; it++) {
            int idx = tid + it * 256;
            int r = idx / LPR, f = idx % LPR;
            uint32_t off = r * ST + f * 16;
            size_t go = (size_t)r * K + ch * KCH + f * 8;
            cp16(base + off, Agh + go);
            cp16(base + TL + off, Bgh + go);
            if (TERMS == 3) {
                cp16(base + 2 * TL + off, Agl + go);
                cp16(base + 3 * TL + off, Bgl + go);
            }
        }
        asm volatile("cp.async.commit_group;" ::: "memory");
    };

    const int t8 = lane >> 3, rr = lane & 7;
    const uint32_t a_off = (uint32_t)((t8 & 1) * 8 + rr) * ST + (t8 >> 1) * 16;
    const uint32_t b_off = (uint32_t)((t8 >> 1) * 8 + rr) * ST + (t8 & 1) * 16;

    const int NC = K / KCH;
    stage(0, 0);
    for (int ch = 0; ch < NC; ch++) {
        const int buf = ch & 1;
        if (ch + 1 < NC) {
            stage(ch + 1, buf ^ 1);
            asm volatile("cp.async.wait_group 1;" ::: "memory");
        } else {
            asm volatile("cp.async.wait_group 0;" ::: "memory");
        }
        __syncthreads();

        const uint32_t ab = sb + buf * BUF;
        const uint32_t bb = ab + TL;

        #pragma unroll
        for (int k16 = 0; k16 < KCH / 16; k16++) {
            const uint32_t kb = k16 * 32;
            uint32_t bhf[4][2], blf[4][2];
            #pragma unroll
            for (int pr = 0; pr < 2; pr++) {
                uint32_t r4[4];
                ldsm4(r4, bb + (uint32_t)(wn + pr * 16) * ST + b_off + kb);
                bhf[pr * 2][0] = r4[0]; bhf[pr * 2][1] = r4[1];
                bhf[pr * 2 + 1][0] = r4[2]; bhf[pr * 2 + 1][1] = r4[3];
                if (TERMS == 3) {
                    ldsm4(r4, bb + 2 * TL + (uint32_t)(wn + pr * 16) * ST + b_off + kb);
                    blf[pr * 2][0] = r4[0]; blf[pr * 2][1] = r4[1];
                    blf[pr * 2 + 1][0] = r4[2]; blf[pr * 2 + 1][1] = r4[3];
                }
            }
            #pragma unroll
            for (int im = 0; im < 4; im++) {
                uint32_t af[4];
                ldsm4(af, ab + (uint32_t)(wm + im * 16) * ST + a_off + kb);
                #pragma unroll
                for (int jn = 0; jn < 4; jn++) {
                    mma16(acc[im][jn], af, bhf[jn], (const T*)nullptr);
                    if (TERMS == 3) mma16(acc[im][jn], af, blf[jn], (const T*)nullptr);
                }
                if (TERMS == 3) {
                    uint32_t alf[4];
                    ldsm4(alf, ab + 2 * TL + (uint32_t)(wm + im * 16) * ST + a_off + kb);
                    #pragma unroll
                    for (int jn = 0; jn < 4; jn++)
                        mma16(acc[im][jn], alf, bhf[jn], (const T*)nullptr);
                }
            }
        }
        __syncthreads();
    }

    // epilogue
    #pragma unroll
    for (int im = 0; im < 4; im++) {
        int r = m0 + wm + im * 16 + (lane >> 2);
        float rv0 = 0.f, rv1 = 0.f;
        if (RK1) {
            rv0 = __ldg(&rvec[(size_t)b * 4096 + r]);
            rv1 = __ldg(&rvec[(size_t)b * 4096 + r + 8]);
        }
        #pragma unroll
        for (int jn = 0; jn < 4; jn++) {
            int cc = n0 + wn + jn * 8 + (lane & 3) * 2;
            float b0 = 0.f, b1 = 0.f;
            if (HAS_BIAS) { b0 = __ldg(&bias[cc]); b1 = __ldg(&bias[cc + 1]); }
            if (RK1) {
                float c0v = __ldg(&cvec[(size_t)b * 4096 + cc]);
                float c1v = __ldg(&cvec[(size_t)b * 4096 + cc + 1]);
                b0 += c0v; b1 += c1v;
            }
            float v00 = acc[im][jn][0] + b0 + (RK1 ? rv0 : 0.f);
            float v01 = acc[im][jn][1] + b1 + (RK1 ? rv0 : 0.f);
            float v10 = acc[im][jn][2] + b0 + (RK1 ? rv1 : 0.f);
            float v11 = acc[im][jn][3] + b1 + (RK1 ? rv1 : 0.f);
            if constexpr (OUTM == 2) {
                // Gcat: [hi|hi|lo], row stride 1536
                size_t ob0 = ((size_t)b * M + r) * 1536 + cc;
                size_t ob1 = ob0 + (size_t)8 * 1536;
                __nv_bfloat16 h00 = __float2bfloat16_rn(v00), h01 = __float2bfloat16_rn(v01);
                __nv_bfloat16 h10 = __float2bfloat16_rn(v10), h11 = __float2bfloat16_rn(v11);
                __nv_bfloat162 H0(h00, h01), H1(h10, h11);
                __nv_bfloat162 L0(__float2bfloat16_rn(v00 - __bfloat162float(h00)),
                                  __float2bfloat16_rn(v01 - __bfloat162float(h01)));
                __nv_bfloat162 L1(__float2bfloat16_rn(v10 - __bfloat162float(h10)),
                                  __float2bfloat16_rn(v11 - __bfloat162float(h11)));
                __nv_bfloat16* Cb = (__nv_bfloat16*)Ch;
                *(__nv_bfloat162*)(Cb + ob0)        = H0;
                *(__nv_bfloat162*)(Cb + ob0 + 512)  = H0;
                *(__nv_bfloat162*)(Cb + ob0 + 1024) = L0;
                *(__nv_bfloat162*)(Cb + ob1)        = H1;
                *(__nv_bfloat162*)(Cb + ob1 + 512)  = H1;
                *(__nv_bfloat162*)(Cb + ob1 + 1024) = L1;
            } else {
                size_t o0 = (size_t)b * (size_t)M * N + (size_t)r * N + cc;
                size_t o1 = o0 + (size_t)8 * N;
                *(float2*)(Cf + o0) = make_float2(v00, v01);
                *(float2*)(Cf + o1) = make_float2(v10, v11);
            }
        }
    }
}

// ---------------- M = Wf^T Wg (fp32, exact-ish) ----------------
__global__ void wtw_gemm(const float* __restrict__ Wf, const float* __restrict__ Wg,
                         float* __restrict__ Mo)
{
    __shared__ float a[32][33], bsm[32][33];
    int c0 = blockIdx.y * 32, p0 = blockIdx.x * 32;
    int tx = threadIdx.x, ty = threadIdx.y;   // (32, 8)
    float acc[4] = {0.f, 0.f, 0.f, 0.f};
    for (int o0 = 0; o0 < 512; o0 += 32) {
        #pragma unroll
        for (int k = 0; k < 4; k++) {
            a[ty + k * 8][tx]   = Wf[(o0 + ty + k * 8) * 512 + c0 + tx];
            bsm[ty + k * 8][tx] = Wg[(o0 + ty + k * 8) * 512 + p0 + tx];
        }
        __syncthreads();
        #pragma unroll
        for (int oo = 0; oo < 32; oo++) {
            float bv = bsm[oo][tx];
            #pragma unroll
            for (int k = 0; k < 4; k++)
                acc[k] = fmaf(a[oo][ty + k * 8], bv, acc[k]);
        }
        __syncthreads();
    }
    #pragma unroll
    for (int k = 0; k < 4; k++)
        Mo[(c0 + ty + k * 8) * 512 + p0 + tx] = acc[k];
}

// out[c] = sum_o W[o][c] * v[o]
__global__ void bias_vec(const float* __restrict__ W, const float* __restrict__ v,
                         float* __restrict__ out)
{
    int c = blockIdx.x * 128 + threadIdx.x;
    float s = 0.f;
    for (int o = 0; o < 512; o++) s = fmaf(W[o * 512 + c], v[o], s);
    out[c] = s;
}

// ---------------- block reductions ----------------
__device__ __forceinline__ float block_reduce_max(float v, float* red) {
    #pragma unroll
    for (int o = 16; o > 0; o >>= 1) v = fmaxf(v, __shfl_xor_sync(0xffffffffu, v, o));
    int wid = threadIdx.x >> 5, lid = threadIdx.x & 31;
    if (lid == 0) red[wid] = v;
    __syncthreads();
    if (wid == 0) {
        v = (lid < 8) ? red[lid] : -1e30f;
        #pragma unroll
        for (int o = 4; o > 0; o >>= 1) v = fmaxf(v, __shfl_xor_sync(0xffffffffu, v, o));
        if (lid == 0) red[0] = v;
    }
    __syncthreads();
    float r = red[0];
    __syncthreads();
    return r;
}
__device__ __forceinline__ float block_reduce_sum(float v, float* red) {
    #pragma unroll
    for (int o = 16; o > 0; o >>= 1) v += __shfl_xor_sync(0xffffffffu, v, o);
    int wid = threadIdx.x >> 5, lid = threadIdx.x & 31;
    if (lid == 0) red[wid] = v;
    __syncthreads();
    if (wid == 0) {
        v = (lid < 8) ? red[lid] : 0.f;
        #pragma unroll
        for (int o = 4; o > 0; o >>= 1) v += __shfl_xor_sync(0xffffffffu, v, o);
        if (lid == 0) red[0] = v;
    }
    __syncthreads();
    float r = red[0];
    __syncthreads();
    return r;
}

__global__ void dot512(const float* __restrict__ a, const float* __restrict__ b,
                       float* __restrict__ out)
{
    __shared__ float red[32];
    int t = threadIdx.x;
    float s = fmaf(a[t], b[t], a[t + 256] * b[t + 256]);
    s = block_reduce_sum(s, red);
    if (t == 0) out[0] = s;
}

// out[b][n] = sum_c key[b][c][n] * wv[c] (+ *dptr)
__global__ void rank1_gemv(const float* __restrict__ key, const float* __restrict__ wv,
                           const float* __restrict__ dptr, float* __restrict__ out)
{
    int n = blockIdx.x * 256 + threadIdx.x;
    int b = blockIdx.y;
    const float* kb = key + (size_t)b * 512ull * 4096ull + n;
    float s = dptr ? __ldg(dptr) : 0.f;
    #pragma unroll 4
    for (int c = 0; c < 512; c++)
        s = fmaf(__ldg(kb + (size_t)c * 4096), __ldg(&wv[c]), s);
    out[b * 4096 + n] = s;
}

// ---------------- transpose+split: fp32 [b][512][4096] -> hi/lo bf16 [b][4096][512] ----------------
__global__ void transpose_split(const float* __restrict__ src,
                                __nv_bfloat16* __restrict__ dh, __nv_bfloat16* __restrict__ dl)
{
    __shared__ float t[32][33];
    int b = blockIdx.z;
    const float* s = src + (size_t)b * 512ull * 4096ull;
    size_t dbo = (size_t)b * 512ull * 4096ull;
    int c0 = blockIdx.x * 32, r0 = blockIdx.y * 32;
    int tx = threadIdx.x, ty = threadIdx.y;
    #pragma unroll
    for (int k = 0; k < 4; k++)
        t[ty + k * 8][tx] = s[(size_t)(r0 + ty + k * 8) * 4096 + c0 + tx];
    __syncthreads();
    #pragma unroll
    for (int k = 0; k < 4; k++) {
        float v = t[tx][ty + k * 8];
        size_t o = dbo + (size_t)(c0 + ty + k * 8) * 512 + r0 + tx;
        __nv_bfloat16 h = __float2bfloat16_rn(v);
        dh[o] = h;
        dl[o] = __float2bfloat16_rn(v - __bfloat162float(h));
    }
}

// fp32 [b][512][4096] -> Xcat bf16 [b][4096][1536] = [hi | lo | hi]
__global__ void transpose_split_cat(const float* __restrict__ src,
                                    __nv_bfloat16* __restrict__ dst)
{
    __shared__ float t[32][33];
    int b = blockIdx.z;
    const float* s = src + (size_t)b * 512ull * 4096ull;
    size_t dbo = (size_t)b * 4096ull * 1536ull;
    int c0 = blockIdx.x * 32, r0 = blockIdx.y * 32;
    int tx = threadIdx.x, ty = threadIdx.y;
    #pragma unroll
    for (int k = 0; k < 4; k++)
        t[ty + k * 8][tx] = s[(size_t)(r0 + ty + k * 8) * 4096 + c0 + tx];
    __syncthreads();
    #pragma unroll
    for (int k = 0; k < 4; k++) {
        float v = t[tx][ty + k * 8];
        size_t o = dbo + (size_t)(c0 + ty + k * 8) * 1536 + r0 + tx;
        __nv_bfloat16 h = __float2bfloat16_rn(v);
        dst[o] = h;
        dst[o + 512]  = __float2bfloat16_rn(v - __bfloat162float(h));
        dst[o + 1024] = h;
    }
}

__global__ void weight_split(const float* __restrict__ w,
                             __nv_bfloat16* __restrict__ wh, __nv_bfloat16* __restrict__ wl, int n)
{
    int i = blockIdx.x * 256 + threadIdx.x;
    if (i < n) {
        float v = w[i];
        __nv_bfloat16 h = __float2bfloat16_rn(v);
        wh[i] = h;
        wl[i] = __float2bfloat16_rn(v - __bfloat162float(h));
    }
}

// HmT fp32 [b][4096(n)][512(c)] -> Hcat half [b][1024][4096]: [H ; H^2]
__global__ void transpose_sq_half(const float* __restrict__ src, half* __restrict__ dst)
{
    __shared__ float t[32][33];
    int b = blockIdx.z;
    const float* s = src + (size_t)b * 4096ull * 512ull;
    half* d = dst + (size_t)b * 1024ull * 4096ull;
    int c0 = blockIdx.x * 32, n0 = blockIdx.y * 32;
    int tx = threadIdx.x, ty = threadIdx.y;
    #pragma unroll
    for (int k = 0; k < 4; k++)
        t[ty + k * 8][tx] = s[(size_t)(n0 + ty + k * 8) * 512 + c0 + tx];
    __syncthreads();
    #pragma unroll
    for (int k = 0; k < 4; k++) {
        float v = t[tx][ty + k * 8];
        d[(size_t)(c0 + ty + k * 8) * 4096 + n0 + tx] = __float2half_rn(v);
        d[(size_t)(512 + c0 + ty + k * 8) * 4096 + n0 + tx] = __float2half_rn(v * v);
    }
}

// Ccat [b][n][1024] -> meanT/stdT [b][c][n]
__global__ void meanstd_transpose(const float* __restrict__ Ccat,
                                  float* __restrict__ meanT, float* __restrict__ stdT)
{
    __shared__ float tm[32][33], ts[32][33];
    int b = blockIdx.z;
    int c0 = blockIdx.x * 32, n0 = blockIdx.y * 32;
    const float* Cb = Ccat + (size_t)b * 4096ull * 1024ull;
    int tx = threadIdx.x, ty = threadIdx.y;
    #pragma unroll
    for (int k = 0; k < 4; k++) {
        int n = n0 + ty + k * 8;
        float mn = Cb[(size_t)n * 1024 + c0 + tx];
        float sc = Cb[(size_t)n * 1024 + 512 + c0 + tx];
        tm[ty + k * 8][tx] = mn;
        ts[ty + k * 8][tx] = fast_sqrt(fmaxf(sc - mn * mn, 0.f));
    }
    __syncthreads();
    size_t ob = (size_t)b * 512ull * 4096ull;
    #pragma unroll
    for (int k = 0; k < 4; k++) {
        int c = c0 + ty + k * 8;
        meanT[ob + (size_t)c * 4096 + n0 + tx] = tm[tx][ty + k * 8];
        stdT [ob + (size_t)c * 4096 + n0 + tx] = ts[tx][ty + k * 8];
    }
}

// ---------------- softmax mix: fp32 in -> half S out ----------------
__global__ __launch_bounds__(256) void softmax_mix_kernel(
    const float* __restrict__ attn, half* __restrict__ S, const float* __restrict__ w_mix)
{
    __shared__ float e1s[4096];
    __shared__ float red[32];
    const float* p = attn + (size_t)blockIdx.x * 4096;
    half* q = S + (size_t)blockIdx.x * 4096;
    int tid = threadIdx.x;

    float lmax = -1e30f;
    for (int i = tid; i < 4096; i += 256) {
        float v = p[i];
        e1s[i] = v;
        lmax = fmaxf(lmax, v);
    }
    float m1 = block_reduce_max(lmax, red);
    float m2 = fmaxf(m1, 0.f);
    float Cneg = fast_exp(-m2);

    float z1 = 0.f, z2p = 0.f, nneg = 0.f;
    for (int i = tid; i < 4096; i += 256) {
        float v = e1s[i];
        float e1 = fast_exp(v - m1);
        bool pos = v > 0.f;
        z1 += e1;
        if (pos) z2p += e1; else nneg += 1.f;
        e1s[i] = pos ? e1 : -e1;
    }
    float Z1 = block_reduce_sum(z1, red);
    float Z2 = block_reduce_sum(z2p, red) + block_reduce_sum(nneg, red) * Cneg;

    float ew0 = fast_exp(w_mix[0]), ew1 = fast_exp(w_mix[1]);
    float inv = 1.f / (ew0 + ew1);
    float iz1 = (ew0 * inv) / Z1;
    float iz2 = (ew1 * inv) / Z2;
    float Cn2 = Cneg * iz2;

    float za = 0.f;
    for (int i = tid; i < 4096; i += 256) {
        float se = e1s[i];
        float e1 = fabsf(se);
        float A = (se > 0.f) ? e1 * (iz1 + iz2) : fmaf(e1, iz1, Cn2);
        float e = fast_exp(A);
        e1s[i] = e;
        za += e;
    }
    float ZA = block_reduce_sum(za, red);
    float izA = 1.f / ZA;
    for (int i = tid; i < 4096; i += 256)
        q[i] = __float2half_rn(e1s[i] * izA);
}

// ---------------- finalize: out = stdT * mvn(content) + meanT ----------------
__global__ __launch_bounds__(256) void finalize_kernel(
    const float* __restrict__ content, const float* __restrict__ meanT,
    const float* __restrict__ stdT, float* __restrict__ out)
{
    __shared__ float red[32];
    int c = blockIdx.x, b = blockIdx.y;
    size_t off = ((size_t)b * 512 + c) * 4096;
    const float* x = content + off;
    int tid = threadIdx.x;

    float s = 0.f, ss = 0.f;
    for (int i = tid; i < 4096; i += 256) {
        float v = x[i];
        s += v; ss += v * v;
    }
    s = block_reduce_sum(s, red);
    ss = block_reduce_sum(ss, red);
    float mu = s * (1.f / 4096.f);
    float var = (ss - 4096.f * mu * mu) * (1.f / 4095.f);
    float rstd = rsqrtf(var + 1e-5f);

    for (int i = tid; i < 4096; i += 256)
        out[off + i] = stdT[off + i] * ((x[i] - mu) * rstd) + meanT[off + i];
}

// ---------------- launch ----------------
extern "C" void kernel_launch(void* const* d_in, const int* in_sizes, int n_in,
                              void* d_out, int out_size)
{
    const float* content     = (const float*)d_in[0];
    const float* style       = (const float*)d_in[1];
    const float* content_key = (const float*)d_in[2];
    const float* style_key   = (const float*)d_in[3];
    const float* f_w = (const float*)d_in[4];
    const float* f_b = (const float*)d_in[5];
    const float* g_w = (const float*)d_in[6];
    const float* g_b = (const float*)d_in[7];
    const float* h_w = (const float*)d_in[8];
    const float* h_b = (const float*)d_in[9];
    const float* w_mix = (const float*)d_in[10];
    float* out = (float*)d_out;

    typedef __nv_bfloat16 bf16;
    void *p;
    cudaGetSymbolAddress(&p, g_attn4);  float* attn = (float*)p;
    cudaGetSymbolAddress(&p, g_S4);     half*  S    = (half*)p;
    cudaGetSymbolAddress(&p, g_xth4);   bf16*  XTh  = (bf16*)p;
    cudaGetSymbolAddress(&p, g_xtl4);   bf16*  XTl  = (bf16*)p;
    cudaGetSymbolAddress(&p, g_Xcat4);  bf16*  Xcat = (bf16*)p;
    cudaGetSymbolAddress(&p, g_Gcat4);  bf16*  Gcat = (bf16*)p;
    cudaGetSymbolAddress(&p, g_M4);     float* Mbuf = (float*)p;
    cudaGetSymbolAddress(&p, g_Mh4);    bf16*  Mh   = (bf16*)p;
    cudaGetSymbolAddress(&p, g_Ml4);    bf16*  Ml   = (bf16*)p;
    cudaGetSymbolAddress(&p, g_Wh24);   bf16*  Wh2  = (bf16*)p;
    cudaGetSymbolAddress(&p, g_Wl24);   bf16*  Wl2  = (bf16*)p;
    cudaGetSymbolAddress(&p, g_HmT4);   float* HmT  = (float*)p;
    cudaGetSymbolAddress(&p, g_Hcat4);  half*  Hcat = (half*)p;
    cudaGetSymbolAddress(&p, g_Ccat4);  float* Ccat = (float*)p;
    cudaGetSymbolAddress(&p, g_meanT4); float* meanT= (float*)p;
    cudaGetSymbolAddress(&p, g_stdT4);  float* stdT = (float*)p;
    cudaGetSymbolAddress(&p, g_rn4);    float* rn   = (float*)p;
    cudaGetSymbolAddress(&p, g_cm4);    float* cm   = (float*)p;
    cudaGetSymbolAddress(&p, g_wfb4);   float* wfb  = (float*)p;
    cudaGetSymbolAddress(&p, g_wgb4);   float* wgb  = (float*)p;
    cudaGetSymbolAddress(&p, g_d4);     float* dsc  = (float*)p;

    const size_t XN = 4ull * 4096 * 512;

    const int SM3 = 2 * 4 * (128 * 80);    // 81920  (TERMS=3, KCH=32)
    const int SM1 = 2 * 2 * (128 * 144);   // 73728  (TERMS=1, KCH=64)
    cudaFuncSetAttribute((gemm16<bf16,3,32,2,0,0>), cudaFuncAttributeMaxDynamicSharedMemorySize, SM3);
    cudaFuncSetAttribute((gemm16<bf16,3,32,0,1,0>), cudaFuncAttributeMaxDynamicSharedMemorySize, SM3);
    cudaFuncSetAttribute((gemm16<bf16,1,64,0,0,1>), cudaFuncAttributeMaxDynamicSharedMemorySize, SM1);
    cudaFuncSetAttribute((gemm16<half,1,64,0,0,0>), cudaFuncAttributeMaxDynamicSharedMemorySize, SM1);

    // 0) fold Wf^T Wg -> M (fp32), split; rank-1 bias vectors
    wtw_gemm<<<dim3(16, 16), dim3(32, 8)>>>(f_w, g_w, Mbuf);
    weight_split<<<dim3(1024), 256>>>(Mbuf, Mh, Ml, 262144);
    weight_split<<<dim3(1024), 256>>>(h_w, Wh2, Wl2, 262144);
    bias_vec<<<4, 128>>>(f_w, g_b, wfb);     // wfb = Wf^T bg
    bias_vec<<<4, 128>>>(g_w, f_b, wgb);     // wgb = Wg^T bf
    dot512<<<1, 256>>>(f_b, g_b, dsc);       // d = bf . bg

    // 1) input transposes/splits
    transpose_split_cat<<<dim3(128, 16, 4), dim3(32, 8)>>>(content_key, Xcat);
    transpose_split<<<dim3(128, 16, 4), dim3(32, 8)>>>(style_key, XTh + 0 * XN, XTl + 0 * XN);
    transpose_split<<<dim3(128, 16, 4), dim3(32, 8)>>>(style,     XTh + 1 * XN, XTl + 1 * XN);

    // rank-1 logit corrections: rn[b][n] = x_n.wfb + d ; cm[b][m] = y_m.wgb
    rank1_gemv<<<dim3(16, 4), 256>>>(content_key, wfb, dsc, rn);
    rank1_gemv<<<dim3(16, 4), 256>>>(style_key, wgb, nullptr, cm);

    // 2) G' = M . style_key (bf16x3) -> Gcat [hi|hi|lo]
    gemm16<bf16,3,32,2,0,0><<<dim3(4, 32, 4), 256, SM3>>>(
        XTh + 0 * XN, XTl + 0 * XN, Mh, Ml, nullptr, nullptr, nullptr,
        nullptr, Gcat, 4096, 512, 512, 4096ull * 512, 0);

    //    H conv (bf16x3): HmT fp32 [n][c]
    gemm16<bf16,3,32,0,1,0><<<dim3(4, 32, 4), 256, SM3>>>(
        XTh + 1 * XN, XTl + 1 * XN, Wh2, Wl2, h_b, nullptr, nullptr,
        HmT, nullptr, 4096, 512, 512, 4096ull * 512, 0);

    // 3) Hcat half [b][1024][4096] = [H[c][n] ; H^2]
    transpose_sq_half<<<dim3(16, 128, 4), dim3(32, 8)>>>(HmT, Hcat);

    // 4) attention logits: single 1-term GEMM over K=1536 (= AhBh+AlBh+AhBl) + rank-1
    gemm16<bf16,1,64,0,0,1><<<dim3(32, 32, 4), 256, SM1>>>(
        Xcat, nullptr, Gcat, nullptr, nullptr, rn, cm,
        attn, nullptr, 4096, 4096, 1536, 4096ull * 1536, 4096ull * 1536);

    // 5) triple-softmax mix -> S half
    softmax_mix_kernel<<<16384, 256>>>(attn, S, w_mix);

    // 6) mean/second GEMM (fp16, KCH=64): Ccat[n][1024] = S[n][m] * Hcat[cc][m]
    gemm16<half,1,64,0,0,0><<<dim3(8, 32, 4), 256, SM1>>>(
        S, nullptr, Hcat, nullptr, nullptr, nullptr, nullptr,
        Ccat, nullptr, 4096, 1024, 4096, 4096ull * 4096, 1024ull * 4096);

    // 7) Ccat -> meanT/stdT [b][c][n]
    meanstd_transpose<<<dim3(16, 128, 4), dim3(32, 8)>>>(Ccat, meanT, stdT);

    // 8) finalize
    finalize_kernel<<<dim3(512, 4), 256>>>(content, meanT, stdT, out);
}

// round 9
// speedup vs baseline: 1.0756x; 1.0756x over previous
#include <cuda_runtime.h>
#include <cuda_bf16.h>
#include <cuda_fp16.h>
#include <math.h>
#include <stdint.h>

// ---------------- scratch (uint4 => 16B alignment for cp.async) ----------------
__device__ uint4 g_attn4 [8388608];    // half attn/S (in-place) [4][4096][4096]
__device__ uint4 g_xth4  [3145728];    // bf16 XT hi, 3 inputs x [4][4096][512]
__device__ uint4 g_xtl4  [3145728];    // bf16 XT lo
__device__ uint4 g_wh4   [98304];      // bf16 W hi, 3 x [512][512]
__device__ uint4 g_wl4   [98304];
__device__ uint4 g_Fh4   [1048576];    // bf16 Fm hi [4][4096][512]
__device__ uint4 g_Fl4   [1048576];
__device__ uint4 g_Gh4   [1048576];
__device__ uint4 g_Gl4   [1048576];
__device__ uint4 g_HmT4  [2097152];    // fp32 Hm [4][4096][512] ([n][c])
__device__ uint4 g_Hcat4 [2097152];    // half Hcat [4][1024][4096]
__device__ uint4 g_Ccat4 [4194304];    // fp32 Ccat [4][4096][1024]
__device__ uint4 g_meanT4[2097152];    // fp32 [4][512][4096]
__device__ uint4 g_stdT4 [2097152];

// ---------------- helpers ----------------
__device__ __forceinline__ uint32_t smem_u32(const void* p) {
    uint32_t a;
    asm("{ .reg .u64 t; cvta.to.shared.u64 t, %1; cvt.u32.u64 %0, t; }" : "=r"(a) : "l"(p));
    return a;
}
__device__ __forceinline__ void cp16(uint32_t dst, const void* src) {
    asm volatile("cp.async.ca.shared.global [%0], [%1], 16;" :: "r"(dst), "l"(src));
}
__device__ __forceinline__ void ldsm4(uint32_t* r, uint32_t addr) {
    asm volatile("ldmatrix.sync.aligned.m8n8.x4.shared.b16 {%0,%1,%2,%3}, [%4];"
        : "=r"(r[0]), "=r"(r[1]), "=r"(r[2]), "=r"(r[3]) : "r"(addr));
}
__device__ __forceinline__ void mma16(float* d, const uint32_t* a, const uint32_t* b,
                                      const __nv_bfloat16*) {
    asm volatile("mma.sync.aligned.m16n8k16.row.col.f32.bf16.bf16.f32 "
        "{%0,%1,%2,%3}, {%4,%5,%6,%7}, {%8,%9}, {%0,%1,%2,%3};"
        : "+f"(d[0]), "+f"(d[1]), "+f"(d[2]), "+f"(d[3])
        : "r"(a[0]), "r"(a[1]), "r"(a[2]), "r"(a[3]), "r"(b[0]), "r"(b[1]));
}
__device__ __forceinline__ void mma16(float* d, const uint32_t* a, const uint32_t* b,
                                      const half*) {
    asm volatile("mma.sync.aligned.m16n8k16.row.col.f32.f16.f16.f32 "
        "{%0,%1,%2,%3}, {%4,%5,%6,%7}, {%8,%9}, {%0,%1,%2,%3};"
        : "+f"(d[0]), "+f"(d[1]), "+f"(d[2]), "+f"(d[3])
        : "r"(a[0]), "r"(a[1]), "r"(a[2]), "r"(a[3]), "r"(b[0]), "r"(b[1]));
}

// FMA-only exp (Schraudolph round + deg-6 Taylor of 2^f), rel err ~1.5e-7.
__device__ __forceinline__ float fast_exp(float x) {
    x = fmaxf(x, -80.f);
    float t = x * 1.44269504088896f;
    float z = t + 12582912.f;
    int   i = __float_as_int(z) - 0x4B400000;
    float f = t - (z - 12582912.f);
    float p = 1.53989037e-4f;
    p = fmaf(p, f, 1.33335581e-3f);
    p = fmaf(p, f, 9.61812910e-3f);
    p = fmaf(p, f, 5.55041087e-2f);
    p = fmaf(p, f, 2.40226507e-1f);
    p = fmaf(p, f, 6.93147181e-1f);
    p = fmaf(p, f, 1.0f);
    return __int_as_float(__float_as_int(p) + (i << 23));
}

// FMA-only sqrt via bit-hack rsqrt + 2 Newton iters.
__device__ __forceinline__ float fast_sqrt(float v) {
    float x = fmaxf(v, 1e-30f);
    float xh = 0.5f * x;
    float y = __int_as_float(0x5f375a86 - (__float_as_int(x) >> 1));
    y = y * fmaf(-xh, y * y, 1.5f);
    y = y * fmaf(-xh, y * y, 1.5f);
    return v * y;
}

// ---------------- GEMM: C[b][m][n] = sum_k A[m][k]*B[n][k] (+bias[n]) ----------------
// TERMS=3: AhBh+AlBh+AhBl; TERMS=1: hi only. Block 128x128xKCH, 8 warps (2m x 4n),
// warp tile 64x32, cp.async double buffer, ldmatrix loads.
// OUTM: 0 = fp32 (Cf), 1 = half (Chf), 2 = bf16 hi/lo split (Ch, Cl).
template<typename T, int TERMS, int KCH, int OUTM, int HAS_BIAS>
__global__ __launch_bounds__(256, 2) void gemm16(
    const T* __restrict__ Ah, const T* __restrict__ Al,
    const T* __restrict__ Bh, const T* __restrict__ Bl,
    const float* __restrict__ bias,
    float* __restrict__ Cf, half* __restrict__ Chf,
    T* __restrict__ Ch, T* __restrict__ Cl,
    int M, int N, int K, size_t sA, size_t sB)
{
    extern __shared__ char smem[];
    const int tid = threadIdx.x, lane = tid & 31, wid = tid >> 5;
    const int b = blockIdx.z;
    const int n0 = blockIdx.x * 128, m0 = blockIdx.y * 128;
    const T* Agh = Ah + (size_t)b * sA + (size_t)m0 * K;
    const T* Bgh = Bh + (size_t)b * sB + (size_t)n0 * K;
    const T* Agl = (TERMS == 3) ? (Al + (size_t)b * sA + (size_t)m0 * K) : nullptr;
    const T* Bgl = (TERMS == 3) ? (Bl + (size_t)b * sB + (size_t)n0 * K) : nullptr;

    const uint32_t sb = smem_u32(smem);
    constexpr uint32_t ST  = KCH * 2 + 16;
    constexpr uint32_t TL  = 128u * ST;
    constexpr uint32_t BUF = (TERMS == 3 ? 4u : 2u) * TL;
    constexpr int LPR = KCH / 8;
    constexpr int PP  = (128 * LPR) / 256;

    const int wm = (wid >> 2) * 64, wn = (wid & 3) * 32;

    float acc[4][4][4];
    #pragma unroll
    for (int i = 0; i < 4; i++)
        #pragma unroll
        for (int j = 0; j < 4; j++)
            #pragma unroll
            for (int r = 0; r < 4; r++) acc[i][j][r] = 0.f;

    auto stage = [&](int ch, int buf) {
        uint32_t base = sb + buf * BUF;
        #pragma unroll
        for (int it = 0; it < PP; it++) {
            int idx = tid + it * 256;
            int r = idx / LPR, f = idx % LPR;
            uint32_t off = r * ST + f * 16;
            size_t go = (size_t)r * K + ch * KCH + f * 8;
            cp16(base + off, Agh + go);
            cp16(base + TL + off, Bgh + go);
            if (TERMS == 3) {
                cp16(base + 2 * TL + off, Agl + go);
                cp16(base + 3 * TL + off, Bgl + go);
            }
        }
        asm volatile("cp.async.commit_group;" ::: "memory");
    };

    const int t8 = lane >> 3, rr = lane & 7;
    const uint32_t a_off = (uint32_t)((t8 & 1) * 8 + rr) * ST + (t8 >> 1) * 16;
    const uint32_t b_off = (uint32_t)((t8 >> 1) * 8 + rr) * ST + (t8 & 1) * 16;

    const int NC = K / KCH;
    stage(0, 0);
    for (int ch = 0; ch < NC; ch++) {
        const int buf = ch & 1;
        if (ch + 1 < NC) {
            stage(ch + 1, buf ^ 1);
            asm volatile("cp.async.wait_group 1;" ::: "memory");
        } else {
            asm volatile("cp.async.wait_group 0;" ::: "memory");
        }
        __syncthreads();

        const uint32_t ab = sb + buf * BUF;
        const uint32_t bb = ab + TL;

        #pragma unroll
        for (int k16 = 0; k16 < KCH / 16; k16++) {
            const uint32_t kb = k16 * 32;
            uint32_t bhf[4][2], blf[4][2];
            #pragma unroll
            for (int pr = 0; pr < 2; pr++) {
                uint32_t r4[4];
                ldsm4(r4, bb + (uint32_t)(wn + pr * 16) * ST + b_off + kb);
                bhf[pr * 2][0] = r4[0]; bhf[pr * 2][1] = r4[1];
                bhf[pr * 2 + 1][0] = r4[2]; bhf[pr * 2 + 1][1] = r4[3];
                if (TERMS == 3) {
                    ldsm4(r4, bb + 2 * TL + (uint32_t)(wn + pr * 16) * ST + b_off + kb);
                    blf[pr * 2][0] = r4[0]; blf[pr * 2][1] = r4[1];
                    blf[pr * 2 + 1][0] = r4[2]; blf[pr * 2 + 1][1] = r4[3];
                }
            }
            #pragma unroll
            for (int im = 0; im < 4; im++) {
                uint32_t af[4];
                ldsm4(af, ab + (uint32_t)(wm + im * 16) * ST + a_off + kb);
                #pragma unroll
                for (int jn = 0; jn < 4; jn++) {
                    mma16(acc[im][jn], af, bhf[jn], (const T*)nullptr);
                    if (TERMS == 3) mma16(acc[im][jn], af, blf[jn], (const T*)nullptr);
                }
                if (TERMS == 3) {
                    uint32_t alf[4];
                    ldsm4(alf, ab + 2 * TL + (uint32_t)(wm + im * 16) * ST + a_off + kb);
                    #pragma unroll
                    for (int jn = 0; jn < 4; jn++)
                        mma16(acc[im][jn], alf, bhf[jn], (const T*)nullptr);
                }
            }
        }
        __syncthreads();
    }

    // epilogue
    #pragma unroll
    for (int im = 0; im < 4; im++) {
        int r = m0 + wm + im * 16 + (lane >> 2);
        #pragma unroll
        for (int jn = 0; jn < 4; jn++) {
            int cc = n0 + wn + jn * 8 + (lane & 3) * 2;
            float b0 = 0.f, b1 = 0.f;
            if (HAS_BIAS) { b0 = __ldg(&bias[cc]); b1 = __ldg(&bias[cc + 1]); }
            float v00 = acc[im][jn][0] + b0, v01 = acc[im][jn][1] + b1;
            float v10 = acc[im][jn][2] + b0, v11 = acc[im][jn][3] + b1;
            size_t o0 = (size_t)b * (size_t)M * N + (size_t)r * N + cc;
            size_t o1 = o0 + (size_t)8 * N;
            if constexpr (OUTM == 2) {
                __nv_bfloat16 h00 = __float2bfloat16_rn(v00), h01 = __float2bfloat16_rn(v01);
                __nv_bfloat16 h10 = __float2bfloat16_rn(v10), h11 = __float2bfloat16_rn(v11);
                *(__nv_bfloat162*)(Ch + o0) = __nv_bfloat162(h00, h01);
                *(__nv_bfloat162*)(Ch + o1) = __nv_bfloat162(h10, h11);
                *(__nv_bfloat162*)(Cl + o0) = __nv_bfloat162(
                    __float2bfloat16_rn(v00 - __bfloat162float(h00)),
                    __float2bfloat16_rn(v01 - __bfloat162float(h01)));
                *(__nv_bfloat162*)(Cl + o1) = __nv_bfloat162(
                    __float2bfloat16_rn(v10 - __bfloat162float(h10)),
                    __float2bfloat16_rn(v11 - __bfloat162float(h11)));
            } else if constexpr (OUTM == 1) {
                *(half2*)(Chf + o0) = __floats2half2_rn(v00, v01);
                *(half2*)(Chf + o1) = __floats2half2_rn(v10, v11);
            } else {
                *(float2*)(Cf + o0) = make_float2(v00, v01);
                *(float2*)(Cf + o1) = make_float2(v10, v11);
            }
        }
    }
}

// ---------------- transpose+split: fp32 [b][512][4096] -> hi/lo bf16 [b][4096][512] ----------------
__global__ void transpose_split(const float* __restrict__ src,
                                __nv_bfloat16* __restrict__ dh, __nv_bfloat16* __restrict__ dl)
{
    __shared__ float t[32][33];
    int b = blockIdx.z;
    const float* s = src + (size_t)b * 512ull * 4096ull;
    size_t dbo = (size_t)b * 512ull * 4096ull;
    int c0 = blockIdx.x * 32, r0 = blockIdx.y * 32;
    int tx = threadIdx.x, ty = threadIdx.y;
    #pragma unroll
    for (int k = 0; k < 4; k++)
        t[ty + k * 8][tx] = s[(size_t)(r0 + ty + k * 8) * 4096 + c0 + tx];
    __syncthreads();
    #pragma unroll
    for (int k = 0; k < 4; k++) {
        float v = t[tx][ty + k * 8];
        size_t o = dbo + (size_t)(c0 + ty + k * 8) * 512 + r0 + tx;
        __nv_bfloat16 h = __float2bfloat16_rn(v);
        dh[o] = h;
        dl[o] = __float2bfloat16_rn(v - __bfloat162float(h));
    }
}

__global__ void weight_split(const float* __restrict__ w,
                             __nv_bfloat16* __restrict__ wh, __nv_bfloat16* __restrict__ wl, int n)
{
    int i = blockIdx.x * 256 + threadIdx.x;
    if (i < n) {
        float v = w[i];
        __nv_bfloat16 h = __float2bfloat16_rn(v);
        wh[i] = h;
        wl[i] = __float2bfloat16_rn(v - __bfloat162float(h));
    }
}

// HmT fp32 [b][4096(n)][512(c)] -> Hcat half [b][1024][4096]: [H ; H^2]
__global__ void transpose_sq_half(const float* __restrict__ src, half* __restrict__ dst)
{
    __shared__ float t[32][33];
    int b = blockIdx.z;
    const float* s = src + (size_t)b * 4096ull * 512ull;
    half* d = dst + (size_t)b * 1024ull * 4096ull;
    int c0 = blockIdx.x * 32, n0 = blockIdx.y * 32;
    int tx = threadIdx.x, ty = threadIdx.y;
    #pragma unroll
    for (int k = 0; k < 4; k++)
        t[ty + k * 8][tx] = s[(size_t)(n0 + ty + k * 8) * 512 + c0 + tx];
    __syncthreads();
    #pragma unroll
    for (int k = 0; k < 4; k++) {
        float v = t[tx][ty + k * 8];
        d[(size_t)(c0 + ty + k * 8) * 4096 + n0 + tx] = __float2half_rn(v);
        d[(size_t)(512 + c0 + ty + k * 8) * 4096 + n0 + tx] = __float2half_rn(v * v);
    }
}

// Ccat [b][n][1024] -> meanT/stdT [b][c][n]
__global__ void meanstd_transpose(const float* __restrict__ Ccat,
                                  float* __restrict__ meanT, float* __restrict__ stdT)
{
    __shared__ float tm[32][33], ts[32][33];
    int b = blockIdx.z;
    int c0 = blockIdx.x * 32, n0 = blockIdx.y * 32;
    const float* Cb = Ccat + (size_t)b * 4096ull * 1024ull;
    int tx = threadIdx.x, ty = threadIdx.y;
    #pragma unroll
    for (int k = 0; k < 4; k++) {
        int n = n0 + ty + k * 8;
        float mn = Cb[(size_t)n * 1024 + c0 + tx];
        float sc = Cb[(size_t)n * 1024 + 512 + c0 + tx];
        tm[ty + k * 8][tx] = mn;
        ts[ty + k * 8][tx] = fast_sqrt(fmaxf(sc - mn * mn, 0.f));
    }
    __syncthreads();
    size_t ob = (size_t)b * 512ull * 4096ull;
    #pragma unroll
    for (int k = 0; k < 4; k++) {
        int c = c0 + ty + k * 8;
        meanT[ob + (size_t)c * 4096 + n0 + tx] = tm[tx][ty + k * 8];
        stdT [ob + (size_t)c * 4096 + n0 + tx] = ts[tx][ty + k * 8];
    }
}

// ---------------- block reductions ----------------
__device__ __forceinline__ float block_reduce_max(float v, float* red) {
    #pragma unroll
    for (int o = 16; o > 0; o >>= 1) v = fmaxf(v, __shfl_xor_sync(0xffffffffu, v, o));
    int wid = threadIdx.x >> 5, lid = threadIdx.x & 31;
    if (lid == 0) red[wid] = v;
    __syncthreads();
    if (wid == 0) {
        v = (lid < 8) ? red[lid] : -1e30f;
        #pragma unroll
        for (int o = 4; o > 0; o >>= 1) v = fmaxf(v, __shfl_xor_sync(0xffffffffu, v, o));
        if (lid == 0) red[0] = v;
    }
    __syncthreads();
    float r = red[0];
    __syncthreads();
    return r;
}
__device__ __forceinline__ float block_reduce_sum(float v, float* red) {
    #pragma unroll
    for (int o = 16; o > 0; o >>= 1) v += __shfl_xor_sync(0xffffffffu, v, o);
    int wid = threadIdx.x >> 5, lid = threadIdx.x & 31;
    if (lid == 0) red[wid] = v;
    __syncthreads();
    if (wid == 0) {
        v = (lid < 8) ? red[lid] : 0.f;
        #pragma unroll
        for (int o = 4; o > 0; o >>= 1) v += __shfl_xor_sync(0xffffffffu, v, o);
        if (lid == 0) red[0] = v;
    }
    __syncthreads();
    float r = red[0];
    __syncthreads();
    return r;
}

// ---------------- softmax mix: half in -> half S out, IN PLACE ----------------
// e2 = exp(max(v,0)-m2) with m2=max(m1,0): e2 = (v>0) ? e1 : exp(-m2).
__global__ __launch_bounds__(256) void softmax_mix_kernel(
    half* __restrict__ attn, const float* __restrict__ w_mix)
{
    __shared__ float e1s[4096];
    __shared__ float red[32];
    half* p = attn + (size_t)blockIdx.x * 4096;
    int tid = threadIdx.x;

    float lmax = -1e30f;
    for (int i = tid; i < 4096; i += 256) {
        float v = __half2float(p[i]);
        e1s[i] = v;
        lmax = fmaxf(lmax, v);
    }
    float m1 = block_reduce_max(lmax, red);
    float m2 = fmaxf(m1, 0.f);
    float Cneg = fast_exp(-m2);

    float z1 = 0.f, z2p = 0.f, nneg = 0.f;
    for (int i = tid; i < 4096; i += 256) {
        float v = e1s[i];
        float e1 = fast_exp(v - m1);
        bool pos = v > 0.f;
        z1 += e1;
        if (pos) z2p += e1; else nneg += 1.f;
        e1s[i] = pos ? e1 : -e1;
    }
    float Z1 = block_reduce_sum(z1, red);
    float Z2 = block_reduce_sum(z2p, red) + block_reduce_sum(nneg, red) * Cneg;

    float ew0 = fast_exp(w_mix[0]), ew1 = fast_exp(w_mix[1]);
    float inv = 1.f / (ew0 + ew1);
    float iz1 = (ew0 * inv) / Z1;
    float iz2 = (ew1 * inv) / Z2;
    float Cn2 = Cneg * iz2;

    float za = 0.f;
    for (int i = tid; i < 4096; i += 256) {
        float se = e1s[i];
        float e1 = fabsf(se);
        float A = (se > 0.f) ? e1 * (iz1 + iz2) : fmaf(e1, iz1, Cn2);
        float e = fast_exp(A);
        e1s[i] = e;
        za += e;
    }
    float ZA = block_reduce_sum(za, red);
    float izA = 1.f / ZA;
    for (int i = tid; i < 4096; i += 256)
        p[i] = __float2half_rn(e1s[i] * izA);
}

// ---------------- finalize: out = stdT * mvn(content) + meanT ----------------
__global__ __launch_bounds__(256) void finalize_kernel(
    const float* __restrict__ content, const float* __restrict__ meanT,
    const float* __restrict__ stdT, float* __restrict__ out)
{
    __shared__ float red[32];
    int c = blockIdx.x, b = blockIdx.y;
    size_t off = ((size_t)b * 512 + c) * 4096;
    const float* x = content + off;
    int tid = threadIdx.x;

    float s = 0.f, ss = 0.f;
    for (int i = tid; i < 4096; i += 256) {
        float v = x[i];
        s += v; ss += v * v;
    }
    s = block_reduce_sum(s, red);
    ss = block_reduce_sum(ss, red);
    float mu = s * (1.f / 4096.f);
    float var = (ss - 4096.f * mu * mu) * (1.f / 4095.f);
    float rstd = rsqrtf(var + 1e-5f);

    for (int i = tid; i < 4096; i += 256)
        out[off + i] = stdT[off + i] * ((x[i] - mu) * rstd) + meanT[off + i];
}

// ---------------- launch ----------------
extern "C" void kernel_launch(void* const* d_in, const int* in_sizes, int n_in,
                              void* d_out, int out_size)
{
    const float* content     = (const float*)d_in[0];
    const float* style       = (const float*)d_in[1];
    const float* content_key = (const float*)d_in[2];
    const float* style_key   = (const float*)d_in[3];
    const float* f_w = (const float*)d_in[4];
    const float* f_b = (const float*)d_in[5];
    const float* g_w = (const float*)d_in[6];
    const float* g_b = (const float*)d_in[7];
    const float* h_w = (const float*)d_in[8];
    const float* h_b = (const float*)d_in[9];
    const float* w_mix = (const float*)d_in[10];
    float* out = (float*)d_out;

    typedef __nv_bfloat16 bf16;
    void *p;
    cudaGetSymbolAddress(&p, g_attn4);  half*  attn = (half*)p;   // logits & S, in place
    cudaGetSymbolAddress(&p, g_xth4);   bf16*  XTh  = (bf16*)p;
    cudaGetSymbolAddress(&p, g_xtl4);   bf16*  XTl  = (bf16*)p;
    cudaGetSymbolAddress(&p, g_wh4);    bf16*  Wh   = (bf16*)p;
    cudaGetSymbolAddress(&p, g_wl4);    bf16*  Wl   = (bf16*)p;
    cudaGetSymbolAddress(&p, g_Fh4);    bf16*  Fh   = (bf16*)p;
    cudaGetSymbolAddress(&p, g_Fl4);    bf16*  Fl   = (bf16*)p;
    cudaGetSymbolAddress(&p, g_Gh4);    bf16*  Gh   = (bf16*)p;
    cudaGetSymbolAddress(&p, g_Gl4);    bf16*  Gl   = (bf16*)p;
    cudaGetSymbolAddress(&p, g_HmT4);   float* HmT  = (float*)p;
    cudaGetSymbolAddress(&p, g_Hcat4);  half*  Hcat = (half*)p;
    cudaGetSymbolAddress(&p, g_Ccat4);  float* Ccat = (float*)p;
    cudaGetSymbolAddress(&p, g_meanT4); float* meanT= (float*)p;
    cudaGetSymbolAddress(&p, g_stdT4);  float* stdT = (float*)p;

    const size_t XN = 4ull * 4096 * 512;
    const size_t WN = 512ull * 512;

    const int SM3 = 2 * 4 * (128 * 80);    // 81920  (TERMS=3, KCH=32)
    const int SM1 = 2 * 2 * (128 * 144);   // 73728  (TERMS=1, KCH=64)
    cudaFuncSetAttribute((gemm16<bf16,3,32,2,1>), cudaFuncAttributeMaxDynamicSharedMemorySize, SM3);
    cudaFuncSetAttribute((gemm16<bf16,3,32,0,1>), cudaFuncAttributeMaxDynamicSharedMemorySize, SM3);
    cudaFuncSetAttribute((gemm16<bf16,3,32,1,0>), cudaFuncAttributeMaxDynamicSharedMemorySize, SM3);
    cudaFuncSetAttribute((gemm16<half,1,64,0,0>), cudaFuncAttributeMaxDynamicSharedMemorySize, SM1);

    // 1) transpose+split inputs -> XT hi/lo bf16 [b][4096][512]
    transpose_split<<<dim3(128, 16, 4), dim3(32, 8)>>>(content_key, XTh + 0 * XN, XTl + 0 * XN);
    transpose_split<<<dim3(128, 16, 4), dim3(32, 8)>>>(style_key,   XTh + 1 * XN, XTl + 1 * XN);
    transpose_split<<<dim3(128, 16, 4), dim3(32, 8)>>>(style,       XTh + 2 * XN, XTl + 2 * XN);
    weight_split<<<dim3(1024), 256>>>(f_w, Wh + 0 * WN, Wl + 0 * WN, 262144);
    weight_split<<<dim3(1024), 256>>>(g_w, Wh + 1 * WN, Wl + 1 * WN, 262144);
    weight_split<<<dim3(1024), 256>>>(h_w, Wh + 2 * WN, Wl + 2 * WN, 262144);

    // 2) convs (bf16x3): F,G -> hi/lo bf16; H -> fp32
    gemm16<bf16,3,32,2,1><<<dim3(4, 32, 4), 256, SM3>>>(XTh + 0 * XN, XTl + 0 * XN,
        Wh + 0 * WN, Wl + 0 * WN, f_b, nullptr, nullptr, Fh, Fl,
        4096, 512, 512, 4096ull * 512, 0);
    gemm16<bf16,3,32,2,1><<<dim3(4, 32, 4), 256, SM3>>>(XTh + 1 * XN, XTl + 1 * XN,
        Wh + 1 * WN, Wl + 1 * WN, g_b, nullptr, nullptr, Gh, Gl,
        4096, 512, 512, 4096ull * 512, 0);
    gemm16<bf16,3,32,0,1><<<dim3(4, 32, 4), 256, SM3>>>(XTh + 2 * XN, XTl + 2 * XN,
        Wh + 2 * WN, Wl + 2 * WN, h_b, HmT, nullptr, nullptr, nullptr,
        4096, 512, 512, 4096ull * 512, 0);

    // 3) Hcat half [b][1024][4096] = [H[c][n] ; H^2]
    transpose_sq_half<<<dim3(16, 128, 4), dim3(32, 8)>>>(HmT, Hcat);

    // 4) attention logits (bf16x3) -> half attn buffer
    gemm16<bf16,3,32,1,0><<<dim3(32, 32, 4), 256, SM3>>>(Fh, Fl, Gh, Gl, nullptr,
        nullptr, attn, nullptr, nullptr, 4096, 4096, 512, 4096ull * 512, 4096ull * 512);

    // 5) triple-softmax mix, in place (half -> half)
    softmax_mix_kernel<<<16384, 256>>>(attn, w_mix);

    // 6) mean/second GEMM (fp16, KCH=64): Ccat[n][1024] = S[n][m] * Hcat[cc][m]
    gemm16<half,1,64,0,0><<<dim3(8, 32, 4), 256, SM1>>>(attn, nullptr, Hcat, nullptr, nullptr,
        Ccat, nullptr, nullptr, nullptr, 4096, 1024, 4096, 4096ull * 4096, 1024ull * 4096);

    // 7) Ccat -> meanT/stdT [b][c][n]
    meanstd_transpose<<<dim3(16, 128, 4), dim3(32, 8)>>>(Ccat, meanT, stdT);

    // 8) finalize
    finalize_kernel<<<dim3(512, 4), 256>>>(content, meanT, stdT, out);
}

// round 10
// speedup vs baseline: 1.1629x; 1.0812x over previous
#include <cuda_runtime.h>
#include <cuda_bf16.h>
#include <cuda_fp16.h>
#include <math.h>
#include <stdint.h>

// ---------------- scratch (uint4 => 16B alignment for cp.async) ----------------
__device__ uint4 g_attn4 [8388608];    // half attn/S (in-place) [4][4096][4096]
__device__ uint4 g_xth4  [3145728];    // bf16 XT hi, 3 inputs x [4][4096][512]
__device__ uint4 g_xtl4  [3145728];    // bf16 XT lo
__device__ uint4 g_wh4   [98304];      // bf16 W hi, 3 x [512][512]
__device__ uint4 g_wl4   [98304];
__device__ uint4 g_Fh4   [1048576];    // bf16 Fm hi [4][4096][512]
__device__ uint4 g_Fl4   [1048576];
__device__ uint4 g_Gh4   [1048576];
__device__ uint4 g_Gl4   [1048576];
__device__ uint4 g_HmT4  [2097152];    // fp32 Hm [4][4096][512] ([n][c])
__device__ uint4 g_Hcat4 [2097152];    // half Hcat [4][1024][4096], rows interleaved (H[c],H^2[c])
__device__ uint4 g_meanT4[2097152];    // fp32 [4][512][4096]
__device__ uint4 g_stdT4 [2097152];

// ---------------- helpers ----------------
__device__ __forceinline__ uint32_t smem_u32(const void* p) {
    uint32_t a;
    asm("{ .reg .u64 t; cvta.to.shared.u64 t, %1; cvt.u32.u64 %0, t; }" : "=r"(a) : "l"(p));
    return a;
}
__device__ __forceinline__ void cp16(uint32_t dst, const void* src) {
    asm volatile("cp.async.ca.shared.global [%0], [%1], 16;" :: "r"(dst), "l"(src));
}
__device__ __forceinline__ void ldsm4(uint32_t* r, uint32_t addr) {
    asm volatile("ldmatrix.sync.aligned.m8n8.x4.shared.b16 {%0,%1,%2,%3}, [%4];"
        : "=r"(r[0]), "=r"(r[1]), "=r"(r[2]), "=r"(r[3]) : "r"(addr));
}
__device__ __forceinline__ void mma16(float* d, const uint32_t* a, const uint32_t* b,
                                      const __nv_bfloat16*) {
    asm volatile("mma.sync.aligned.m16n8k16.row.col.f32.bf16.bf16.f32 "
        "{%0,%1,%2,%3}, {%4,%5,%6,%7}, {%8,%9}, {%0,%1,%2,%3};"
        : "+f"(d[0]), "+f"(d[1]), "+f"(d[2]), "+f"(d[3])
        : "r"(a[0]), "r"(a[1]), "r"(a[2]), "r"(a[3]), "r"(b[0]), "r"(b[1]));
}
__device__ __forceinline__ void mma16(float* d, const uint32_t* a, const uint32_t* b,
                                      const half*) {
    asm volatile("mma.sync.aligned.m16n8k16.row.col.f32.f16.f16.f32 "
        "{%0,%1,%2,%3}, {%4,%5,%6,%7}, {%8,%9}, {%0,%1,%2,%3};"
        : "+f"(d[0]), "+f"(d[1]), "+f"(d[2]), "+f"(d[3])
        : "r"(a[0]), "r"(a[1]), "r"(a[2]), "r"(a[3]), "r"(b[0]), "r"(b[1]));
}

// FMA-only exp (Schraudolph round + deg-6 Taylor of 2^f), rel err ~1.5e-7.
__device__ __forceinline__ float fast_exp(float x) {
    x = fmaxf(x, -80.f);
    float t = x * 1.44269504088896f;
    float z = t + 12582912.f;
    int   i = __float_as_int(z) - 0x4B400000;
    float f = t - (z - 12582912.f);
    float p = 1.53989037e-4f;
    p = fmaf(p, f, 1.33335581e-3f);
    p = fmaf(p, f, 9.61812910e-3f);
    p = fmaf(p, f, 5.55041087e-2f);
    p = fmaf(p, f, 2.40226507e-1f);
    p = fmaf(p, f, 6.93147181e-1f);
    p = fmaf(p, f, 1.0f);
    return __int_as_float(__float_as_int(p) + (i << 23));
}

// FMA-only sqrt via bit-hack rsqrt + 2 Newton iters.
__device__ __forceinline__ float fast_sqrt(float v) {
    float x = fmaxf(v, 1e-30f);
    float xh = 0.5f * x;
    float y = __int_as_float(0x5f375a86 - (__float_as_int(x) >> 1));
    y = y * fmaf(-xh, y * y, 1.5f);
    y = y * fmaf(-xh, y * y, 1.5f);
    return v * y;
}

// ---------------- GEMM: C[b][m][n] = sum_k A[m][k]*B[n][k] (+bias[n]) ----------------
// TERMS=3: AhBh+AlBh+AhBl; TERMS=1: hi only. Block 128x128xKCH, 8 warps (2m x 4n),
// warp tile 64x32, cp.async double buffer, ldmatrix loads.
// OUTM: 0=fp32 (Cf), 1=half (Chf), 2=bf16 hi/lo (Ch,Cl),
//       3=mean/std direct: B rows interleaved (mean,sec) pairs; writes
//         Cf=meanT, Cf2=stdT as [b][N/2][M] fp32.
template<typename T, int TERMS, int KCH, int OUTM, int HAS_BIAS>
__global__ __launch_bounds__(256, 2) void gemm16(
    const T* __restrict__ Ah, const T* __restrict__ Al,
    const T* __restrict__ Bh, const T* __restrict__ Bl,
    const float* __restrict__ bias,
    float* __restrict__ Cf, float* __restrict__ Cf2, half* __restrict__ Chf,
    T* __restrict__ Ch, T* __restrict__ Cl,
    int M, int N, int K, size_t sA, size_t sB)
{
    extern __shared__ char smem[];
    const int tid = threadIdx.x, lane = tid & 31, wid = tid >> 5;
    const int b = blockIdx.z;
    const int n0 = blockIdx.x * 128, m0 = blockIdx.y * 128;
    const T* Agh = Ah + (size_t)b * sA + (size_t)m0 * K;
    const T* Bgh = Bh + (size_t)b * sB + (size_t)n0 * K;
    const T* Agl = (TERMS == 3) ? (Al + (size_t)b * sA + (size_t)m0 * K) : nullptr;
    const T* Bgl = (TERMS == 3) ? (Bl + (size_t)b * sB + (size_t)n0 * K) : nullptr;

    const uint32_t sb = smem_u32(smem);
    constexpr uint32_t ST  = KCH * 2 + 16;
    constexpr uint32_t TL  = 128u * ST;
    constexpr uint32_t BUF = (TERMS == 3 ? 4u : 2u) * TL;
    constexpr int LPR = KCH / 8;
    constexpr int PP  = (128 * LPR) / 256;

    const int wm = (wid >> 2) * 64, wn = (wid & 3) * 32;

    float acc[4][4][4];
    #pragma unroll
    for (int i = 0; i < 4; i++)
        #pragma unroll
        for (int j = 0; j < 4; j++)
            #pragma unroll
            for (int r = 0; r < 4; r++) acc[i][j][r] = 0.f;

    auto stage = [&](int ch, int buf) {
        uint32_t base = sb + buf * BUF;
        #pragma unroll
        for (int it = 0; it < PP; it++) {
            int idx = tid + it * 256;
            int r = idx / LPR, f = idx % LPR;
            uint32_t off = r * ST + f * 16;
            size_t go = (size_t)r * K + ch * KCH + f * 8;
            cp16(base + off, Agh + go);
            cp16(base + TL + off, Bgh + go);
            if (TERMS == 3) {
                cp16(base + 2 * TL + off, Agl + go);
                cp16(base + 3 * TL + off, Bgl + go);
            }
        }
        asm volatile("cp.async.commit_group;" ::: "memory");
    };

    const int t8 = lane >> 3, rr = lane & 7;
    const uint32_t a_off = (uint32_t)((t8 & 1) * 8 + rr) * ST + (t8 >> 1) * 16;
    const uint32_t b_off = (uint32_t)((t8 >> 1) * 8 + rr) * ST + (t8 & 1) * 16;

    const int NC = K / KCH;
    stage(0, 0);
    for (int ch = 0; ch < NC; ch++) {
        const int buf = ch & 1;
        if (ch + 1 < NC) {
            stage(ch + 1, buf ^ 1);
            asm volatile("cp.async.wait_group 1;" ::: "memory");
        } else {
            asm volatile("cp.async.wait_group 0;" ::: "memory");
        }
        __syncthreads();

        const uint32_t ab = sb + buf * BUF;
        const uint32_t bb = ab + TL;

        #pragma unroll
        for (int k16 = 0; k16 < KCH / 16; k16++) {
            const uint32_t kb = k16 * 32;
            uint32_t bhf[4][2], blf[4][2];
            #pragma unroll
            for (int pr = 0; pr < 2; pr++) {
                uint32_t r4[4];
                ldsm4(r4, bb + (uint32_t)(wn + pr * 16) * ST + b_off + kb);
                bhf[pr * 2][0] = r4[0]; bhf[pr * 2][1] = r4[1];
                bhf[pr * 2 + 1][0] = r4[2]; bhf[pr * 2 + 1][1] = r4[3];
                if (TERMS == 3) {
                    ldsm4(r4, bb + 2 * TL + (uint32_t)(wn + pr * 16) * ST + b_off + kb);
                    blf[pr * 2][0] = r4[0]; blf[pr * 2][1] = r4[1];
                    blf[pr * 2 + 1][0] = r4[2]; blf[pr * 2 + 1][1] = r4[3];
                }
            }
            #pragma unroll
            for (int im = 0; im < 4; im++) {
                uint32_t af[4];
                ldsm4(af, ab + (uint32_t)(wm + im * 16) * ST + a_off + kb);
                #pragma unroll
                for (int jn = 0; jn < 4; jn++) {
                    mma16(acc[im][jn], af, bhf[jn], (const T*)nullptr);
                    if (TERMS == 3) mma16(acc[im][jn], af, blf[jn], (const T*)nullptr);
                }
                if (TERMS == 3) {
                    uint32_t alf[4];
                    ldsm4(alf, ab + 2 * TL + (uint32_t)(wm + im * 16) * ST + a_off + kb);
                    #pragma unroll
                    for (int jn = 0; jn < 4; jn++)
                        mma16(acc[im][jn], alf, bhf[jn], (const T*)nullptr);
                }
            }
        }
        __syncthreads();
    }

    // epilogue
    #pragma unroll
    for (int im = 0; im < 4; im++) {
        int r = m0 + wm + im * 16 + (lane >> 2);
        #pragma unroll
        for (int jn = 0; jn < 4; jn++) {
            int cc = n0 + wn + jn * 8 + (lane & 3) * 2;
            float b0 = 0.f, b1 = 0.f;
            if (HAS_BIAS) { b0 = __ldg(&bias[cc]); b1 = __ldg(&bias[cc + 1]); }
            float v00 = acc[im][jn][0] + b0, v01 = acc[im][jn][1] + b1;
            float v10 = acc[im][jn][2] + b0, v11 = acc[im][jn][3] + b1;
            if constexpr (OUTM == 3) {
                // (v00,v01) = (mean, second) of channel cc/2 at row r; (v10,v11) at r+8
                size_t base = ((size_t)b * (N >> 1) + (cc >> 1)) * (size_t)M;
                Cf [base + r]     = v00;
                Cf2[base + r]     = fast_sqrt(fmaxf(v01 - v00 * v00, 0.f));
                Cf [base + r + 8] = v10;
                Cf2[base + r + 8] = fast_sqrt(fmaxf(v11 - v10 * v10, 0.f));
            } else {
                size_t o0 = (size_t)b * (size_t)M * N + (size_t)r * N + cc;
                size_t o1 = o0 + (size_t)8 * N;
                if constexpr (OUTM == 2) {
                    __nv_bfloat16 h00 = __float2bfloat16_rn(v00), h01 = __float2bfloat16_rn(v01);
                    __nv_bfloat16 h10 = __float2bfloat16_rn(v10), h11 = __float2bfloat16_rn(v11);
                    *(__nv_bfloat162*)(Ch + o0) = __nv_bfloat162(h00, h01);
                    *(__nv_bfloat162*)(Ch + o1) = __nv_bfloat162(h10, h11);
                    *(__nv_bfloat162*)(Cl + o0) = __nv_bfloat162(
                        __float2bfloat16_rn(v00 - __bfloat162float(h00)),
                        __float2bfloat16_rn(v01 - __bfloat162float(h01)));
                    *(__nv_bfloat162*)(Cl + o1) = __nv_bfloat162(
                        __float2bfloat16_rn(v10 - __bfloat162float(h10)),
                        __float2bfloat16_rn(v11 - __bfloat162float(h11)));
                } else if constexpr (OUTM == 1) {
                    *(half2*)(Chf + o0) = __floats2half2_rn(v00, v01);
                    *(half2*)(Chf + o1) = __floats2half2_rn(v10, v11);
                } else {
                    *(float2*)(Cf + o0) = make_float2(v00, v01);
                    *(float2*)(Cf + o1) = make_float2(v10, v11);
                }
            }
        }
    }
}

// ---------------- transpose+split: fp32 [b][512][4096] -> hi/lo bf16 [b][4096][512] ----------------
__global__ void transpose_split(const float* __restrict__ src,
                                __nv_bfloat16* __restrict__ dh, __nv_bfloat16* __restrict__ dl)
{
    __shared__ float t[32][33];
    int b = blockIdx.z;
    const float* s = src + (size_t)b * 512ull * 4096ull;
    size_t dbo = (size_t)b * 512ull * 4096ull;
    int c0 = blockIdx.x * 32, r0 = blockIdx.y * 32;
    int tx = threadIdx.x, ty = threadIdx.y;
    #pragma unroll
    for (int k = 0; k < 4; k++)
        t[ty + k * 8][tx] = s[(size_t)(r0 + ty + k * 8) * 4096 + c0 + tx];
    __syncthreads();
    #pragma unroll
    for (int k = 0; k < 4; k++) {
        float v = t[tx][ty + k * 8];
        size_t o = dbo + (size_t)(c0 + ty + k * 8) * 512 + r0 + tx;
        __nv_bfloat16 h = __float2bfloat16_rn(v);
        dh[o] = h;
        dl[o] = __float2bfloat16_rn(v - __bfloat162float(h));
    }
}

__global__ void weight_split(const float* __restrict__ w,
                             __nv_bfloat16* __restrict__ wh, __nv_bfloat16* __restrict__ wl, int n)
{
    int i = blockIdx.x * 256 + threadIdx.x;
    if (i < n) {
        float v = w[i];
        __nv_bfloat16 h = __float2bfloat16_rn(v);
        wh[i] = h;
        wl[i] = __float2bfloat16_rn(v - __bfloat162float(h));
    }
}

// HmT fp32 [b][4096(n)][512(c)] -> Hcat half [b][1024][4096], rows interleaved:
// row 2c = H[c][n], row 2c+1 = H[c][n]^2
__global__ void transpose_sq_half(const float* __restrict__ src, half* __restrict__ dst)
{
    __shared__ float t[32][33];
    int b = blockIdx.z;
    const float* s = src + (size_t)b * 4096ull * 512ull;
    half* d = dst + (size_t)b * 1024ull * 4096ull;
    int c0 = blockIdx.x * 32, n0 = blockIdx.y * 32;
    int tx = threadIdx.x, ty = threadIdx.y;
    #pragma unroll
    for (int k = 0; k < 4; k++)
        t[ty + k * 8][tx] = s[(size_t)(n0 + ty + k * 8) * 512 + c0 + tx];
    __syncthreads();
    #pragma unroll
    for (int k = 0; k < 4; k++) {
        float v = t[tx][ty + k * 8];
        int c = c0 + ty + k * 8;
        d[(size_t)(2 * c)     * 4096 + n0 + tx] = __float2half_rn(v);
        d[(size_t)(2 * c + 1) * 4096 + n0 + tx] = __float2half_rn(v * v);
    }
}

// ---------------- block reductions ----------------
__device__ __forceinline__ float block_reduce_max(float v, float* red) {
    #pragma unroll
    for (int o = 16; o > 0; o >>= 1) v = fmaxf(v, __shfl_xor_sync(0xffffffffu, v, o));
    int wid = threadIdx.x >> 5, lid = threadIdx.x & 31;
    if (lid == 0) red[wid] = v;
    __syncthreads();
    if (wid == 0) {
        v = (lid < 8) ? red[lid] : -1e30f;
        #pragma unroll
        for (int o = 4; o > 0; o >>= 1) v = fmaxf(v, __shfl_xor_sync(0xffffffffu, v, o));
        if (lid == 0) red[0] = v;
    }
    __syncthreads();
    float r = red[0];
    __syncthreads();
    return r;
}
__device__ __forceinline__ float block_reduce_sum(float v, float* red) {
    #pragma unroll
    for (int o = 16; o > 0; o >>= 1) v += __shfl_xor_sync(0xffffffffu, v, o);
    int wid = threadIdx.x >> 5, lid = threadIdx.x & 31;
    if (lid == 0) red[wid] = v;
    __syncthreads();
    if (wid == 0) {
        v = (lid < 8) ? red[lid] : 0.f;
        #pragma unroll
        for (int o = 4; o > 0; o >>= 1) v += __shfl_xor_sync(0xffffffffu, v, o);
        if (lid == 0) red[0] = v;
    }
    __syncthreads();
    float r = red[0];
    __syncthreads();
    return r;
}
// three sums in one barrier sequence
__device__ __forceinline__ void block_reduce_sum3(float& a, float& b, float& c, float* red) {
    #pragma unroll
    for (int o = 16; o > 0; o >>= 1) {
        a += __shfl_xor_sync(0xffffffffu, a, o);
        b += __shfl_xor_sync(0xffffffffu, b, o);
        c += __shfl_xor_sync(0xffffffffu, c, o);
    }
    int wid = threadIdx.x >> 5, lid = threadIdx.x & 31;
    if (lid == 0) { red[wid] = a; red[32 + wid] = b; red[64 + wid] = c; }
    __syncthreads();
    if (wid == 0) {
        a = (lid < 8) ? red[lid] : 0.f;
        b = (lid < 8) ? red[32 + lid] : 0.f;
        c = (lid < 8) ? red[64 + lid] : 0.f;
        #pragma unroll
        for (int o = 4; o > 0; o >>= 1) {
            a += __shfl_xor_sync(0xffffffffu, a, o);
            b += __shfl_xor_sync(0xffffffffu, b, o);
            c += __shfl_xor_sync(0xffffffffu, c, o);
        }
        if (lid == 0) { red[0] = a; red[32] = b; red[64] = c; }
    }
    __syncthreads();
    a = red[0]; b = red[32]; c = red[64];
    __syncthreads();
}

// ---------------- softmax mix: register-resident, half in/out, IN PLACE ----------------
// Each thread owns 16 contiguous elements of the 4096-row.
__global__ __launch_bounds__(256) void softmax_mix_kernel(
    half* __restrict__ attn, const float* __restrict__ w_mix)
{
    __shared__ float red[96];
    half* p = attn + (size_t)blockIdx.x * 4096;
    int tid = threadIdx.x;

    // load 16 halves (2x uint4)
    uint4 u0 = ((const uint4*)p)[tid * 2];
    uint4 u1 = ((const uint4*)p)[tid * 2 + 1];
    float v[16];
    {
        const half2* h0 = (const half2*)&u0;
        const half2* h1 = (const half2*)&u1;
        #pragma unroll
        for (int k = 0; k < 4; k++) {
            float2 f0 = __half22float2(h0[k]);
            float2 f1 = __half22float2(h1[k]);
            v[2 * k] = f0.x; v[2 * k + 1] = f0.y;
            v[8 + 2 * k] = f1.x; v[8 + 2 * k + 1] = f1.y;
        }
    }

    float lmax = -1e30f;
    #pragma unroll
    for (int k = 0; k < 16; k++) lmax = fmaxf(lmax, v[k]);
    float m1 = block_reduce_max(lmax, red);
    float m2 = fmaxf(m1, 0.f);
    float Cneg = fast_exp(-m2);

    float z1 = 0.f, z2p = 0.f, nneg = 0.f;
    #pragma unroll
    for (int k = 0; k < 16; k++) {
        float x = v[k];
        float e1 = fast_exp(x - m1);
        bool pos = x > 0.f;
        z1 += e1;
        if (pos) z2p += e1; else nneg += 1.f;
        v[k] = pos ? e1 : -e1;   // sign encodes (x>0)
    }
    block_reduce_sum3(z1, z2p, nneg, red);
    float Z1 = z1;
    float Z2 = z2p + nneg * Cneg;

    float ew0 = fast_exp(w_mix[0]), ew1 = fast_exp(w_mix[1]);
    float inv = 1.f / (ew0 + ew1);
    float iz1 = (ew0 * inv) / Z1;
    float iz2 = (ew1 * inv) / Z2;
    float Cn2 = Cneg * iz2;

    float za = 0.f;
    #pragma unroll
    for (int k = 0; k < 16; k++) {
        float se = v[k];
        float e1 = fabsf(se);
        float A = (se > 0.f) ? e1 * (iz1 + iz2) : fmaf(e1, iz1, Cn2);
        float e = fast_exp(A);   // A in (0,1]
        v[k] = e;
        za += e;
    }
    float ZA = block_reduce_sum(za, red);
    float izA = 1.f / ZA;

    half2 o[8];
    #pragma unroll
    for (int k = 0; k < 8; k++)
        o[k] = __floats2half2_rn(v[2 * k] * izA, v[2 * k + 1] * izA);
    ((uint4*)p)[tid * 2]     = *(uint4*)&o[0];
    ((uint4*)p)[tid * 2 + 1] = *(uint4*)&o[4];
}

// ---------------- finalize: out = stdT * mvn(content) + meanT ----------------
__global__ __launch_bounds__(256) void finalize_kernel(
    const float* __restrict__ content, const float* __restrict__ meanT,
    const float* __restrict__ stdT, float* __restrict__ out)
{
    __shared__ float red[32];
    int c = blockIdx.x, b = blockIdx.y;
    size_t off = ((size_t)b * 512 + c) * 4096;
    const float* x = content + off;
    int tid = threadIdx.x;

    float s = 0.f, ss = 0.f;
    for (int i = tid; i < 4096; i += 256) {
        float v = x[i];
        s += v; ss += v * v;
    }
    s = block_reduce_sum(s, red);
    ss = block_reduce_sum(ss, red);
    float mu = s * (1.f / 4096.f);
    float var = (ss - 4096.f * mu * mu) * (1.f / 4095.f);
    float rstd = rsqrtf(var + 1e-5f);

    for (int i = tid; i < 4096; i += 256)
        out[off + i] = stdT[off + i] * ((x[i] - mu) * rstd) + meanT[off + i];
}

// ---------------- launch ----------------
extern "C" void kernel_launch(void* const* d_in, const int* in_sizes, int n_in,
                              void* d_out, int out_size)
{
    const float* content     = (const float*)d_in[0];
    const float* style       = (const float*)d_in[1];
    const float* content_key = (const float*)d_in[2];
    const float* style_key   = (const float*)d_in[3];
    const float* f_w = (const float*)d_in[4];
    const float* f_b = (const float*)d_in[5];
    const float* g_w = (const float*)d_in[6];
    const float* g_b = (const float*)d_in[7];
    const float* h_w = (const float*)d_in[8];
    const float* h_b = (const float*)d_in[9];
    const float* w_mix = (const float*)d_in[10];
    float* out = (float*)d_out;

    typedef __nv_bfloat16 bf16;
    void *p;
    cudaGetSymbolAddress(&p, g_attn4);  half*  attn = (half*)p;   // logits & S, in place
    cudaGetSymbolAddress(&p, g_xth4);   bf16*  XTh  = (bf16*)p;
    cudaGetSymbolAddress(&p, g_xtl4);   bf16*  XTl  = (bf16*)p;
    cudaGetSymbolAddress(&p, g_wh4);    bf16*  Wh   = (bf16*)p;
    cudaGetSymbolAddress(&p, g_wl4);    bf16*  Wl   = (bf16*)p;
    cudaGetSymbolAddress(&p, g_Fh4);    bf16*  Fh   = (bf16*)p;
    cudaGetSymbolAddress(&p, g_Fl4);    bf16*  Fl   = (bf16*)p;
    cudaGetSymbolAddress(&p, g_Gh4);    bf16*  Gh   = (bf16*)p;
    cudaGetSymbolAddress(&p, g_Gl4);    bf16*  Gl   = (bf16*)p;
    cudaGetSymbolAddress(&p, g_HmT4);   float* HmT  = (float*)p;
    cudaGetSymbolAddress(&p, g_Hcat4);  half*  Hcat = (half*)p;
    cudaGetSymbolAddress(&p, g_meanT4); float* meanT= (float*)p;
    cudaGetSymbolAddress(&p, g_stdT4);  float* stdT = (float*)p;

    const size_t XN = 4ull * 4096 * 512;
    const size_t WN = 512ull * 512;

    const int SM3 = 2 * 4 * (128 * 80);    // 81920  (TERMS=3, KCH=32)
    const int SM1 = 2 * 2 * (128 * 144);   // 73728  (TERMS=1, KCH=64)
    cudaFuncSetAttribute((gemm16<bf16,3,32,2,1>), cudaFuncAttributeMaxDynamicSharedMemorySize, SM3);
    cudaFuncSetAttribute((gemm16<bf16,3,32,0,1>), cudaFuncAttributeMaxDynamicSharedMemorySize, SM3);
    cudaFuncSetAttribute((gemm16<bf16,3,32,1,0>), cudaFuncAttributeMaxDynamicSharedMemorySize, SM3);
    cudaFuncSetAttribute((gemm16<half,1,64,3,0>), cudaFuncAttributeMaxDynamicSharedMemorySize, SM1);

    // F chain (launches 0-2)
    transpose_split<<<dim3(128, 16, 4), dim3(32, 8)>>>(content_key, XTh + 0 * XN, XTl + 0 * XN);
    weight_split<<<dim3(1024), 256>>>(f_w, Wh + 0 * WN, Wl + 0 * WN, 262144);
    gemm16<bf16,3,32,2,1><<<dim3(4, 32, 4), 256, SM3>>>(XTh + 0 * XN, XTl + 0 * XN,
        Wh + 0 * WN, Wl + 0 * WN, f_b, nullptr, nullptr, nullptr, Fh, Fl,
        4096, 512, 512, 4096ull * 512, 0);

    // G chain (launches 3-5; ncu -s 5 captures conv_G)
    transpose_split<<<dim3(128, 16, 4), dim3(32, 8)>>>(style_key, XTh + 1 * XN, XTl + 1 * XN);
    weight_split<<<dim3(1024), 256>>>(g_w, Wh + 1 * WN, Wl + 1 * WN, 262144);
    gemm16<bf16,3,32,2,1><<<dim3(4, 32, 4), 256, SM3>>>(XTh + 1 * XN, XTl + 1 * XN,
        Wh + 1 * WN, Wl + 1 * WN, g_b, nullptr, nullptr, nullptr, Gh, Gl,
        4096, 512, 512, 4096ull * 512, 0);

    // H chain
    transpose_split<<<dim3(128, 16, 4), dim3(32, 8)>>>(style, XTh + 2 * XN, XTl + 2 * XN);
    weight_split<<<dim3(1024), 256>>>(h_w, Wh + 2 * WN, Wl + 2 * WN, 262144);
    gemm16<bf16,3,32,0,1><<<dim3(4, 32, 4), 256, SM3>>>(XTh + 2 * XN, XTl + 2 * XN,
        Wh + 2 * WN, Wl + 2 * WN, h_b, HmT, nullptr, nullptr, nullptr, nullptr,
        4096, 512, 512, 4096ull * 512, 0);

    // Hcat half [b][1024][4096], interleaved (H, H^2) rows
    transpose_sq_half<<<dim3(16, 128, 4), dim3(32, 8)>>>(HmT, Hcat);

    // attention logits (bf16x3) -> half attn buffer
    gemm16<bf16,3,32,1,0><<<dim3(32, 32, 4), 256, SM3>>>(Fh, Fl, Gh, Gl, nullptr,
        nullptr, nullptr, attn, nullptr, nullptr,
        4096, 4096, 512, 4096ull * 512, 4096ull * 512);

    // triple-softmax mix, in place (register-resident)
    softmax_mix_kernel<<<16384, 256>>>(attn, w_mix);

    // mean/second GEMM (fp16, KCH=64) -> meanT/stdT directly
    gemm16<half,1,64,3,0><<<dim3(8, 32, 4), 256, SM1>>>(attn, nullptr, Hcat, nullptr, nullptr,
        meanT, stdT, nullptr, nullptr, nullptr,
        4096, 1024, 4096, 4096ull * 4096, 1024ull * 4096);

    // finalize
    finalize_kernel<<<dim3(512, 4), 256>>>(content, meanT, stdT, out);
}

// round 11
// speedup vs baseline: 1.3565x; 1.1665x over previous
#include <cuda_runtime.h>
#include <cuda_bf16.h>
#include <cuda_fp16.h>
#include <math.h>
#include <stdint.h>

// ---------------- scratch (uint4 => 16B alignment for cp.async) ----------------
__device__ uint4 g_attn4 [8388608];    // half attn/S (in-place) [4][4096][4096]
__device__ uint4 g_xth4  [3145728];    // bf16 XT hi, 3 inputs x [4][4096][512]
__device__ uint4 g_xtl4  [3145728];    // bf16 XT lo
__device__ uint4 g_wh4   [98304];      // bf16 W hi, 3 x [512][512]
__device__ uint4 g_wl4   [98304];
__device__ uint4 g_Fh4   [1048576];    // half F hi [4][4096][512]
__device__ uint4 g_Fl4   [1048576];    // half F lo
__device__ uint4 g_Gh4   [1048576];    // half G hi (no lo needed: 2-term attn)
__device__ uint4 g_HmT4  [2097152];    // fp32 Hm [4][4096][512] ([n][c])
__device__ uint4 g_Hcat4 [2097152];    // half Hcat [4][1024][4096], rows interleaved (H[c],H^2[c])
__device__ uint4 g_meanT4[2097152];    // fp32 [4][512][4096]
__device__ uint4 g_stdT4 [2097152];

// ---------------- helpers ----------------
__device__ __forceinline__ uint32_t smem_u32(const void* p) {
    uint32_t a;
    asm("{ .reg .u64 t; cvta.to.shared.u64 t, %1; cvt.u32.u64 %0, t; }" : "=r"(a) : "l"(p));
    return a;
}
__device__ __forceinline__ void cp16(uint32_t dst, const void* src) {
    asm volatile("cp.async.ca.shared.global [%0], [%1], 16;" :: "r"(dst), "l"(src));
}
__device__ __forceinline__ void ldsm4(uint32_t* r, uint32_t addr) {
    asm volatile("ldmatrix.sync.aligned.m8n8.x4.shared.b16 {%0,%1,%2,%3}, [%4];"
        : "=r"(r[0]), "=r"(r[1]), "=r"(r[2]), "=r"(r[3]) : "r"(addr));
}
__device__ __forceinline__ void mma16(float* d, const uint32_t* a, const uint32_t* b,
                                      const __nv_bfloat16*) {
    asm volatile("mma.sync.aligned.m16n8k16.row.col.f32.bf16.bf16.f32 "
        "{%0,%1,%2,%3}, {%4,%5,%6,%7}, {%8,%9}, {%0,%1,%2,%3};"
        : "+f"(d[0]), "+f"(d[1]), "+f"(d[2]), "+f"(d[3])
        : "r"(a[0]), "r"(a[1]), "r"(a[2]), "r"(a[3]), "r"(b[0]), "r"(b[1]));
}
__device__ __forceinline__ void mma16(float* d, const uint32_t* a, const uint32_t* b,
                                      const half*) {
    asm volatile("mma.sync.aligned.m16n8k16.row.col.f32.f16.f16.f32 "
        "{%0,%1,%2,%3}, {%4,%5,%6,%7}, {%8,%9}, {%0,%1,%2,%3};"
        : "+f"(d[0]), "+f"(d[1]), "+f"(d[2]), "+f"(d[3])
        : "r"(a[0]), "r"(a[1]), "r"(a[2]), "r"(a[3]), "r"(b[0]), "r"(b[1]));
}

// FMA-only exp (Schraudolph round + deg-6 Taylor of 2^f), rel err ~1.5e-7.
__device__ __forceinline__ float fast_exp(float x) {
    x = fmaxf(x, -80.f);
    float t = x * 1.44269504088896f;
    float z = t + 12582912.f;
    int   i = __float_as_int(z) - 0x4B400000;
    float f = t - (z - 12582912.f);
    float p = 1.53989037e-4f;
    p = fmaf(p, f, 1.33335581e-3f);
    p = fmaf(p, f, 9.61812910e-3f);
    p = fmaf(p, f, 5.55041087e-2f);
    p = fmaf(p, f, 2.40226507e-1f);
    p = fmaf(p, f, 6.93147181e-1f);
    p = fmaf(p, f, 1.0f);
    return __int_as_float(__float_as_int(p) + (i << 23));
}

// FMA-only sqrt via bit-hack rsqrt + 2 Newton iters.
__device__ __forceinline__ float fast_sqrt(float v) {
    float x = fmaxf(v, 1e-30f);
    float xh = 0.5f * x;
    float y = __int_as_float(0x5f375a86 - (__float_as_int(x) >> 1));
    y = y * fmaf(-xh, y * y, 1.5f);
    y = y * fmaf(-xh, y * y, 1.5f);
    return v * y;
}

// ---------------- GEMM: C[b][m][n] = sum_k A[m][k]*B[n][k] (+bias[n]) ----------------
// TERMS=3: AhBh+AlBh+AhBl; TERMS=2: AhBh+AlBh (B hi only); TERMS=1: hi only.
// Block 128x128xKCH, 8 warps (2m x 4n), warp tile 64x32, cp.async double buffer,
// ldmatrix loads. smem tile order: Ah, Bh, Al, Bl.
// OUTM: 0=fp32 (Cf), 1=half (Chf), 3=mean/std direct (Cf=meanT, Cf2=stdT [b][N/2][M]),
//       4=half hi/lo split (Chf=hi, Chf2=lo).
template<typename T, int TERMS, int KCH, int OUTM, int HAS_BIAS>
__global__ __launch_bounds__(256, 2) void gemm16(
    const T* __restrict__ Ah, const T* __restrict__ Al,
    const T* __restrict__ Bh, const T* __restrict__ Bl,
    const float* __restrict__ bias,
    float* __restrict__ Cf, float* __restrict__ Cf2,
    half* __restrict__ Chf, half* __restrict__ Chf2,
    int M, int N, int K, size_t sA, size_t sB)
{
    extern __shared__ char smem[];
    const int tid = threadIdx.x, lane = tid & 31, wid = tid >> 5;
    const int b = blockIdx.z;
    const int n0 = blockIdx.x * 128, m0 = blockIdx.y * 128;
    const T* Agh = Ah + (size_t)b * sA + (size_t)m0 * K;
    const T* Bgh = Bh + (size_t)b * sB + (size_t)n0 * K;
    const T* Agl = (TERMS >= 2) ? (Al + (size_t)b * sA + (size_t)m0 * K) : nullptr;
    const T* Bgl = (TERMS == 3) ? (Bl + (size_t)b * sB + (size_t)n0 * K) : nullptr;

    const uint32_t sb = smem_u32(smem);
    constexpr uint32_t ST  = KCH * 2 + 16;
    constexpr uint32_t TL  = 128u * ST;
    constexpr uint32_t BUF = (TERMS == 3 ? 4u : (TERMS == 2 ? 3u : 2u)) * TL;
    constexpr int LPR = KCH / 8;
    constexpr int PP  = (128 * LPR) / 256;

    const int wm = (wid >> 2) * 64, wn = (wid & 3) * 32;

    float acc[4][4][4];
    #pragma unroll
    for (int i = 0; i < 4; i++)
        #pragma unroll
        for (int j = 0; j < 4; j++)
            #pragma unroll
            for (int r = 0; r < 4; r++) acc[i][j][r] = 0.f;

    auto stage = [&](int ch, int buf) {
        uint32_t base = sb + buf * BUF;
        #pragma unroll
        for (int it = 0; it < PP; it++) {
            int idx = tid + it * 256;
            int r = idx / LPR, f = idx % LPR;
            uint32_t off = r * ST + f * 16;
            size_t go = (size_t)r * K + ch * KCH + f * 8;
            cp16(base + off, Agh + go);
            cp16(base + TL + off, Bgh + go);
            if (TERMS >= 2) cp16(base + 2 * TL + off, Agl + go);
            if (TERMS == 3) cp16(base + 3 * TL + off, Bgl + go);
        }
        asm volatile("cp.async.commit_group;" ::: "memory");
    };

    const int t8 = lane >> 3, rr = lane & 7;
    const uint32_t a_off = (uint32_t)((t8 & 1) * 8 + rr) * ST + (t8 >> 1) * 16;
    const uint32_t b_off = (uint32_t)((t8 >> 1) * 8 + rr) * ST + (t8 & 1) * 16;

    const int NC = K / KCH;
    stage(0, 0);
    for (int ch = 0; ch < NC; ch++) {
        const int buf = ch & 1;
        if (ch + 1 < NC) {
            stage(ch + 1, buf ^ 1);
            asm volatile("cp.async.wait_group 1;" ::: "memory");
        } else {
            asm volatile("cp.async.wait_group 0;" ::: "memory");
        }
        __syncthreads();

        const uint32_t ab = sb + buf * BUF;
        const uint32_t bb = ab + TL;

        #pragma unroll
        for (int k16 = 0; k16 < KCH / 16; k16++) {
            const uint32_t kb = k16 * 32;
            uint32_t bhf[4][2], blf[4][2];
            #pragma unroll
            for (int pr = 0; pr < 2; pr++) {
                uint32_t r4[4];
                ldsm4(r4, bb + (uint32_t)(wn + pr * 16) * ST + b_off + kb);
                bhf[pr * 2][0] = r4[0]; bhf[pr * 2][1] = r4[1];
                bhf[pr * 2 + 1][0] = r4[2]; bhf[pr * 2 + 1][1] = r4[3];
                if (TERMS == 3) {
                    ldsm4(r4, ab + 3 * TL + (uint32_t)(wn + pr * 16) * ST + b_off + kb);
                    blf[pr * 2][0] = r4[0]; blf[pr * 2][1] = r4[1];
                    blf[pr * 2 + 1][0] = r4[2]; blf[pr * 2 + 1][1] = r4[3];
                }
            }
            #pragma unroll
            for (int im = 0; im < 4; im++) {
                uint32_t af[4];
                ldsm4(af, ab + (uint32_t)(wm + im * 16) * ST + a_off + kb);
                #pragma unroll
                for (int jn = 0; jn < 4; jn++) {
                    mma16(acc[im][jn], af, bhf[jn], (const T*)nullptr);
                    if (TERMS == 3) mma16(acc[im][jn], af, blf[jn], (const T*)nullptr);
                }
                if (TERMS >= 2) {
                    uint32_t alf[4];
                    ldsm4(alf, ab + 2 * TL + (uint32_t)(wm + im * 16) * ST + a_off + kb);
                    #pragma unroll
                    for (int jn = 0; jn < 4; jn++)
                        mma16(acc[im][jn], alf, bhf[jn], (const T*)nullptr);
                }
            }
        }
        __syncthreads();
    }

    // epilogue
    #pragma unroll
    for (int im = 0; im < 4; im++) {
        int r = m0 + wm + im * 16 + (lane >> 2);
        #pragma unroll
        for (int jn = 0; jn < 4; jn++) {
            int cc = n0 + wn + jn * 8 + (lane & 3) * 2;
            float b0 = 0.f, b1 = 0.f;
            if (HAS_BIAS) { b0 = __ldg(&bias[cc]); b1 = __ldg(&bias[cc + 1]); }
            float v00 = acc[im][jn][0] + b0, v01 = acc[im][jn][1] + b1;
            float v10 = acc[im][jn][2] + b0, v11 = acc[im][jn][3] + b1;
            if constexpr (OUTM == 3) {
                // (v00,v01) = (mean, second) of channel cc/2 at row r; (v10,v11) at r+8
                size_t base = ((size_t)b * (N >> 1) + (cc >> 1)) * (size_t)M;
                Cf [base + r]     = v00;
                Cf2[base + r]     = fast_sqrt(fmaxf(v01 - v00 * v00, 0.f));
                Cf [base + r + 8] = v10;
                Cf2[base + r + 8] = fast_sqrt(fmaxf(v11 - v10 * v10, 0.f));
            } else {
                size_t o0 = (size_t)b * (size_t)M * N + (size_t)r * N + cc;
                size_t o1 = o0 + (size_t)8 * N;
                if constexpr (OUTM == 4) {
                    half h00 = __float2half_rn(v00), h01 = __float2half_rn(v01);
                    half h10 = __float2half_rn(v10), h11 = __float2half_rn(v11);
                    *(half2*)(Chf + o0) = half2(h00, h01);
                    *(half2*)(Chf + o1) = half2(h10, h11);
                    *(half2*)(Chf2 + o0) = half2(
                        __float2half_rn(v00 - __half2float(h00)),
                        __float2half_rn(v01 - __half2float(h01)));
                    *(half2*)(Chf2 + o1) = half2(
                        __float2half_rn(v10 - __half2float(h10)),
                        __float2half_rn(v11 - __half2float(h11)));
                } else if constexpr (OUTM == 1) {
                    *(half2*)(Chf + o0) = __floats2half2_rn(v00, v01);
                    *(half2*)(Chf + o1) = __floats2half2_rn(v10, v11);
                } else {
                    *(float2*)(Cf + o0) = make_float2(v00, v01);
                    *(float2*)(Cf + o1) = make_float2(v10, v11);
                }
            }
        }
    }
}

// ---------------- transpose+split: fp32 [b][512][4096] -> hi/lo bf16 [b][4096][512] ----------------
__global__ void transpose_split(const float* __restrict__ src,
                                __nv_bfloat16* __restrict__ dh, __nv_bfloat16* __restrict__ dl)
{
    __shared__ float t[32][33];
    int b = blockIdx.z;
    const float* s = src + (size_t)b * 512ull * 4096ull;
    size_t dbo = (size_t)b * 512ull * 4096ull;
    int c0 = blockIdx.x * 32, r0 = blockIdx.y * 32;
    int tx = threadIdx.x, ty = threadIdx.y;
    #pragma unroll
    for (int k = 0; k < 4; k++)
        t[ty + k * 8][tx] = s[(size_t)(r0 + ty + k * 8) * 4096 + c0 + tx];
    __syncthreads();
    #pragma unroll
    for (int k = 0; k < 4; k++) {
        float v = t[tx][ty + k * 8];
        size_t o = dbo + (size_t)(c0 + ty + k * 8) * 512 + r0 + tx;
        __nv_bfloat16 h = __float2bfloat16_rn(v);
        dh[o] = h;
        dl[o] = __float2bfloat16_rn(v - __bfloat162float(h));
    }
}

__global__ void weight_split(const float* __restrict__ w,
                             __nv_bfloat16* __restrict__ wh, __nv_bfloat16* __restrict__ wl, int n)
{
    int i = blockIdx.x * 256 + threadIdx.x;
    if (i < n) {
        float v = w[i];
        __nv_bfloat16 h = __float2bfloat16_rn(v);
        wh[i] = h;
        wl[i] = __float2bfloat16_rn(v - __bfloat162float(h));
    }
}

// HmT fp32 [b][4096(n)][512(c)] -> Hcat half [b][1024][4096], rows interleaved:
// row 2c = H[c][n], row 2c+1 = H[c][n]^2
__global__ void transpose_sq_half(const float* __restrict__ src, half* __restrict__ dst)
{
    __shared__ float t[32][33];
    int b = blockIdx.z;
    const float* s = src + (size_t)b * 4096ull * 512ull;
    half* d = dst + (size_t)b * 1024ull * 4096ull;
    int c0 = blockIdx.x * 32, n0 = blockIdx.y * 32;
    int tx = threadIdx.x, ty = threadIdx.y;
    #pragma unroll
    for (int k = 0; k < 4; k++)
        t[ty + k * 8][tx] = s[(size_t)(n0 + ty + k * 8) * 512 + c0 + tx];
    __syncthreads();
    #pragma unroll
    for (int k = 0; k < 4; k++) {
        float v = t[tx][ty + k * 8];
        int c = c0 + ty + k * 8;
        d[(size_t)(2 * c)     * 4096 + n0 + tx] = __float2half_rn(v);
        d[(size_t)(2 * c + 1) * 4096 + n0 + tx] = __float2half_rn(v * v);
    }
}

// ---------------- block reductions ----------------
__device__ __forceinline__ float block_reduce_max(float v, float* red) {
    #pragma unroll
    for (int o = 16; o > 0; o >>= 1) v = fmaxf(v, __shfl_xor_sync(0xffffffffu, v, o));
    int wid = threadIdx.x >> 5, lid = threadIdx.x & 31;
    if (lid == 0) red[wid] = v;
    __syncthreads();
    if (wid == 0) {
        v = (lid < 8) ? red[lid] : -1e30f;
        #pragma unroll
        for (int o = 4; o > 0; o >>= 1) v = fmaxf(v, __shfl_xor_sync(0xffffffffu, v, o));
        if (lid == 0) red[0] = v;
    }
    __syncthreads();
    float r = red[0];
    __syncthreads();
    return r;
}
__device__ __forceinline__ float block_reduce_sum(float v, float* red) {
    #pragma unroll
    for (int o = 16; o > 0; o >>= 1) v += __shfl_xor_sync(0xffffffffu, v, o);
    int wid = threadIdx.x >> 5, lid = threadIdx.x & 31;
    if (lid == 0) red[wid] = v;
    __syncthreads();
    if (wid == 0) {
        v = (lid < 8) ? red[lid] : 0.f;
        #pragma unroll
        for (int o = 4; o > 0; o >>= 1) v += __shfl_xor_sync(0xffffffffu, v, o);
        if (lid == 0) red[0] = v;
    }
    __syncthreads();
    float r = red[0];
    __syncthreads();
    return r;
}
// three sums in one barrier sequence
__device__ __forceinline__ void block_reduce_sum3(float& a, float& b, float& c, float* red) {
    #pragma unroll
    for (int o = 16; o > 0; o >>= 1) {
        a += __shfl_xor_sync(0xffffffffu, a, o);
        b += __shfl_xor_sync(0xffffffffu, b, o);
        c += __shfl_xor_sync(0xffffffffu, c, o);
    }
    int wid = threadIdx.x >> 5, lid = threadIdx.x & 31;
    if (lid == 0) { red[wid] = a; red[32 + wid] = b; red[64 + wid] = c; }
    __syncthreads();
    if (wid == 0) {
        a = (lid < 8) ? red[lid] : 0.f;
        b = (lid < 8) ? red[32 + lid] : 0.f;
        c = (lid < 8) ? red[64 + lid] : 0.f;
        #pragma unroll
        for (int o = 4; o > 0; o >>= 1) {
            a += __shfl_xor_sync(0xffffffffu, a, o);
            b += __shfl_xor_sync(0xffffffffu, b, o);
            c += __shfl_xor_sync(0xffffffffu, c, o);
        }
        if (lid == 0) { red[0] = a; red[32] = b; red[64] = c; }
    }
    __syncthreads();
    a = red[0]; b = red[32]; c = red[64];
    __syncthreads();
}

// ---------------- softmax mix: register-resident, half in/out, IN PLACE ----------------
__global__ __launch_bounds__(256) void softmax_mix_kernel(
    half* __restrict__ attn, const float* __restrict__ w_mix)
{
    __shared__ float red[96];
    half* p = attn + (size_t)blockIdx.x * 4096;
    int tid = threadIdx.x;

    uint4 u0 = ((const uint4*)p)[tid * 2];
    uint4 u1 = ((const uint4*)p)[tid * 2 + 1];
    float v[16];
    {
        const half2* h0 = (const half2*)&u0;
        const half2* h1 = (const half2*)&u1;
        #pragma unroll
        for (int k = 0; k < 4; k++) {
            float2 f0 = __half22float2(h0[k]);
            float2 f1 = __half22float2(h1[k]);
            v[2 * k] = f0.x; v[2 * k + 1] = f0.y;
            v[8 + 2 * k] = f1.x; v[8 + 2 * k + 1] = f1.y;
        }
    }

    float lmax = -1e30f;
    #pragma unroll
    for (int k = 0; k < 16; k++) lmax = fmaxf(lmax, v[k]);
    float m1 = block_reduce_max(lmax, red);
    float m2 = fmaxf(m1, 0.f);
    float Cneg = fast_exp(-m2);

    float z1 = 0.f, z2p = 0.f, nneg = 0.f;
    #pragma unroll
    for (int k = 0; k < 16; k++) {
        float x = v[k];
        float e1 = fast_exp(x - m1);
        bool pos = x > 0.f;
        z1 += e1;
        if (pos) z2p += e1; else nneg += 1.f;
        v[k] = pos ? e1 : -e1;
    }
    block_reduce_sum3(z1, z2p, nneg, red);
    float Z1 = z1;
    float Z2 = z2p + nneg * Cneg;

    float ew0 = fast_exp(w_mix[0]), ew1 = fast_exp(w_mix[1]);
    float inv = 1.f / (ew0 + ew1);
    float iz1 = (ew0 * inv) / Z1;
    float iz2 = (ew1 * inv) / Z2;
    float Cn2 = Cneg * iz2;

    float za = 0.f;
    #pragma unroll
    for (int k = 0; k < 16; k++) {
        float se = v[k];
        float e1 = fabsf(se);
        float A = (se > 0.f) ? e1 * (iz1 + iz2) : fmaf(e1, iz1, Cn2);
        float e = fast_exp(A);
        v[k] = e;
        za += e;
    }
    float ZA = block_reduce_sum(za, red);
    float izA = 1.f / ZA;

    half2 o[8];
    #pragma unroll
    for (int k = 0; k < 8; k++)
        o[k] = __floats2half2_rn(v[2 * k] * izA, v[2 * k + 1] * izA);
    ((uint4*)p)[tid * 2]     = *(uint4*)&o[0];
    ((uint4*)p)[tid * 2 + 1] = *(uint4*)&o[4];
}

// ---------------- finalize: out = stdT * mvn(content) + meanT ----------------
__global__ __launch_bounds__(256) void finalize_kernel(
    const float* __restrict__ content, const float* __restrict__ meanT,
    const float* __restrict__ stdT, float* __restrict__ out)
{
    __shared__ float red[32];
    int c = blockIdx.x, b = blockIdx.y;
    size_t off = ((size_t)b * 512 + c) * 4096;
    const float* x = content + off;
    int tid = threadIdx.x;

    float s = 0.f, ss = 0.f;
    for (int i = tid; i < 4096; i += 256) {
        float v = x[i];
        s += v; ss += v * v;
    }
    s = block_reduce_sum(s, red);
    ss = block_reduce_sum(ss, red);
    float mu = s * (1.f / 4096.f);
    float var = (ss - 4096.f * mu * mu) * (1.f / 4095.f);
    float rstd = rsqrtf(var + 1e-5f);

    for (int i = tid; i < 4096; i += 256)
        out[off + i] = stdT[off + i] * ((x[i] - mu) * rstd) + meanT[off + i];
}

// ---------------- launch ----------------
extern "C" void kernel_launch(void* const* d_in, const int* in_sizes, int n_in,
                              void* d_out, int out_size)
{
    const float* content     = (const float*)d_in[0];
    const float* style       = (const float*)d_in[1];
    const float* content_key = (const float*)d_in[2];
    const float* style_key   = (const float*)d_in[3];
    const float* f_w = (const float*)d_in[4];
    const float* f_b = (const float*)d_in[5];
    const float* g_w = (const float*)d_in[6];
    const float* g_b = (const float*)d_in[7];
    const float* h_w = (const float*)d_in[8];
    const float* h_b = (const float*)d_in[9];
    const float* w_mix = (const float*)d_in[10];
    float* out = (float*)d_out;

    typedef __nv_bfloat16 bf16;
    void *p;
    cudaGetSymbolAddress(&p, g_attn4);  half*  attn = (half*)p;   // logits & S, in place
    cudaGetSymbolAddress(&p, g_xth4);   bf16*  XTh  = (bf16*)p;
    cudaGetSymbolAddress(&p, g_xtl4);   bf16*  XTl  = (bf16*)p;
    cudaGetSymbolAddress(&p, g_wh4);    bf16*  Wh   = (bf16*)p;
    cudaGetSymbolAddress(&p, g_wl4);    bf16*  Wl   = (bf16*)p;
    cudaGetSymbolAddress(&p, g_Fh4);    half*  Fh   = (half*)p;
    cudaGetSymbolAddress(&p, g_Fl4);    half*  Fl   = (half*)p;
    cudaGetSymbolAddress(&p, g_Gh4);    half*  Gh   = (half*)p;
    cudaGetSymbolAddress(&p, g_HmT4);   float* HmT  = (float*)p;
    cudaGetSymbolAddress(&p, g_Hcat4);  half*  Hcat = (half*)p;
    cudaGetSymbolAddress(&p, g_meanT4); float* meanT= (float*)p;
    cudaGetSymbolAddress(&p, g_stdT4);  float* stdT = (float*)p;

    const size_t XN = 4ull * 4096 * 512;
    const size_t WN = 512ull * 512;

    const int SM3 = 2 * 4 * (128 * 80);    // 81920  (TERMS=3, KCH=32) — convs
    const int SM2 = 2 * 3 * (128 * 80);    // 61440  (TERMS=2, KCH=32) — attn
    const int SM1 = 2 * 2 * (128 * 144);   // 73728  (TERMS=1, KCH=64) — meansec
    cudaFuncSetAttribute((gemm16<bf16,3,32,4,1>), cudaFuncAttributeMaxDynamicSharedMemorySize, SM3);
    cudaFuncSetAttribute((gemm16<bf16,3,32,1,1>), cudaFuncAttributeMaxDynamicSharedMemorySize, SM3);
    cudaFuncSetAttribute((gemm16<bf16,3,32,0,1>), cudaFuncAttributeMaxDynamicSharedMemorySize, SM3);
    cudaFuncSetAttribute((gemm16<half,2,32,1,0>), cudaFuncAttributeMaxDynamicSharedMemorySize, SM2);
    cudaFuncSetAttribute((gemm16<half,1,64,3,0>), cudaFuncAttributeMaxDynamicSharedMemorySize, SM1);

    // F chain: conv F -> half hi/lo
    transpose_split<<<dim3(128, 16, 4), dim3(32, 8)>>>(content_key, XTh + 0 * XN, XTl + 0 * XN);
    weight_split<<<dim3(1024), 256>>>(f_w, Wh + 0 * WN, Wl + 0 * WN, 262144);
    gemm16<bf16,3,32,4,1><<<dim3(4, 32, 4), 256, SM3>>>(XTh + 0 * XN, XTl + 0 * XN,
        Wh + 0 * WN, Wl + 0 * WN, f_b, nullptr, nullptr, Fh, Fl,
        4096, 512, 512, 4096ull * 512, 0);

    // G chain: conv G -> half hi only (2-term attn never reads G lo)
    transpose_split<<<dim3(128, 16, 4), dim3(32, 8)>>>(style_key, XTh + 1 * XN, XTl + 1 * XN);
    weight_split<<<dim3(1024), 256>>>(g_w, Wh + 1 * WN, Wl + 1 * WN, 262144);
    gemm16<bf16,3,32,1,1><<<dim3(4, 32, 4), 256, SM3>>>(XTh + 1 * XN, XTl + 1 * XN,
        Wh + 1 * WN, Wl + 1 * WN, g_b, nullptr, nullptr, Gh, nullptr,
        4096, 512, 512, 4096ull * 512, 0);

    // H chain
    transpose_split<<<dim3(128, 16, 4), dim3(32, 8)>>>(style, XTh + 2 * XN, XTl + 2 * XN);
    weight_split<<<dim3(1024), 256>>>(h_w, Wh + 2 * WN, Wl + 2 * WN, 262144);
    gemm16<bf16,3,32,0,1><<<dim3(4, 32, 4), 256, SM3>>>(XTh + 2 * XN, XTl + 2 * XN,
        Wh + 2 * WN, Wl + 2 * WN, h_b, HmT, nullptr, nullptr, nullptr,
        4096, 512, 512, 4096ull * 512, 0);

    // Hcat half [b][1024][4096], interleaved (H, H^2) rows
    transpose_sq_half<<<dim3(16, 128, 4), dim3(32, 8)>>>(HmT, Hcat);

    // attention logits (fp16 2-term: FhGh + FlGh) -> half attn buffer
    gemm16<half,2,32,1,0><<<dim3(32, 32, 4), 256, SM2>>>(Fh, Fl, Gh, nullptr, nullptr,
        nullptr, nullptr, attn, nullptr,
        4096, 4096, 512, 4096ull * 512, 4096ull * 512);

    // triple-softmax mix, in place (register-resident)
    softmax_mix_kernel<<<16384, 256>>>(attn, w_mix);

    // mean/second GEMM (fp16, KCH=64) -> meanT/stdT directly
    gemm16<half,1,64,3,0><<<dim3(8, 32, 4), 256, SM1>>>(attn, nullptr, Hcat, nullptr, nullptr,
        meanT, stdT, nullptr, nullptr,
        4096, 1024, 4096, 4096ull * 4096, 1024ull * 4096);

    // finalize
    finalize_kernel<<<dim3(512, 4), 256>>>(content, meanT, stdT, out);
}

// round 12
// speedup vs baseline: 1.4499x; 1.0688x over previous
#include <cuda_runtime.h>
#include <cuda_fp16.h>
#include <math.h>
#include <stdint.h>

// ---------------- scratch (uint4 => 16B alignment for cp.async) ----------------
__device__ uint4 g_attn4 [8388608];    // half attn/S (in-place) [4][4096][4096]
__device__ uint4 g_xth4  [3145728];    // half XT hi, 3 inputs x [4][4096][512]
__device__ uint4 g_xtl4  [3145728];    // half XT lo
__device__ uint4 g_wh4   [49152];      // half W hi, 3 x [512][512]
__device__ uint4 g_Fh4   [1048576];    // half F hi [4][4096][512]
__device__ uint4 g_Fl4   [1048576];    // half F lo
__device__ uint4 g_Gh4   [1048576];    // half G hi (no lo: 2-term attn)
__device__ uint4 g_Hcat4 [2097152];    // half Hcat [4][1024][4096], rows interleaved (H[c],H^2[c])
__device__ uint4 g_meanT4[2097152];    // fp32 [4][512][4096]
__device__ uint4 g_stdT4 [2097152];

// ---------------- helpers ----------------
__device__ __forceinline__ uint32_t smem_u32(const void* p) {
    uint32_t a;
    asm("{ .reg .u64 t; cvta.to.shared.u64 t, %1; cvt.u32.u64 %0, t; }" : "=r"(a) : "l"(p));
    return a;
}
__device__ __forceinline__ void cp16(uint32_t dst, const void* src) {
    asm volatile("cp.async.ca.shared.global [%0], [%1], 16;" :: "r"(dst), "l"(src));
}
__device__ __forceinline__ void ldsm4(uint32_t* r, uint32_t addr) {
    asm volatile("ldmatrix.sync.aligned.m8n8.x4.shared.b16 {%0,%1,%2,%3}, [%4];"
        : "=r"(r[0]), "=r"(r[1]), "=r"(r[2]), "=r"(r[3]) : "r"(addr));
}
__device__ __forceinline__ void mma16(float* d, const uint32_t* a, const uint32_t* b) {
    asm volatile("mma.sync.aligned.m16n8k16.row.col.f32.f16.f16.f32 "
        "{%0,%1,%2,%3}, {%4,%5,%6,%7}, {%8,%9}, {%0,%1,%2,%3};"
        : "+f"(d[0]), "+f"(d[1]), "+f"(d[2]), "+f"(d[3])
        : "r"(a[0]), "r"(a[1]), "r"(a[2]), "r"(a[3]), "r"(b[0]), "r"(b[1]));
}

// FMA-only exp (Schraudolph round + deg-6 Taylor of 2^f), rel err ~1.5e-7.
__device__ __forceinline__ float fast_exp(float x) {
    x = fmaxf(x, -80.f);
    float t = x * 1.44269504088896f;
    float z = t + 12582912.f;
    int   i = __float_as_int(z) - 0x4B400000;
    float f = t - (z - 12582912.f);
    float p = 1.53989037e-4f;
    p = fmaf(p, f, 1.33335581e-3f);
    p = fmaf(p, f, 9.61812910e-3f);
    p = fmaf(p, f, 5.55041087e-2f);
    p = fmaf(p, f, 2.40226507e-1f);
    p = fmaf(p, f, 6.93147181e-1f);
    p = fmaf(p, f, 1.0f);
    return __int_as_float(__float_as_int(p) + (i << 23));
}

// FMA-only sqrt via bit-hack rsqrt + 2 Newton iters.
__device__ __forceinline__ float fast_sqrt(float v) {
    float x = fmaxf(v, 1e-30f);
    float xh = 0.5f * x;
    float y = __int_as_float(0x5f375a86 - (__float_as_int(x) >> 1));
    y = y * fmaf(-xh, y * y, 1.5f);
    y = y * fmaf(-xh, y * y, 1.5f);
    return v * y;
}

// ---------------- GEMM: C[b][m][n] = sum_k A[m][k]*B[n][k] (+bias[n]) ----------------
// TERMS=2: AhBh+AlBh (B hi only); TERMS=1: hi only.
// Block 128x128xKCH, 8 warps (2m x 4n), warp tile 64x32, cp.async double buffer,
// ldmatrix loads. smem tile order: Ah, Bh, Al.
// OUTM: 1=half (Chf), 3=mean/std direct (Cf=meanT, Cf2=stdT [b][N/2][M]),
//       4=half hi/lo split (Chf=hi, Chf2=lo),
//       5=Hcat direct: Chf[b][2N][M], row 2cc=val, row 2cc+1=val^2, column r.
template<int TERMS, int KCH, int OUTM, int HAS_BIAS>
__global__ __launch_bounds__(256, 2) void gemm16(
    const half* __restrict__ Ah, const half* __restrict__ Al,
    const half* __restrict__ Bh,
    const float* __restrict__ bias,
    float* __restrict__ Cf, float* __restrict__ Cf2,
    half* __restrict__ Chf, half* __restrict__ Chf2,
    int M, int N, int K, size_t sA, size_t sB)
{
    extern __shared__ char smem[];
    const int tid = threadIdx.x, lane = tid & 31, wid = tid >> 5;
    const int b = blockIdx.z;
    const int n0 = blockIdx.x * 128, m0 = blockIdx.y * 128;
    const half* Agh = Ah + (size_t)b * sA + (size_t)m0 * K;
    const half* Bgh = Bh + (size_t)b * sB + (size_t)n0 * K;
    const half* Agl = (TERMS == 2) ? (Al + (size_t)b * sA + (size_t)m0 * K) : nullptr;

    const uint32_t sb = smem_u32(smem);
    constexpr uint32_t ST  = KCH * 2 + 16;
    constexpr uint32_t TL  = 128u * ST;
    constexpr uint32_t BUF = (TERMS == 2 ? 3u : 2u) * TL;
    constexpr int LPR = KCH / 8;
    constexpr int PP  = (128 * LPR) / 256;

    const int wm = (wid >> 2) * 64, wn = (wid & 3) * 32;

    float acc[4][4][4];
    #pragma unroll
    for (int i = 0; i < 4; i++)
        #pragma unroll
        for (int j = 0; j < 4; j++)
            #pragma unroll
            for (int r = 0; r < 4; r++) acc[i][j][r] = 0.f;

    auto stage = [&](int ch, int buf) {
        uint32_t base = sb + buf * BUF;
        #pragma unroll
        for (int it = 0; it < PP; it++) {
            int idx = tid + it * 256;
            int r = idx / LPR, f = idx % LPR;
            uint32_t off = r * ST + f * 16;
            size_t go = (size_t)r * K + ch * KCH + f * 8;
            cp16(base + off, Agh + go);
            cp16(base + TL + off, Bgh + go);
            if (TERMS == 2) cp16(base + 2 * TL + off, Agl + go);
        }
        asm volatile("cp.async.commit_group;" ::: "memory");
    };

    const int t8 = lane >> 3, rr = lane & 7;
    const uint32_t a_off = (uint32_t)((t8 & 1) * 8 + rr) * ST + (t8 >> 1) * 16;
    const uint32_t b_off = (uint32_t)((t8 >> 1) * 8 + rr) * ST + (t8 & 1) * 16;

    const int NC = K / KCH;
    stage(0, 0);
    for (int ch = 0; ch < NC; ch++) {
        const int buf = ch & 1;
        if (ch + 1 < NC) {
            stage(ch + 1, buf ^ 1);
            asm volatile("cp.async.wait_group 1;" ::: "memory");
        } else {
            asm volatile("cp.async.wait_group 0;" ::: "memory");
        }
        __syncthreads();

        const uint32_t ab = sb + buf * BUF;
        const uint32_t bb = ab + TL;

        #pragma unroll
        for (int k16 = 0; k16 < KCH / 16; k16++) {
            const uint32_t kb = k16 * 32;
            uint32_t bhf[4][2];
            #pragma unroll
            for (int pr = 0; pr < 2; pr++) {
                uint32_t r4[4];
                ldsm4(r4, bb + (uint32_t)(wn + pr * 16) * ST + b_off + kb);
                bhf[pr * 2][0] = r4[0]; bhf[pr * 2][1] = r4[1];
                bhf[pr * 2 + 1][0] = r4[2]; bhf[pr * 2 + 1][1] = r4[3];
            }
            #pragma unroll
            for (int im = 0; im < 4; im++) {
                uint32_t af[4];
                ldsm4(af, ab + (uint32_t)(wm + im * 16) * ST + a_off + kb);
                #pragma unroll
                for (int jn = 0; jn < 4; jn++)
                    mma16(acc[im][jn], af, bhf[jn]);
                if (TERMS == 2) {
                    uint32_t alf[4];
                    ldsm4(alf, ab + 2 * TL + (uint32_t)(wm + im * 16) * ST + a_off + kb);
                    #pragma unroll
                    for (int jn = 0; jn < 4; jn++)
                        mma16(acc[im][jn], alf, bhf[jn]);
                }
            }
        }
        __syncthreads();
    }

    // epilogue
    #pragma unroll
    for (int im = 0; im < 4; im++) {
        int r = m0 + wm + im * 16 + (lane >> 2);
        #pragma unroll
        for (int jn = 0; jn < 4; jn++) {
            int cc = n0 + wn + jn * 8 + (lane & 3) * 2;
            float b0 = 0.f, b1 = 0.f;
            if (HAS_BIAS) { b0 = __ldg(&bias[cc]); b1 = __ldg(&bias[cc + 1]); }
            float v00 = acc[im][jn][0] + b0, v01 = acc[im][jn][1] + b1;
            float v10 = acc[im][jn][2] + b0, v11 = acc[im][jn][3] + b1;
            if constexpr (OUTM == 3) {
                // (v00,v01) = (mean, second) of channel cc/2 at row r; (v10,v11) at r+8
                size_t base = ((size_t)b * (N >> 1) + (cc >> 1)) * (size_t)M;
                Cf [base + r]     = v00;
                Cf2[base + r]     = fast_sqrt(fmaxf(v01 - v00 * v00, 0.f));
                Cf [base + r + 8] = v10;
                Cf2[base + r + 8] = fast_sqrt(fmaxf(v11 - v10 * v10, 0.f));
            } else if constexpr (OUTM == 5) {
                // Hcat: [b][2N][M], row 2cc = value, row 2cc+1 = value^2, column r
                half* Hc = Chf + (size_t)b * (size_t)(2 * N) * (size_t)M;
                Hc[(size_t)(2 * cc)     * M + r]     = __float2half_rn(v00);
                Hc[(size_t)(2 * cc + 1) * M + r]     = __float2half_rn(v00 * v00);
                Hc[(size_t)(2 * cc + 2) * M + r]     = __float2half_rn(v01);
                Hc[(size_t)(2 * cc + 3) * M + r]     = __float2half_rn(v01 * v01);
                Hc[(size_t)(2 * cc)     * M + r + 8] = __float2half_rn(v10);
                Hc[(size_t)(2 * cc + 1) * M + r + 8] = __float2half_rn(v10 * v10);
                Hc[(size_t)(2 * cc + 2) * M + r + 8] = __float2half_rn(v11);
                Hc[(size_t)(2 * cc + 3) * M + r + 8] = __float2half_rn(v11 * v11);
            } else {
                size_t o0 = (size_t)b * (size_t)M * N + (size_t)r * N + cc;
                size_t o1 = o0 + (size_t)8 * N;
                if constexpr (OUTM == 4) {
                    half h00 = __float2half_rn(v00), h01 = __float2half_rn(v01);
                    half h10 = __float2half_rn(v10), h11 = __float2half_rn(v11);
                    *(half2*)(Chf + o0) = half2(h00, h01);
                    *(half2*)(Chf + o1) = half2(h10, h11);
                    *(half2*)(Chf2 + o0) = half2(
                        __float2half_rn(v00 - __half2float(h00)),
                        __float2half_rn(v01 - __half2float(h01)));
                    *(half2*)(Chf2 + o1) = half2(
                        __float2half_rn(v10 - __half2float(h10)),
                        __float2half_rn(v11 - __half2float(h11)));
                } else {
                    *(half2*)(Chf + o0) = __floats2half2_rn(v00, v01);
                    *(half2*)(Chf + o1) = __floats2half2_rn(v10, v11);
                }
            }
        }
    }
}

// ---------------- transpose+split: fp32 [b][512][4096] -> hi/lo half [b][4096][512] ----------------
__global__ void transpose_split(const float* __restrict__ src,
                                half* __restrict__ dh, half* __restrict__ dl)
{
    __shared__ float t[32][33];
    int b = blockIdx.z;
    const float* s = src + (size_t)b * 512ull * 4096ull;
    size_t dbo = (size_t)b * 512ull * 4096ull;
    int c0 = blockIdx.x * 32, r0 = blockIdx.y * 32;
    int tx = threadIdx.x, ty = threadIdx.y;
    #pragma unroll
    for (int k = 0; k < 4; k++)
        t[ty + k * 8][tx] = s[(size_t)(r0 + ty + k * 8) * 4096 + c0 + tx];
    __syncthreads();
    #pragma unroll
    for (int k = 0; k < 4; k++) {
        float v = t[tx][ty + k * 8];
        size_t o = dbo + (size_t)(c0 + ty + k * 8) * 512 + r0 + tx;
        half h = __float2half_rn(v);
        dh[o] = h;
        dl[o] = __float2half_rn(v - __half2float(h));
    }
}

__global__ void weight_to_half(const float* __restrict__ w, half* __restrict__ wh, int n)
{
    int i = blockIdx.x * 256 + threadIdx.x;
    if (i < n) wh[i] = __float2half_rn(w[i]);
}

// ---------------- block reductions ----------------
__device__ __forceinline__ float block_reduce_max(float v, float* red) {
    #pragma unroll
    for (int o = 16; o > 0; o >>= 1) v = fmaxf(v, __shfl_xor_sync(0xffffffffu, v, o));
    int wid = threadIdx.x >> 5, lid = threadIdx.x & 31;
    if (lid == 0) red[wid] = v;
    __syncthreads();
    if (wid == 0) {
        v = (lid < 8) ? red[lid] : -1e30f;
        #pragma unroll
        for (int o = 4; o > 0; o >>= 1) v = fmaxf(v, __shfl_xor_sync(0xffffffffu, v, o));
        if (lid == 0) red[0] = v;
    }
    __syncthreads();
    float r = red[0];
    __syncthreads();
    return r;
}
__device__ __forceinline__ float block_reduce_sum(float v, float* red) {
    #pragma unroll
    for (int o = 16; o > 0; o >>= 1) v += __shfl_xor_sync(0xffffffffu, v, o);
    int wid = threadIdx.x >> 5, lid = threadIdx.x & 31;
    if (lid == 0) red[wid] = v;
    __syncthreads();
    if (wid == 0) {
        v = (lid < 8) ? red[lid] : 0.f;
        #pragma unroll
        for (int o = 4; o > 0; o >>= 1) v += __shfl_xor_sync(0xffffffffu, v, o);
        if (lid == 0) red[0] = v;
    }
    __syncthreads();
    float r = red[0];
    __syncthreads();
    return r;
}
__device__ __forceinline__ void block_reduce_sum3(float& a, float& b, float& c, float* red) {
    #pragma unroll
    for (int o = 16; o > 0; o >>= 1) {
        a += __shfl_xor_sync(0xffffffffu, a, o);
        b += __shfl_xor_sync(0xffffffffu, b, o);
        c += __shfl_xor_sync(0xffffffffu, c, o);
    }
    int wid = threadIdx.x >> 5, lid = threadIdx.x & 31;
    if (lid == 0) { red[wid] = a; red[32 + wid] = b; red[64 + wid] = c; }
    __syncthreads();
    if (wid == 0) {
        a = (lid < 8) ? red[lid] : 0.f;
        b = (lid < 8) ? red[32 + lid] : 0.f;
        c = (lid < 8) ? red[64 + lid] : 0.f;
        #pragma unroll
        for (int o = 4; o > 0; o >>= 1) {
            a += __shfl_xor_sync(0xffffffffu, a, o);
            b += __shfl_xor_sync(0xffffffffu, b, o);
            c += __shfl_xor_sync(0xffffffffu, c, o);
        }
        if (lid == 0) { red[0] = a; red[32] = b; red[64] = c; }
    }
    __syncthreads();
    a = red[0]; b = red[32]; c = red[64];
    __syncthreads();
}

// ---------------- softmax mix: register-resident, half in/out, IN PLACE ----------------
__global__ __launch_bounds__(256) void softmax_mix_kernel(
    half* __restrict__ attn, const float* __restrict__ w_mix)
{
    __shared__ float red[96];
    half* p = attn + (size_t)blockIdx.x * 4096;
    int tid = threadIdx.x;

    uint4 u0 = ((const uint4*)p)[tid * 2];
    uint4 u1 = ((const uint4*)p)[tid * 2 + 1];
    float v[16];
    {
        const half2* h0 = (const half2*)&u0;
        const half2* h1 = (const half2*)&u1;
        #pragma unroll
        for (int k = 0; k < 4; k++) {
            float2 f0 = __half22float2(h0[k]);
            float2 f1 = __half22float2(h1[k]);
            v[2 * k] = f0.x; v[2 * k + 1] = f0.y;
            v[8 + 2 * k] = f1.x; v[8 + 2 * k + 1] = f1.y;
        }
    }

    float lmax = -1e30f;
    #pragma unroll
    for (int k = 0; k < 16; k++) lmax = fmaxf(lmax, v[k]);
    float m1 = block_reduce_max(lmax, red);
    float m2 = fmaxf(m1, 0.f);
    float Cneg = fast_exp(-m2);

    float z1 = 0.f, z2p = 0.f, nneg = 0.f;
    #pragma unroll
    for (int k = 0; k < 16; k++) {
        float x = v[k];
        float e1 = fast_exp(x - m1);
        bool pos = x > 0.f;
        z1 += e1;
        if (pos) z2p += e1; else nneg += 1.f;
        v[k] = pos ? e1 : -e1;
    }
    block_reduce_sum3(z1, z2p, nneg, red);
    float Z1 = z1;
    float Z2 = z2p + nneg * Cneg;

    float ew0 = fast_exp(w_mix[0]), ew1 = fast_exp(w_mix[1]);
    float inv = 1.f / (ew0 + ew1);
    float iz1 = (ew0 * inv) / Z1;
    float iz2 = (ew1 * inv) / Z2;
    float Cn2 = Cneg * iz2;

    float za = 0.f;
    #pragma unroll
    for (int k = 0; k < 16; k++) {
        float se = v[k];
        float e1 = fabsf(se);
        float A = (se > 0.f) ? e1 * (iz1 + iz2) : fmaf(e1, iz1, Cn2);
        float e = fast_exp(A);
        v[k] = e;
        za += e;
    }
    float ZA = block_reduce_sum(za, red);
    float izA = 1.f / ZA;

    half2 o[8];
    #pragma unroll
    for (int k = 0; k < 8; k++)
        o[k] = __floats2half2_rn(v[2 * k] * izA, v[2 * k + 1] * izA);
    ((uint4*)p)[tid * 2]     = *(uint4*)&o[0];
    ((uint4*)p)[tid * 2 + 1] = *(uint4*)&o[4];
}

// ---------------- finalize: out = stdT * mvn(content) + meanT ----------------
__global__ __launch_bounds__(256) void finalize_kernel(
    const float* __restrict__ content, const float* __restrict__ meanT,
    const float* __restrict__ stdT, float* __restrict__ out)
{
    __shared__ float red[32];
    int c = blockIdx.x, b = blockIdx.y;
    size_t off = ((size_t)b * 512 + c) * 4096;
    const float* x = content + off;
    int tid = threadIdx.x;

    float s = 0.f, ss = 0.f;
    for (int i = tid; i < 4096; i += 256) {
        float v = x[i];
        s += v; ss += v * v;
    }
    s = block_reduce_sum(s, red);
    ss = block_reduce_sum(ss, red);
    float mu = s * (1.f / 4096.f);
    float var = (ss - 4096.f * mu * mu) * (1.f / 4095.f);
    float rstd = rsqrtf(var + 1e-5f);

    for (int i = tid; i < 4096; i += 256)
        out[off + i] = stdT[off + i] * ((x[i] - mu) * rstd) + meanT[off + i];
}

// ---------------- launch ----------------
extern "C" void kernel_launch(void* const* d_in, const int* in_sizes, int n_in,
                              void* d_out, int out_size)
{
    const float* content     = (const float*)d_in[0];
    const float* style       = (const float*)d_in[1];
    const float* content_key = (const float*)d_in[2];
    const float* style_key   = (const float*)d_in[3];
    const float* f_w = (const float*)d_in[4];
    const float* f_b = (const float*)d_in[5];
    const float* g_w = (const float*)d_in[6];
    const float* g_b = (const float*)d_in[7];
    const float* h_w = (const float*)d_in[8];
    const float* h_b = (const float*)d_in[9];
    const float* w_mix = (const float*)d_in[10];
    float* out = (float*)d_out;

    void *p;
    cudaGetSymbolAddress(&p, g_attn4);  half*  attn = (half*)p;   // logits & S, in place
    cudaGetSymbolAddress(&p, g_xth4);   half*  XTh  = (half*)p;
    cudaGetSymbolAddress(&p, g_xtl4);   half*  XTl  = (half*)p;
    cudaGetSymbolAddress(&p, g_wh4);    half*  Wh   = (half*)p;
    cudaGetSymbolAddress(&p, g_Fh4);    half*  Fh   = (half*)p;
    cudaGetSymbolAddress(&p, g_Fl4);    half*  Fl   = (half*)p;
    cudaGetSymbolAddress(&p, g_Gh4);    half*  Gh   = (half*)p;
    cudaGetSymbolAddress(&p, g_Hcat4);  half*  Hcat = (half*)p;
    cudaGetSymbolAddress(&p, g_meanT4); float* meanT= (float*)p;
    cudaGetSymbolAddress(&p, g_stdT4);  float* stdT = (float*)p;

    const size_t XN = 4ull * 4096 * 512;
    const size_t WN = 512ull * 512;

    const int SM2 = 2 * 3 * (128 * 80);    // 61440  (TERMS=2, KCH=32) — convs + attn
    const int SM1 = 2 * 2 * (128 * 144);   // 73728  (TERMS=1, KCH=64) — meansec
    cudaFuncSetAttribute((gemm16<2,32,4,1>), cudaFuncAttributeMaxDynamicSharedMemorySize, SM2);
    cudaFuncSetAttribute((gemm16<2,32,1,1>), cudaFuncAttributeMaxDynamicSharedMemorySize, SM2);
    cudaFuncSetAttribute((gemm16<2,32,5,1>), cudaFuncAttributeMaxDynamicSharedMemorySize, SM2);
    cudaFuncSetAttribute((gemm16<2,32,1,0>), cudaFuncAttributeMaxDynamicSharedMemorySize, SM2);
    cudaFuncSetAttribute((gemm16<1,64,3,0>), cudaFuncAttributeMaxDynamicSharedMemorySize, SM1);

    // F chain: conv F (fp16 2-term) -> half hi/lo
    transpose_split<<<dim3(128, 16, 4), dim3(32, 8)>>>(content_key, XTh + 0 * XN, XTl + 0 * XN);
    weight_to_half<<<dim3(1024), 256>>>(f_w, Wh + 0 * WN, 262144);
    gemm16<2,32,4,1><<<dim3(4, 32, 4), 256, SM2>>>(XTh + 0 * XN, XTl + 0 * XN,
        Wh + 0 * WN, f_b, nullptr, nullptr, Fh, Fl,
        4096, 512, 512, 4096ull * 512, 0);

    // G chain: conv G (fp16 2-term) -> half hi only
    transpose_split<<<dim3(128, 16, 4), dim3(32, 8)>>>(style_key, XTh + 1 * XN, XTl + 1 * XN);
    weight_to_half<<<dim3(1024), 256>>>(g_w, Wh + 1 * WN, 262144);
    gemm16<2,32,1,1><<<dim3(4, 32, 4), 256, SM2>>>(XTh + 1 * XN, XTl + 1 * XN,
        Wh + 1 * WN, g_b, nullptr, nullptr, Gh, nullptr,
        4096, 512, 512, 4096ull * 512, 0);

    // H chain: conv H (fp16 2-term) -> Hcat directly (interleaved (H, H^2) rows)
    transpose_split<<<dim3(128, 16, 4), dim3(32, 8)>>>(style, XTh + 2 * XN, XTl + 2 * XN);
    weight_to_half<<<dim3(1024), 256>>>(h_w, Wh + 2 * WN, 262144);
    gemm16<2,32,5,1><<<dim3(4, 32, 4), 256, SM2>>>(XTh + 2 * XN, XTl + 2 * XN,
        Wh + 2 * WN, h_b, nullptr, nullptr, Hcat, nullptr,
        4096, 512, 512, 4096ull * 512, 0);

    // attention logits (fp16 2-term: FhGh + FlGh) -> half attn buffer
    gemm16<2,32,1,0><<<dim3(32, 32, 4), 256, SM2>>>(Fh, Fl, Gh, nullptr,
        nullptr, nullptr, attn, nullptr,
        4096, 4096, 512, 4096ull * 512, 4096ull * 512);

    // triple-softmax mix, in place (register-resident)
    softmax_mix_kernel<<<16384, 256>>>(attn, w_mix);

    // mean/second GEMM (fp16, KCH=64) -> meanT/stdT directly
    gemm16<1,64,3,0><<<dim3(8, 32, 4), 256, SM1>>>(attn, nullptr, Hcat, nullptr,
        meanT, stdT, nullptr, nullptr,
        4096, 1024, 4096, 4096ull * 4096, 1024ull * 4096);

    // finalize
    finalize_kernel<<<dim3(512, 4), 256>>>(content, meanT, stdT, out);
}

// round 13
// speedup vs baseline: 1.4928x; 1.0296x over previous
#include <cuda_runtime.h>
#include <cuda_fp16.h>
#include <math.h>
#include <stdint.h>

// ---------------- scratch (uint4 => 16B alignment for cp.async) ----------------
__device__ uint4 g_attn4 [8388608];    // half attn/S (in-place) [4][4096][4096]
__device__ uint4 g_xth4  [3145728];    // half XT hi, 3 inputs x [4][4096][512]
__device__ uint4 g_xtl4  [3145728];    // half XT lo
__device__ uint4 g_wh4   [49152];      // half W hi, 3 x [512][512]
__device__ uint4 g_Fh4   [1048576];    // half F hi [4][4096][512]
__device__ uint4 g_Fl4   [1048576];    // half F lo
__device__ uint4 g_Gh4   [1048576];    // half G hi (no lo: 2-term attn)
__device__ uint4 g_Hcat4 [2097152];    // half Hcat [4][1024][4096], rows interleaved (H[c],H^2[c])
__device__ uint4 g_meanT4[2097152];    // fp32 [4][512][4096]
__device__ uint4 g_stdT4 [2097152];

// ---------------- helpers ----------------
__device__ __forceinline__ uint32_t smem_u32(const void* p) {
    uint32_t a;
    asm("{ .reg .u64 t; cvta.to.shared.u64 t, %1; cvt.u32.u64 %0, t; }" : "=r"(a) : "l"(p));
    return a;
}
__device__ __forceinline__ void cp16(uint32_t dst, const void* src) {
    asm volatile("cp.async.ca.shared.global [%0], [%1], 16;" :: "r"(dst), "l"(src));
}
__device__ __forceinline__ void ldsm4(uint32_t* r, uint32_t addr) {
    asm volatile("ldmatrix.sync.aligned.m8n8.x4.shared.b16 {%0,%1,%2,%3}, [%4];"
        : "=r"(r[0]), "=r"(r[1]), "=r"(r[2]), "=r"(r[3]) : "r"(addr));
}
__device__ __forceinline__ void mma16(float* d, const uint32_t* a, const uint32_t* b) {
    asm volatile("mma.sync.aligned.m16n8k16.row.col.f32.f16.f16.f32 "
        "{%0,%1,%2,%3}, {%4,%5,%6,%7}, {%8,%9}, {%0,%1,%2,%3};"
        : "+f"(d[0]), "+f"(d[1]), "+f"(d[2]), "+f"(d[3])
        : "r"(a[0]), "r"(a[1]), "r"(a[2]), "r"(a[3]), "r"(b[0]), "r"(b[1]));
}

// FMA-only exp (Schraudolph round + deg-6 Taylor of 2^f), rel err ~1.5e-7.
__device__ __forceinline__ float fast_exp(float x) {
    x = fmaxf(x, -80.f);
    float t = x * 1.44269504088896f;
    float z = t + 12582912.f;
    int   i = __float_as_int(z) - 0x4B400000;
    float f = t - (z - 12582912.f);
    float p = 1.53989037e-4f;
    p = fmaf(p, f, 1.33335581e-3f);
    p = fmaf(p, f, 9.61812910e-3f);
    p = fmaf(p, f, 5.55041087e-2f);
    p = fmaf(p, f, 2.40226507e-1f);
    p = fmaf(p, f, 6.93147181e-1f);
    p = fmaf(p, f, 1.0f);
    return __int_as_float(__float_as_int(p) + (i << 23));
}

// FMA-only sqrt via bit-hack rsqrt + 2 Newton iters.
__device__ __forceinline__ float fast_sqrt(float v) {
    float x = fmaxf(v, 1e-30f);
    float xh = 0.5f * x;
    float y = __int_as_float(0x5f375a86 - (__float_as_int(x) >> 1));
    y = y * fmaf(-xh, y * y, 1.5f);
    y = y * fmaf(-xh, y * y, 1.5f);
    return v * y;
}

// ---------------- GEMM: C[b][m][n] = sum_k A[m][k]*B[n][k] (+bias[n]) ----------------
// TERMS=2: AhBh+AlBh (B hi only); TERMS=1: hi only.
// Block 128x128xKCH, 8 warps (2m x 4n), warp tile 64x32, cp.async double buffer,
// ldmatrix loads. smem tile order: Ah, Bh, Al.
// OUTM: 1=half (Chf), 3=mean/std direct (Cf=meanT, Cf2=stdT [b][N/2][M]),
//       4=half hi/lo split (Chf=hi, Chf2=lo),
//       5=Hcat direct: Chf[b][2N][M], row 2cc=val, row 2cc+1=val^2, column r.
template<int TERMS, int KCH, int OUTM, int HAS_BIAS>
__global__ __launch_bounds__(256, 2) void gemm16(
    const half* __restrict__ Ah, const half* __restrict__ Al,
    const half* __restrict__ Bh,
    const float* __restrict__ bias,
    float* __restrict__ Cf, float* __restrict__ Cf2,
    half* __restrict__ Chf, half* __restrict__ Chf2,
    int M, int N, int K, size_t sA, size_t sB)
{
    extern __shared__ char smem[];
    const int tid = threadIdx.x, lane = tid & 31, wid = tid >> 5;
    const int b = blockIdx.z;
    const int n0 = blockIdx.x * 128, m0 = blockIdx.y * 128;
    const half* Agh = Ah + (size_t)b * sA + (size_t)m0 * K;
    const half* Bgh = Bh + (size_t)b * sB + (size_t)n0 * K;
    const half* Agl = (TERMS == 2) ? (Al + (size_t)b * sA + (size_t)m0 * K) : nullptr;

    const uint32_t sb = smem_u32(smem);
    constexpr uint32_t ST  = KCH * 2 + 16;
    constexpr uint32_t TL  = 128u * ST;
    constexpr uint32_t BUF = (TERMS == 2 ? 3u : 2u) * TL;
    constexpr int LPR = KCH / 8;
    constexpr int PP  = (128 * LPR) / 256;

    const int wm = (wid >> 2) * 64, wn = (wid & 3) * 32;

    float acc[4][4][4];
    #pragma unroll
    for (int i = 0; i < 4; i++)
        #pragma unroll
        for (int j = 0; j < 4; j++)
            #pragma unroll
            for (int r = 0; r < 4; r++) acc[i][j][r] = 0.f;

    auto stage = [&](int ch, int buf) {
        uint32_t base = sb + buf * BUF;
        #pragma unroll
        for (int it = 0; it < PP; it++) {
            int idx = tid + it * 256;
            int r = idx / LPR, f = idx % LPR;
            uint32_t off = r * ST + f * 16;
            size_t go = (size_t)r * K + ch * KCH + f * 8;
            cp16(base + off, Agh + go);
            cp16(base + TL + off, Bgh + go);
            if (TERMS == 2) cp16(base + 2 * TL + off, Agl + go);
        }
        asm volatile("cp.async.commit_group;" ::: "memory");
    };

    const int t8 = lane >> 3, rr = lane & 7;
    const uint32_t a_off = (uint32_t)((t8 & 1) * 8 + rr) * ST + (t8 >> 1) * 16;
    const uint32_t b_off = (uint32_t)((t8 >> 1) * 8 + rr) * ST + (t8 & 1) * 16;

    const int NC = K / KCH;
    stage(0, 0);
    for (int ch = 0; ch < NC; ch++) {
        const int buf = ch & 1;
        if (ch + 1 < NC) {
            stage(ch + 1, buf ^ 1);
            asm volatile("cp.async.wait_group 1;" ::: "memory");
        } else {
            asm volatile("cp.async.wait_group 0;" ::: "memory");
        }
        __syncthreads();

        const uint32_t ab = sb + buf * BUF;
        const uint32_t bb = ab + TL;

        #pragma unroll
        for (int k16 = 0; k16 < KCH / 16; k16++) {
            const uint32_t kb = k16 * 32;
            uint32_t bhf[4][2];
            #pragma unroll
            for (int pr = 0; pr < 2; pr++) {
                uint32_t r4[4];
                ldsm4(r4, bb + (uint32_t)(wn + pr * 16) * ST + b_off + kb);
                bhf[pr * 2][0] = r4[0]; bhf[pr * 2][1] = r4[1];
                bhf[pr * 2 + 1][0] = r4[2]; bhf[pr * 2 + 1][1] = r4[3];
            }
            #pragma unroll
            for (int im = 0; im < 4; im++) {
                uint32_t af[4];
                ldsm4(af, ab + (uint32_t)(wm + im * 16) * ST + a_off + kb);
                #pragma unroll
                for (int jn = 0; jn < 4; jn++)
                    mma16(acc[im][jn], af, bhf[jn]);
                if (TERMS == 2) {
                    uint32_t alf[4];
                    ldsm4(alf, ab + 2 * TL + (uint32_t)(wm + im * 16) * ST + a_off + kb);
                    #pragma unroll
                    for (int jn = 0; jn < 4; jn++)
                        mma16(acc[im][jn], alf, bhf[jn]);
                }
            }
        }
        __syncthreads();
    }

    // epilogue
    #pragma unroll
    for (int im = 0; im < 4; im++) {
        int r = m0 + wm + im * 16 + (lane >> 2);
        #pragma unroll
        for (int jn = 0; jn < 4; jn++) {
            int cc = n0 + wn + jn * 8 + (lane & 3) * 2;
            float b0 = 0.f, b1 = 0.f;
            if (HAS_BIAS) { b0 = __ldg(&bias[cc]); b1 = __ldg(&bias[cc + 1]); }
            float v00 = acc[im][jn][0] + b0, v01 = acc[im][jn][1] + b1;
            float v10 = acc[im][jn][2] + b0, v11 = acc[im][jn][3] + b1;
            if constexpr (OUTM == 3) {
                size_t base = ((size_t)b * (N >> 1) + (cc >> 1)) * (size_t)M;
                Cf [base + r]     = v00;
                Cf2[base + r]     = fast_sqrt(fmaxf(v01 - v00 * v00, 0.f));
                Cf [base + r + 8] = v10;
                Cf2[base + r + 8] = fast_sqrt(fmaxf(v11 - v10 * v10, 0.f));
            } else if constexpr (OUTM == 5) {
                half* Hc = Chf + (size_t)b * (size_t)(2 * N) * (size_t)M;
                Hc[(size_t)(2 * cc)     * M + r]     = __float2half_rn(v00);
                Hc[(size_t)(2 * cc + 1) * M + r]     = __float2half_rn(v00 * v00);
                Hc[(size_t)(2 * cc + 2) * M + r]     = __float2half_rn(v01);
                Hc[(size_t)(2 * cc + 3) * M + r]     = __float2half_rn(v01 * v01);
                Hc[(size_t)(2 * cc)     * M + r + 8] = __float2half_rn(v10);
                Hc[(size_t)(2 * cc + 1) * M + r + 8] = __float2half_rn(v10 * v10);
                Hc[(size_t)(2 * cc + 2) * M + r + 8] = __float2half_rn(v11);
                Hc[(size_t)(2 * cc + 3) * M + r + 8] = __float2half_rn(v11 * v11);
            } else {
                size_t o0 = (size_t)b * (size_t)M * N + (size_t)r * N + cc;
                size_t o1 = o0 + (size_t)8 * N;
                if constexpr (OUTM == 4) {
                    half h00 = __float2half_rn(v00), h01 = __float2half_rn(v01);
                    half h10 = __float2half_rn(v10), h11 = __float2half_rn(v11);
                    *(half2*)(Chf + o0) = half2(h00, h01);
                    *(half2*)(Chf + o1) = half2(h10, h11);
                    *(half2*)(Chf2 + o0) = half2(
                        __float2half_rn(v00 - __half2float(h00)),
                        __float2half_rn(v01 - __half2float(h01)));
                    *(half2*)(Chf2 + o1) = half2(
                        __float2half_rn(v10 - __half2float(h10)),
                        __float2half_rn(v11 - __half2float(h11)));
                } else {
                    *(half2*)(Chf + o0) = __floats2half2_rn(v00, v01);
                    *(half2*)(Chf + o1) = __floats2half2_rn(v10, v11);
                }
            }
        }
    }
}

// ---------------- transpose+split: fp32 [b][512][4096] -> hi/lo half [b][4096][512] ----------------
// half2 paired stores (2 channels per store).
__global__ void transpose_split(const float* __restrict__ src,
                                half* __restrict__ dh, half* __restrict__ dl)
{
    __shared__ float t[32][33];
    int b = blockIdx.z;
    const float* s = src + (size_t)b * 512ull * 4096ull;
    size_t dbo = (size_t)b * 512ull * 4096ull;
    int c0 = blockIdx.x * 32, r0 = blockIdx.y * 32;
    int tx = threadIdx.x, ty = threadIdx.y;
    int tid = ty * 32 + tx;
    #pragma unroll
    for (int k = 0; k < 4; k++)
        t[ty + k * 8][tx] = s[(size_t)(r0 + ty + k * 8) * 4096 + c0 + tx];
    __syncthreads();
    // store: 32 pixel-rows x 16 channel-pairs = 512 half2 stores, 2 passes
    #pragma unroll
    for (int ps = 0; ps < 2; ps++) {
        int idx = tid + ps * 256;
        int rr = idx >> 4;        // pixel offset 0..31
        int cp = idx & 15;        // channel pair
        float v0 = t[2 * cp][rr];
        float v1 = t[2 * cp + 1][rr];
        size_t o = dbo + (size_t)(c0 + rr) * 512 + r0 + 2 * cp;
        half h0 = __float2half_rn(v0), h1 = __float2half_rn(v1);
        *(half2*)(dh + o) = half2(h0, h1);
        *(half2*)(dl + o) = half2(__float2half_rn(v0 - __half2float(h0)),
                                  __float2half_rn(v1 - __half2float(h1)));
    }
}

// all three weights in one launch: blockIdx.y selects tensor
__global__ void weights_to_half(const float* __restrict__ w0, const float* __restrict__ w1,
                                const float* __restrict__ w2, half* __restrict__ wh)
{
    const float* w = (blockIdx.y == 0) ? w0 : (blockIdx.y == 1) ? w1 : w2;
    int i = blockIdx.x * 256 + threadIdx.x;
    wh[(size_t)blockIdx.y * 262144 + i] = __float2half_rn(w[i]);
}

// ---------------- block reductions ----------------
__device__ __forceinline__ float block_reduce_max(float v, float* red) {
    #pragma unroll
    for (int o = 16; o > 0; o >>= 1) v = fmaxf(v, __shfl_xor_sync(0xffffffffu, v, o));
    int wid = threadIdx.x >> 5, lid = threadIdx.x & 31;
    if (lid == 0) red[wid] = v;
    __syncthreads();
    if (wid == 0) {
        v = (lid < 8) ? red[lid] : -1e30f;
        #pragma unroll
        for (int o = 4; o > 0; o >>= 1) v = fmaxf(v, __shfl_xor_sync(0xffffffffu, v, o));
        if (lid == 0) red[0] = v;
    }
    __syncthreads();
    float r = red[0];
    __syncthreads();
    return r;
}
__device__ __forceinline__ float block_reduce_sum(float v, float* red) {
    #pragma unroll
    for (int o = 16; o > 0; o >>= 1) v += __shfl_xor_sync(0xffffffffu, v, o);
    int wid = threadIdx.x >> 5, lid = threadIdx.x & 31;
    if (lid == 0) red[wid] = v;
    __syncthreads();
    if (wid == 0) {
        v = (lid < 8) ? red[lid] : 0.f;
        #pragma unroll
        for (int o = 4; o > 0; o >>= 1) v += __shfl_xor_sync(0xffffffffu, v, o);
        if (lid == 0) red[0] = v;
    }
    __syncthreads();
    float r = red[0];
    __syncthreads();
    return r;
}
__device__ __forceinline__ void block_reduce_sum2(float& a, float& b, float* red) {
    #pragma unroll
    for (int o = 16; o > 0; o >>= 1) {
        a += __shfl_xor_sync(0xffffffffu, a, o);
        b += __shfl_xor_sync(0xffffffffu, b, o);
    }
    int wid = threadIdx.x >> 5, lid = threadIdx.x & 31;
    if (lid == 0) { red[wid] = a; red[32 + wid] = b; }
    __syncthreads();
    if (wid == 0) {
        a = (lid < 8) ? red[lid] : 0.f;
        b = (lid < 8) ? red[32 + lid] : 0.f;
        #pragma unroll
        for (int o = 4; o > 0; o >>= 1) {
            a += __shfl_xor_sync(0xffffffffu, a, o);
            b += __shfl_xor_sync(0xffffffffu, b, o);
        }
        if (lid == 0) { red[0] = a; red[32] = b; }
    }
    __syncthreads();
    a = red[0]; b = red[32];
    __syncthreads();
}
__device__ __forceinline__ void block_reduce_sum3(float& a, float& b, float& c, float* red) {
    #pragma unroll
    for (int o = 16; o > 0; o >>= 1) {
        a += __shfl_xor_sync(0xffffffffu, a, o);
        b += __shfl_xor_sync(0xffffffffu, b, o);
        c += __shfl_xor_sync(0xffffffffu, c, o);
    }
    int wid = threadIdx.x >> 5, lid = threadIdx.x & 31;
    if (lid == 0) { red[wid] = a; red[32 + wid] = b; red[64 + wid] = c; }
    __syncthreads();
    if (wid == 0) {
        a = (lid < 8) ? red[lid] : 0.f;
        b = (lid < 8) ? red[32 + lid] : 0.f;
        c = (lid < 8) ? red[64 + lid] : 0.f;
        #pragma unroll
        for (int o = 4; o > 0; o >>= 1) {
            a += __shfl_xor_sync(0xffffffffu, a, o);
            b += __shfl_xor_sync(0xffffffffu, b, o);
            c += __shfl_xor_sync(0xffffffffu, c, o);
        }
        if (lid == 0) { red[0] = a; red[32] = b; red[64] = c; }
    }
    __syncthreads();
    a = red[0]; b = red[32]; c = red[64];
    __syncthreads();
}

// ---------------- softmax mix: register-resident, half in/out, IN PLACE ----------------
__global__ __launch_bounds__(256) void softmax_mix_kernel(
    half* __restrict__ attn, const float* __restrict__ w_mix)
{
    __shared__ float red[96];
    half* p = attn + (size_t)blockIdx.x * 4096;
    int tid = threadIdx.x;

    uint4 u0 = ((const uint4*)p)[tid * 2];
    uint4 u1 = ((const uint4*)p)[tid * 2 + 1];
    float v[16];
    {
        const half2* h0 = (const half2*)&u0;
        const half2* h1 = (const half2*)&u1;
        #pragma unroll
        for (int k = 0; k < 4; k++) {
            float2 f0 = __half22float2(h0[k]);
            float2 f1 = __half22float2(h1[k]);
            v[2 * k] = f0.x; v[2 * k + 1] = f0.y;
            v[8 + 2 * k] = f1.x; v[8 + 2 * k + 1] = f1.y;
        }
    }

    float lmax = -1e30f;
    #pragma unroll
    for (int k = 0; k < 16; k++) lmax = fmaxf(lmax, v[k]);
    float m1 = block_reduce_max(lmax, red);
    float m2 = fmaxf(m1, 0.f);
    float Cneg = fast_exp(-m2);

    float z1 = 0.f, z2p = 0.f, nneg = 0.f;
    #pragma unroll
    for (int k = 0; k < 16; k++) {
        float x = v[k];
        float e1 = fast_exp(x - m1);
        bool pos = x > 0.f;
        z1 += e1;
        if (pos) z2p += e1; else nneg += 1.f;
        v[k] = pos ? e1 : -e1;
    }
    block_reduce_sum3(z1, z2p, nneg, red);
    float Z1 = z1;
    float Z2 = z2p + nneg * Cneg;

    float ew0 = fast_exp(w_mix[0]), ew1 = fast_exp(w_mix[1]);
    float inv = 1.f / (ew0 + ew1);
    float iz1 = (ew0 * inv) / Z1;
    float iz2 = (ew1 * inv) / Z2;
    float Cn2 = Cneg * iz2;

    float za = 0.f;
    #pragma unroll
    for (int k = 0; k < 16; k++) {
        float se = v[k];
        float e1 = fabsf(se);
        float A = (se > 0.f) ? e1 * (iz1 + iz2) : fmaf(e1, iz1, Cn2);
        float e = fast_exp(A);
        v[k] = e;
        za += e;
    }
    float ZA = block_reduce_sum(za, red);
    float izA = 1.f / ZA;

    half2 o[8];
    #pragma unroll
    for (int k = 0; k < 8; k++)
        o[k] = __floats2half2_rn(v[2 * k] * izA, v[2 * k + 1] * izA);
    ((uint4*)p)[tid * 2]     = *(uint4*)&o[0];
    ((uint4*)p)[tid * 2 + 1] = *(uint4*)&o[4];
}

// ---------------- finalize (register-resident): out = stdT * mvn(content) + meanT ----------------
__global__ __launch_bounds__(256) void finalize_kernel(
    const float* __restrict__ content, const float* __restrict__ meanT,
    const float* __restrict__ stdT, float* __restrict__ out)
{
    __shared__ float red[64];
    int c = blockIdx.x, b = blockIdx.y;
    size_t off = ((size_t)b * 512 + c) * 4096;
    const float4* x4 = (const float4*)(content + off);
    int tid = threadIdx.x;

    float v[16];
    float s = 0.f, ss = 0.f;
    #pragma unroll
    for (int k = 0; k < 4; k++) {
        float4 f = x4[tid * 4 + k];
        v[4 * k] = f.x; v[4 * k + 1] = f.y; v[4 * k + 2] = f.z; v[4 * k + 3] = f.w;
        s += f.x + f.y + f.z + f.w;
        ss += f.x * f.x + f.y * f.y + f.z * f.z + f.w * f.w;
    }
    block_reduce_sum2(s, ss, red);
    float mu = s * (1.f / 4096.f);
    float var = (ss - 4096.f * mu * mu) * (1.f / 4095.f);
    float rstd = rsqrtf(var + 1e-5f);

    const float4* m4 = (const float4*)(meanT + off);
    const float4* s4 = (const float4*)(stdT + off);
    float4* o4 = (float4*)(out + off);
    #pragma unroll
    for (int k = 0; k < 4; k++) {
        float4 mn = m4[tid * 4 + k];
        float4 sd = s4[tid * 4 + k];
        float4 o;
        o.x = sd.x * ((v[4 * k]     - mu) * rstd) + mn.x;
        o.y = sd.y * ((v[4 * k + 1] - mu) * rstd) + mn.y;
        o.z = sd.z * ((v[4 * k + 2] - mu) * rstd) + mn.z;
        o.w = sd.w * ((v[4 * k + 3] - mu) * rstd) + mn.w;
        o4[tid * 4 + k] = o;
    }
}

// ---------------- launch ----------------
extern "C" void kernel_launch(void* const* d_in, const int* in_sizes, int n_in,
                              void* d_out, int out_size)
{
    const float* content     = (const float*)d_in[0];
    const float* style       = (const float*)d_in[1];
    const float* content_key = (const float*)d_in[2];
    const float* style_key   = (const float*)d_in[3];
    const float* f_w = (const float*)d_in[4];
    const float* f_b = (const float*)d_in[5];
    const float* g_w = (const float*)d_in[6];
    const float* g_b = (const float*)d_in[7];
    const float* h_w = (const float*)d_in[8];
    const float* h_b = (const float*)d_in[9];
    const float* w_mix = (const float*)d_in[10];
    float* out = (float*)d_out;

    void *p;
    cudaGetSymbolAddress(&p, g_attn4);  half*  attn = (half*)p;   // logits & S, in place
    cudaGetSymbolAddress(&p, g_xth4);   half*  XTh  = (half*)p;
    cudaGetSymbolAddress(&p, g_xtl4);   half*  XTl  = (half*)p;
    cudaGetSymbolAddress(&p, g_wh4);    half*  Wh   = (half*)p;
    cudaGetSymbolAddress(&p, g_Fh4);    half*  Fh   = (half*)p;
    cudaGetSymbolAddress(&p, g_Fl4);    half*  Fl   = (half*)p;
    cudaGetSymbolAddress(&p, g_Gh4);    half*  Gh   = (half*)p;
    cudaGetSymbolAddress(&p, g_Hcat4);  half*  Hcat = (half*)p;
    cudaGetSymbolAddress(&p, g_meanT4); float* meanT= (float*)p;
    cudaGetSymbolAddress(&p, g_stdT4);  float* stdT = (float*)p;

    const size_t XN = 4ull * 4096 * 512;
    const size_t WN = 512ull * 512;

    const int SM2 = 2 * 3 * (128 * 144);   // 110592 (TERMS=2, KCH=64) — convs + attn
    const int SM1 = 2 * 2 * (128 * 144);   // 73728  (TERMS=1, KCH=64) — meansec
    cudaFuncSetAttribute((gemm16<2,64,4,1>), cudaFuncAttributeMaxDynamicSharedMemorySize, SM2);
    cudaFuncSetAttribute((gemm16<2,64,1,1>), cudaFuncAttributeMaxDynamicSharedMemorySize, SM2);
    cudaFuncSetAttribute((gemm16<2,64,5,1>), cudaFuncAttributeMaxDynamicSharedMemorySize, SM2);
    cudaFuncSetAttribute((gemm16<2,64,1,0>), cudaFuncAttributeMaxDynamicSharedMemorySize, SM2);
    cudaFuncSetAttribute((gemm16<1,64,3,0>), cudaFuncAttributeMaxDynamicSharedMemorySize, SM1);

    // weights (single launch)
    weights_to_half<<<dim3(1024, 3), 256>>>(f_w, g_w, h_w, Wh);

    // F chain: conv F (fp16 2-term) -> half hi/lo
    transpose_split<<<dim3(128, 16, 4), dim3(32, 8)>>>(content_key, XTh + 0 * XN, XTl + 0 * XN);
    gemm16<2,64,4,1><<<dim3(4, 32, 4), 256, SM2>>>(XTh + 0 * XN, XTl + 0 * XN,
        Wh + 0 * WN, f_b, nullptr, nullptr, Fh, Fl,
        4096, 512, 512, 4096ull * 512, 0);

    // G chain: conv G (fp16 2-term) -> half hi only
    transpose_split<<<dim3(128, 16, 4), dim3(32, 8)>>>(style_key, XTh + 1 * XN, XTl + 1 * XN);
    gemm16<2,64,1,1><<<dim3(4, 32, 4), 256, SM2>>>(XTh + 1 * XN, XTl + 1 * XN,
        Wh + 1 * WN, g_b, nullptr, nullptr, Gh, nullptr,
        4096, 512, 512, 4096ull * 512, 0);

    // H chain: conv H (fp16 2-term) -> Hcat directly (interleaved (H, H^2) rows)
    transpose_split<<<dim3(128, 16, 4), dim3(32, 8)>>>(style, XTh + 2 * XN, XTl + 2 * XN);
    gemm16<2,64,5,1><<<dim3(4, 32, 4), 256, SM2>>>(XTh + 2 * XN, XTl + 2 * XN,
        Wh + 2 * WN, h_b, nullptr, nullptr, Hcat, nullptr,
        4096, 512, 512, 4096ull * 512, 0);

    // attention logits (fp16 2-term: FhGh + FlGh) -> half attn buffer
    gemm16<2,64,1,0><<<dim3(32, 32, 4), 256, SM2>>>(Fh, Fl, Gh, nullptr,
        nullptr, nullptr, attn, nullptr,
        4096, 4096, 512, 4096ull * 512, 4096ull * 512);

    // triple-softmax mix, in place (register-resident)
    softmax_mix_kernel<<<16384, 256>>>(attn, w_mix);

    // mean/second GEMM (fp16, KCH=64) -> meanT/stdT directly
    gemm16<1,64,3,0><<<dim3(8, 32, 4), 256, SM1>>>(attn, nullptr, Hcat, nullptr,
        meanT, stdT, nullptr, nullptr,
        4096, 1024, 4096, 4096ull * 4096, 1024ull * 4096);

    // finalize (register-resident)
    finalize_kernel<<<dim3(512, 4), 256>>>(content, meanT, stdT, out);
}

// round 14
// speedup vs baseline: 1.7583x; 1.1779x over previous
#include <cuda_runtime.h>
#include <cuda_fp16.h>
#include <math.h>
#include <stdint.h>

// ---------------- scratch (uint4 => 16B alignment for cp.async) ----------------
__device__ uint4 g_attn4 [8388608];    // half attn/S (in-place) [4][4096][4096]
__device__ uint4 g_xth4  [3145728];    // half XT hi, 3 inputs x [4][4096][512]
__device__ uint4 g_xtl4  [3145728];    // half XT lo
__device__ uint4 g_wh4   [49152];      // half W hi, 3 x [512][512]
__device__ uint4 g_Fh4   [1048576];    // half F hi [4][4096][512]
__device__ uint4 g_Gh4   [1048576];    // half G hi
__device__ uint4 g_Hcat4 [2097152];    // half Hcat [4][1024][4096], rows interleaved (H[c],H^2[c])
__device__ uint4 g_meanT4[2097152];    // fp32 [4][512][4096]
__device__ uint4 g_stdT4 [2097152];

// ---------------- helpers ----------------
__device__ __forceinline__ uint32_t smem_u32(const void* p) {
    uint32_t a;
    asm("{ .reg .u64 t; cvta.to.shared.u64 t, %1; cvt.u32.u64 %0, t; }" : "=r"(a) : "l"(p));
    return a;
}
__device__ __forceinline__ void cp16(uint32_t dst, const void* src) {
    asm volatile("cp.async.ca.shared.global [%0], [%1], 16;" :: "r"(dst), "l"(src));
}
__device__ __forceinline__ void ldsm4(uint32_t* r, uint32_t addr) {
    asm volatile("ldmatrix.sync.aligned.m8n8.x4.shared.b16 {%0,%1,%2,%3}, [%4];"
        : "=r"(r[0]), "=r"(r[1]), "=r"(r[2]), "=r"(r[3]) : "r"(addr));
}
__device__ __forceinline__ void mma16(float* d, const uint32_t* a, const uint32_t* b) {
    asm volatile("mma.sync.aligned.m16n8k16.row.col.f32.f16.f16.f32 "
        "{%0,%1,%2,%3}, {%4,%5,%6,%7}, {%8,%9}, {%0,%1,%2,%3};"
        : "+f"(d[0]), "+f"(d[1]), "+f"(d[2]), "+f"(d[3])
        : "r"(a[0]), "r"(a[1]), "r"(a[2]), "r"(a[3]), "r"(b[0]), "r"(b[1]));
}

// FMA-only exp (Schraudolph round + deg-6 Taylor of 2^f), rel err ~1.5e-7.
__device__ __forceinline__ float fast_exp(float x) {
    x = fmaxf(x, -80.f);
    float t = x * 1.44269504088896f;
    float z = t + 12582912.f;
    int   i = __float_as_int(z) - 0x4B400000;
    float f = t - (z - 12582912.f);
    float p = 1.53989037e-4f;
    p = fmaf(p, f, 1.33335581e-3f);
    p = fmaf(p, f, 9.61812910e-3f);
    p = fmaf(p, f, 5.55041087e-2f);
    p = fmaf(p, f, 2.40226507e-1f);
    p = fmaf(p, f, 6.93147181e-1f);
    p = fmaf(p, f, 1.0f);
    return __int_as_float(__float_as_int(p) + (i << 23));
}

// FMA-only sqrt via bit-hack rsqrt + 2 Newton iters.
__device__ __forceinline__ float fast_sqrt(float v) {
    float x = fmaxf(v, 1e-30f);
    float xh = 0.5f * x;
    float y = __int_as_float(0x5f375a86 - (__float_as_int(x) >> 1));
    y = y * fmaf(-xh, y * y, 1.5f);
    y = y * fmaf(-xh, y * y, 1.5f);
    return v * y;
}

// ---------------- GEMM: C[b][m][n] = sum_k A[m][k]*B[n][k] (+bias[n]) ----------------
// TERMS=2: AhBh+AlBh (B hi only); TERMS=1: hi only.
// Block 128x128xKCH, 8 warps (2m x 4n), warp tile 64x32, cp.async double buffer,
// ldmatrix loads. smem tile order: Ah, Bh, Al.
// OUTM: 1=half (Chf), 3=mean/std direct (Cf=meanT, Cf2=stdT [b][N/2][M]),
//       5=Hcat direct: Chf[b][2N][M], row 2cc=val, row 2cc+1=val^2, column r.
template<int TERMS, int KCH, int OUTM, int HAS_BIAS>
__global__ __launch_bounds__(256, 2) void gemm16(
    const half* __restrict__ Ah, const half* __restrict__ Al,
    const half* __restrict__ Bh,
    const float* __restrict__ bias,
    float* __restrict__ Cf, float* __restrict__ Cf2,
    half* __restrict__ Chf,
    int M, int N, int K, size_t sA, size_t sB)
{
    extern __shared__ char smem[];
    const int tid = threadIdx.x, lane = tid & 31, wid = tid >> 5;
    const int b = blockIdx.z;
    const int n0 = blockIdx.x * 128, m0 = blockIdx.y * 128;
    const half* Agh = Ah + (size_t)b * sA + (size_t)m0 * K;
    const half* Bgh = Bh + (size_t)b * sB + (size_t)n0 * K;
    const half* Agl = (TERMS == 2) ? (Al + (size_t)b * sA + (size_t)m0 * K) : nullptr;

    const uint32_t sb = smem_u32(smem);
    constexpr uint32_t ST  = KCH * 2 + 16;
    constexpr uint32_t TL  = 128u * ST;
    constexpr uint32_t BUF = (TERMS == 2 ? 3u : 2u) * TL;
    constexpr int LPR = KCH / 8;
    constexpr int PP  = (128 * LPR) / 256;

    const int wm = (wid >> 2) * 64, wn = (wid & 3) * 32;

    float acc[4][4][4];
    #pragma unroll
    for (int i = 0; i < 4; i++)
        #pragma unroll
        for (int j = 0; j < 4; j++)
            #pragma unroll
            for (int r = 0; r < 4; r++) acc[i][j][r] = 0.f;

    auto stage = [&](int ch, int buf) {
        uint32_t base = sb + buf * BUF;
        #pragma unroll
        for (int it = 0; it < PP; it++) {
            int idx = tid + it * 256;
            int r = idx / LPR, f = idx % LPR;
            uint32_t off = r * ST + f * 16;
            size_t go = (size_t)r * K + ch * KCH + f * 8;
            cp16(base + off, Agh + go);
            cp16(base + TL + off, Bgh + go);
            if (TERMS == 2) cp16(base + 2 * TL + off, Agl + go);
        }
        asm volatile("cp.async.commit_group;" ::: "memory");
    };

    const int t8 = lane >> 3, rr = lane & 7;
    const uint32_t a_off = (uint32_t)((t8 & 1) * 8 + rr) * ST + (t8 >> 1) * 16;
    const uint32_t b_off = (uint32_t)((t8 >> 1) * 8 + rr) * ST + (t8 & 1) * 16;

    const int NC = K / KCH;
    stage(0, 0);
    for (int ch = 0; ch < NC; ch++) {
        const int buf = ch & 1;
        if (ch + 1 < NC) {
            stage(ch + 1, buf ^ 1);
            asm volatile("cp.async.wait_group 1;" ::: "memory");
        } else {
            asm volatile("cp.async.wait_group 0;" ::: "memory");
        }
        __syncthreads();

        const uint32_t ab = sb + buf * BUF;
        const uint32_t bb = ab + TL;

        #pragma unroll
        for (int k16 = 0; k16 < KCH / 16; k16++) {
            const uint32_t kb = k16 * 32;
            uint32_t bhf[4][2];
            #pragma unroll
            for (int pr = 0; pr < 2; pr++) {
                uint32_t r4[4];
                ldsm4(r4, bb + (uint32_t)(wn + pr * 16) * ST + b_off + kb);
                bhf[pr * 2][0] = r4[0]; bhf[pr * 2][1] = r4[1];
                bhf[pr * 2 + 1][0] = r4[2]; bhf[pr * 2 + 1][1] = r4[3];
            }
            #pragma unroll
            for (int im = 0; im < 4; im++) {
                uint32_t af[4];
                ldsm4(af, ab + (uint32_t)(wm + im * 16) * ST + a_off + kb);
                #pragma unroll
                for (int jn = 0; jn < 4; jn++)
                    mma16(acc[im][jn], af, bhf[jn]);
                if (TERMS == 2) {
                    uint32_t alf[4];
                    ldsm4(alf, ab + 2 * TL + (uint32_t)(wm + im * 16) * ST + a_off + kb);
                    #pragma unroll
                    for (int jn = 0; jn < 4; jn++)
                        mma16(acc[im][jn], alf, bhf[jn]);
                }
            }
        }
        __syncthreads();
    }

    // epilogue
    #pragma unroll
    for (int im = 0; im < 4; im++) {
        int r = m0 + wm + im * 16 + (lane >> 2);
        #pragma unroll
        for (int jn = 0; jn < 4; jn++) {
            int cc = n0 + wn + jn * 8 + (lane & 3) * 2;
            float b0 = 0.f, b1 = 0.f;
            if (HAS_BIAS) { b0 = __ldg(&bias[cc]); b1 = __ldg(&bias[cc + 1]); }
            float v00 = acc[im][jn][0] + b0, v01 = acc[im][jn][1] + b1;
            float v10 = acc[im][jn][2] + b0, v11 = acc[im][jn][3] + b1;
            if constexpr (OUTM == 3) {
                size_t base = ((size_t)b * (N >> 1) + (cc >> 1)) * (size_t)M;
                Cf [base + r]     = v00;
                Cf2[base + r]     = fast_sqrt(fmaxf(v01 - v00 * v00, 0.f));
                Cf [base + r + 8] = v10;
                Cf2[base + r + 8] = fast_sqrt(fmaxf(v11 - v10 * v10, 0.f));
            } else if constexpr (OUTM == 5) {
                half* Hc = Chf + (size_t)b * (size_t)(2 * N) * (size_t)M;
                Hc[(size_t)(2 * cc)     * M + r]     = __float2half_rn(v00);
                Hc[(size_t)(2 * cc + 1) * M + r]     = __float2half_rn(v00 * v00);
                Hc[(size_t)(2 * cc + 2) * M + r]     = __float2half_rn(v01);
                Hc[(size_t)(2 * cc + 3) * M + r]     = __float2half_rn(v01 * v01);
                Hc[(size_t)(2 * cc)     * M + r + 8] = __float2half_rn(v10);
                Hc[(size_t)(2 * cc + 1) * M + r + 8] = __float2half_rn(v10 * v10);
                Hc[(size_t)(2 * cc + 2) * M + r + 8] = __float2half_rn(v11);
                Hc[(size_t)(2 * cc + 3) * M + r + 8] = __float2half_rn(v11 * v11);
            } else {
                size_t o0 = (size_t)b * (size_t)M * N + (size_t)r * N + cc;
                size_t o1 = o0 + (size_t)8 * N;
                *(half2*)(Chf + o0) = __floats2half2_rn(v00, v01);
                *(half2*)(Chf + o1) = __floats2half2_rn(v10, v11);
            }
        }
    }
}

// ---------------- transpose+split: fp32 [b][512][4096] -> hi/lo half [b][4096][512] ----------------
// grid.z = 12: (input index = z/4, batch = z%4); src0/1/2 selected per input.
__global__ void transpose_split_all(const float* __restrict__ s0, const float* __restrict__ s1,
                                    const float* __restrict__ s2,
                                    half* __restrict__ dh, half* __restrict__ dl)
{
    __shared__ float t[32][33];
    int inp = blockIdx.z >> 2;
    int b = blockIdx.z & 3;
    const float* src = (inp == 0) ? s0 : (inp == 1) ? s1 : s2;
    const float* s = src + (size_t)b * 512ull * 4096ull;
    size_t dbo = ((size_t)inp * 4 + b) * 512ull * 4096ull;
    int c0 = blockIdx.x * 32, r0 = blockIdx.y * 32;
    int tx = threadIdx.x, ty = threadIdx.y;
    int tid = ty * 32 + tx;
    #pragma unroll
    for (int k = 0; k < 4; k++)
        t[ty + k * 8][tx] = s[(size_t)(r0 + ty + k * 8) * 4096 + c0 + tx];
    __syncthreads();
    #pragma unroll
    for (int ps = 0; ps < 2; ps++) {
        int idx = tid + ps * 256;
        int rr = idx >> 4;
        int cp = idx & 15;
        float v0 = t[2 * cp][rr];
        float v1 = t[2 * cp + 1][rr];
        size_t o = dbo + (size_t)(c0 + rr) * 512 + r0 + 2 * cp;
        half h0 = __float2half_rn(v0), h1 = __float2half_rn(v1);
        *(half2*)(dh + o) = half2(h0, h1);
        *(half2*)(dl + o) = half2(__float2half_rn(v0 - __half2float(h0)),
                                  __float2half_rn(v1 - __half2float(h1)));
    }
}

// all three weights in one launch: blockIdx.y selects tensor
__global__ void weights_to_half(const float* __restrict__ w0, const float* __restrict__ w1,
                                const float* __restrict__ w2, half* __restrict__ wh)
{
    const float* w = (blockIdx.y == 0) ? w0 : (blockIdx.y == 1) ? w1 : w2;
    int i = blockIdx.x * 256 + threadIdx.x;
    wh[(size_t)blockIdx.y * 262144 + i] = __float2half_rn(w[i]);
}

// ---------------- block reductions ----------------
__device__ __forceinline__ float block_reduce_max(float v, float* red) {
    #pragma unroll
    for (int o = 16; o > 0; o >>= 1) v = fmaxf(v, __shfl_xor_sync(0xffffffffu, v, o));
    int wid = threadIdx.x >> 5, lid = threadIdx.x & 31;
    if (lid == 0) red[wid] = v;
    __syncthreads();
    if (wid == 0) {
        v = (lid < 8) ? red[lid] : -1e30f;
        #pragma unroll
        for (int o = 4; o > 0; o >>= 1) v = fmaxf(v, __shfl_xor_sync(0xffffffffu, v, o));
        if (lid == 0) red[0] = v;
    }
    __syncthreads();
    float r = red[0];
    __syncthreads();
    return r;
}
__device__ __forceinline__ float block_reduce_sum(float v, float* red) {
    #pragma unroll
    for (int o = 16; o > 0; o >>= 1) v += __shfl_xor_sync(0xffffffffu, v, o);
    int wid = threadIdx.x >> 5, lid = threadIdx.x & 31;
    if (lid == 0) red[wid] = v;
    __syncthreads();
    if (wid == 0) {
        v = (lid < 8) ? red[lid] : 0.f;
        #pragma unroll
        for (int o = 4; o > 0; o >>= 1) v += __shfl_xor_sync(0xffffffffu, v, o);
        if (lid == 0) red[0] = v;
    }
    __syncthreads();
    float r = red[0];
    __syncthreads();
    return r;
}
__device__ __forceinline__ void block_reduce_sum2(float& a, float& b, float* red) {
    #pragma unroll
    for (int o = 16; o > 0; o >>= 1) {
        a += __shfl_xor_sync(0xffffffffu, a, o);
        b += __shfl_xor_sync(0xffffffffu, b, o);
    }
    int wid = threadIdx.x >> 5, lid = threadIdx.x & 31;
    if (lid == 0) { red[wid] = a; red[32 + wid] = b; }
    __syncthreads();
    if (wid == 0) {
        a = (lid < 8) ? red[lid] : 0.f;
        b = (lid < 8) ? red[32 + lid] : 0.f;
        #pragma unroll
        for (int o = 4; o > 0; o >>= 1) {
            a += __shfl_xor_sync(0xffffffffu, a, o);
            b += __shfl_xor_sync(0xffffffffu, b, o);
        }
        if (lid == 0) { red[0] = a; red[32] = b; }
    }
    __syncthreads();
    a = red[0]; b = red[32];
    __syncthreads();
}
__device__ __forceinline__ void block_reduce_sum3(float& a, float& b, float& c, float* red) {
    #pragma unroll
    for (int o = 16; o > 0; o >>= 1) {
        a += __shfl_xor_sync(0xffffffffu, a, o);
        b += __shfl_xor_sync(0xffffffffu, b, o);
        c += __shfl_xor_sync(0xffffffffu, c, o);
    }
    int wid = threadIdx.x >> 5, lid = threadIdx.x & 31;
    if (lid == 0) { red[wid] = a; red[32 + wid] = b; red[64 + wid] = c; }
    __syncthreads();
    if (wid == 0) {
        a = (lid < 8) ? red[lid] : 0.f;
        b = (lid < 8) ? red[32 + lid] : 0.f;
        c = (lid < 8) ? red[64 + lid] : 0.f;
        #pragma unroll
        for (int o = 4; o > 0; o >>= 1) {
            a += __shfl_xor_sync(0xffffffffu, a, o);
            b += __shfl_xor_sync(0xffffffffu, b, o);
            c += __shfl_xor_sync(0xffffffffu, c, o);
        }
        if (lid == 0) { red[0] = a; red[32] = b; red[64] = c; }
    }
    __syncthreads();
    a = red[0]; b = red[32]; c = red[64];
    __syncthreads();
}

// ---------------- softmax mix: register-resident, half in/out, IN PLACE ----------------
__global__ __launch_bounds__(256) void softmax_mix_kernel(
    half* __restrict__ attn, const float* __restrict__ w_mix)
{
    __shared__ float red[96];
    half* p = attn + (size_t)blockIdx.x * 4096;
    int tid = threadIdx.x;

    uint4 u0 = ((const uint4*)p)[tid * 2];
    uint4 u1 = ((const uint4*)p)[tid * 2 + 1];
    float v[16];
    {
        const half2* h0 = (const half2*)&u0;
        const half2* h1 = (const half2*)&u1;
        #pragma unroll
        for (int k = 0; k < 4; k++) {
            float2 f0 = __half22float2(h0[k]);
            float2 f1 = __half22float2(h1[k]);
            v[2 * k] = f0.x; v[2 * k + 1] = f0.y;
            v[8 + 2 * k] = f1.x; v[8 + 2 * k + 1] = f1.y;
        }
    }

    float lmax = -1e30f;
    #pragma unroll
    for (int k = 0; k < 16; k++) lmax = fmaxf(lmax, v[k]);
    float m1 = block_reduce_max(lmax, red);
    float m2 = fmaxf(m1, 0.f);
    float Cneg = fast_exp(-m2);

    float z1 = 0.f, z2p = 0.f, nneg = 0.f;
    #pragma unroll
    for (int k = 0; k < 16; k++) {
        float x = v[k];
        float e1 = fast_exp(x - m1);
        bool pos = x > 0.f;
        z1 += e1;
        if (pos) z2p += e1; else nneg += 1.f;
        v[k] = pos ? e1 : -e1;
    }
    block_reduce_sum3(z1, z2p, nneg, red);
    float Z1 = z1;
    float Z2 = z2p + nneg * Cneg;

    float ew0 = fast_exp(w_mix[0]), ew1 = fast_exp(w_mix[1]);
    float inv = 1.f / (ew0 + ew1);
    float iz1 = (ew0 * inv) / Z1;
    float iz2 = (ew1 * inv) / Z2;
    float Cn2 = Cneg * iz2;

    float za = 0.f;
    #pragma unroll
    for (int k = 0; k < 16; k++) {
        float se = v[k];
        float e1 = fabsf(se);
        float A = (se > 0.f) ? e1 * (iz1 + iz2) : fmaf(e1, iz1, Cn2);
        float e = fast_exp(A);
        v[k] = e;
        za += e;
    }
    float ZA = block_reduce_sum(za, red);
    float izA = 1.f / ZA;

    half2 o[8];
    #pragma unroll
    for (int k = 0; k < 8; k++)
        o[k] = __floats2half2_rn(v[2 * k] * izA, v[2 * k + 1] * izA);
    ((uint4*)p)[tid * 2]     = *(uint4*)&o[0];
    ((uint4*)p)[tid * 2 + 1] = *(uint4*)&o[4];
}

// ---------------- finalize (register-resident): out = stdT * mvn(content) + meanT ----------------
__global__ __launch_bounds__(256) void finalize_kernel(
    const float* __restrict__ content, const float* __restrict__ meanT,
    const float* __restrict__ stdT, float* __restrict__ out)
{
    __shared__ float red[64];
    int c = blockIdx.x, b = blockIdx.y;
    size_t off = ((size_t)b * 512 + c) * 4096;
    const float4* x4 = (const float4*)(content + off);
    int tid = threadIdx.x;

    float v[16];
    float s = 0.f, ss = 0.f;
    #pragma unroll
    for (int k = 0; k < 4; k++) {
        float4 f = x4[tid * 4 + k];
        v[4 * k] = f.x; v[4 * k + 1] = f.y; v[4 * k + 2] = f.z; v[4 * k + 3] = f.w;
        s += f.x + f.y + f.z + f.w;
        ss += f.x * f.x + f.y * f.y + f.z * f.z + f.w * f.w;
    }
    block_reduce_sum2(s, ss, red);
    float mu = s * (1.f / 4096.f);
    float var = (ss - 4096.f * mu * mu) * (1.f / 4095.f);
    float rstd = rsqrtf(var + 1e-5f);

    const float4* m4 = (const float4*)(meanT + off);
    const float4* s4 = (const float4*)(stdT + off);
    float4* o4 = (float4*)(out + off);
    #pragma unroll
    for (int k = 0; k < 4; k++) {
        float4 mn = m4[tid * 4 + k];
        float4 sd = s4[tid * 4 + k];
        float4 o;
        o.x = sd.x * ((v[4 * k]     - mu) * rstd) + mn.x;
        o.y = sd.y * ((v[4 * k + 1] - mu) * rstd) + mn.y;
        o.z = sd.z * ((v[4 * k + 2] - mu) * rstd) + mn.z;
        o.w = sd.w * ((v[4 * k + 3] - mu) * rstd) + mn.w;
        o4[tid * 4 + k] = o;
    }
}

// ---------------- launch ----------------
extern "C" void kernel_launch(void* const* d_in, const int* in_sizes, int n_in,
                              void* d_out, int out_size)
{
    const float* content     = (const float*)d_in[0];
    const float* style       = (const float*)d_in[1];
    const float* content_key = (const float*)d_in[2];
    const float* style_key   = (const float*)d_in[3];
    const float* f_w = (const float*)d_in[4];
    const float* f_b = (const float*)d_in[5];
    const float* g_w = (const float*)d_in[6];
    const float* g_b = (const float*)d_in[7];
    const float* h_w = (const float*)d_in[8];
    const float* h_b = (const float*)d_in[9];
    const float* w_mix = (const float*)d_in[10];
    float* out = (float*)d_out;

    void *p;
    cudaGetSymbolAddress(&p, g_attn4);  half*  attn = (half*)p;   // logits & S, in place
    cudaGetSymbolAddress(&p, g_xth4);   half*  XTh  = (half*)p;
    cudaGetSymbolAddress(&p, g_xtl4);   half*  XTl  = (half*)p;
    cudaGetSymbolAddress(&p, g_wh4);    half*  Wh   = (half*)p;
    cudaGetSymbolAddress(&p, g_Fh4);    half*  Fh   = (half*)p;
    cudaGetSymbolAddress(&p, g_Gh4);    half*  Gh   = (half*)p;
    cudaGetSymbolAddress(&p, g_Hcat4);  half*  Hcat = (half*)p;
    cudaGetSymbolAddress(&p, g_meanT4); float* meanT= (float*)p;
    cudaGetSymbolAddress(&p, g_stdT4);  float* stdT = (float*)p;

    const size_t XN = 4ull * 4096 * 512;
    const size_t WN = 512ull * 512;

    const int SM2 = 2 * 3 * (128 * 144);   // 110592 (TERMS=2, KCH=64) — convs
    const int SM1 = 2 * 2 * (128 * 144);   // 73728  (TERMS=1, KCH=64) — attn + meansec
    cudaFuncSetAttribute((gemm16<2,64,1,1>), cudaFuncAttributeMaxDynamicSharedMemorySize, SM2);
    cudaFuncSetAttribute((gemm16<2,64,5,1>), cudaFuncAttributeMaxDynamicSharedMemorySize, SM2);
    cudaFuncSetAttribute((gemm16<1,64,1,0>), cudaFuncAttributeMaxDynamicSharedMemorySize, SM1);
    cudaFuncSetAttribute((gemm16<1,64,3,0>), cudaFuncAttributeMaxDynamicSharedMemorySize, SM1);

    // weights (single launch), input transposes (single launch, 3 inputs x 4 batches)
    weights_to_half<<<dim3(1024, 3), 256>>>(f_w, g_w, h_w, Wh);
    transpose_split_all<<<dim3(128, 16, 12), dim3(32, 8)>>>(content_key, style_key, style,
                                                            XTh, XTl);

    // conv F (fp16 2-term) -> half hi only (attn is 1-term now)
    gemm16<2,64,1,1><<<dim3(4, 32, 4), 256, SM2>>>(XTh + 0 * XN, XTl + 0 * XN,
        Wh + 0 * WN, f_b, nullptr, nullptr, Fh,
        4096, 512, 512, 4096ull * 512, 0);

    // conv G (fp16 2-term) -> half hi only
    gemm16<2,64,1,1><<<dim3(4, 32, 4), 256, SM2>>>(XTh + 1 * XN, XTl + 1 * XN,
        Wh + 1 * WN, g_b, nullptr, nullptr, Gh,
        4096, 512, 512, 4096ull * 512, 0);

    // conv H (fp16 2-term) -> Hcat directly (interleaved (H, H^2) rows)
    gemm16<2,64,5,1><<<dim3(4, 32, 4), 256, SM2>>>(XTh + 2 * XN, XTl + 2 * XN,
        Wh + 2 * WN, h_b, nullptr, nullptr, Hcat,
        4096, 512, 512, 4096ull * 512, 0);

    // attention logits (fp16 1-term: Fh.Gh) -> half attn buffer
    gemm16<1,64,1,0><<<dim3(32, 32, 4), 256, SM1>>>(Fh, nullptr, Gh, nullptr,
        nullptr, nullptr, attn,
        4096, 4096, 512, 4096ull * 512, 4096ull * 512);

    // triple-softmax mix, in place (register-resident)
    softmax_mix_kernel<<<16384, 256>>>(attn, w_mix);

    // mean/second GEMM (fp16, KCH=64) -> meanT/stdT directly
    gemm16<1,64,3,0><<<dim3(8, 32, 4), 256, SM1>>>(attn, nullptr, Hcat, nullptr,
        meanT, stdT, nullptr,
        4096, 1024, 4096, 4096ull * 4096, 1024ull * 4096);

    // finalize (register-resident)
    finalize_kernel<<<dim3(512, 4), 256>>>(content, meanT, stdT, out);
}

// round 15
// speedup vs baseline: 1.8105x; 1.0297x over previous
#include <cuda_runtime.h>
#include <cuda_fp16.h>
#include <math.h>
#include <stdint.h>

// ---------------- scratch (uint4 => 16B alignment for cp.async) ----------------
__device__ uint4 g_attn4 [8388608];    // half attn/S (in-place) [4][4096][4096]
__device__ uint4 g_xth4  [3145728];    // half XT hi, 3 inputs x [4][4096][512]
__device__ uint4 g_xtl4  [3145728];    // half XT lo
__device__ uint4 g_wh4   [49152];      // half W hi, 3 x [512][512]
__device__ uint4 g_Fh4   [1048576];    // half F hi [4][4096][512]
__device__ uint4 g_Gh4   [1048576];    // half G hi
__device__ uint4 g_Hcat4 [2097152];    // half Hcat [4][1024][4096], rows interleaved (H[c],H^2[c])
__device__ uint4 g_meanT4[2097152];    // fp32 [4][512][4096]
__device__ uint4 g_stdT4 [2097152];

// ---------------- helpers ----------------
__device__ __forceinline__ uint32_t smem_u32(const void* p) {
    uint32_t a;
    asm("{ .reg .u64 t; cvta.to.shared.u64 t, %1; cvt.u32.u64 %0, t; }" : "=r"(a) : "l"(p));
    return a;
}
__device__ __forceinline__ void cp16(uint32_t dst, const void* src) {
    asm volatile("cp.async.ca.shared.global [%0], [%1], 16;" :: "r"(dst), "l"(src));
}
__device__ __forceinline__ void ldsm4(uint32_t* r, uint32_t addr) {
    asm volatile("ldmatrix.sync.aligned.m8n8.x4.shared.b16 {%0,%1,%2,%3}, [%4];"
        : "=r"(r[0]), "=r"(r[1]), "=r"(r[2]), "=r"(r[3]) : "r"(addr));
}
__device__ __forceinline__ void mma16(float* d, const uint32_t* a, const uint32_t* b) {
    asm volatile("mma.sync.aligned.m16n8k16.row.col.f32.f16.f16.f32 "
        "{%0,%1,%2,%3}, {%4,%5,%6,%7}, {%8,%9}, {%0,%1,%2,%3};"
        : "+f"(d[0]), "+f"(d[1]), "+f"(d[2]), "+f"(d[3])
        : "r"(a[0]), "r"(a[1]), "r"(a[2]), "r"(a[3]), "r"(b[0]), "r"(b[1]));
}

// FMA-only exp (Schraudolph round + deg-6 Taylor of 2^f), rel err ~1.5e-7.
__device__ __forceinline__ float fast_exp(float x) {
    x = fmaxf(x, -80.f);
    float t = x * 1.44269504088896f;
    float z = t + 12582912.f;
    int   i = __float_as_int(z) - 0x4B400000;
    float f = t - (z - 12582912.f);
    float p = 1.53989037e-4f;
    p = fmaf(p, f, 1.33335581e-3f);
    p = fmaf(p, f, 9.61812910e-3f);
    p = fmaf(p, f, 5.55041087e-2f);
    p = fmaf(p, f, 2.40226507e-1f);
    p = fmaf(p, f, 6.93147181e-1f);
    p = fmaf(p, f, 1.0f);
    return __int_as_float(__float_as_int(p) + (i << 23));
}

// FMA-only sqrt via bit-hack rsqrt + 2 Newton iters.
__device__ __forceinline__ float fast_sqrt(float v) {
    float x = fmaxf(v, 1e-30f);
    float xh = 0.5f * x;
    float y = __int_as_float(0x5f375a86 - (__float_as_int(x) >> 1));
    y = y * fmaf(-xh, y * y, 1.5f);
    y = y * fmaf(-xh, y * y, 1.5f);
    return v * y;
}

// ---------------- shared GEMM mainloop (TERMS, KCH compile-time) ----------------
// Computes acc[4][4][4] for C[m0..+128][n0..+128] = sum_k A[m][k]*B[n][k]
// (TERMS=2 adds Al*Bh). Pointers pre-offset to (m0,0)/(n0,0).
template<int TERMS, int KCH>
__device__ __forceinline__ void gemm_core(
    const half* Agh, const half* Agl, const half* Bgh, int K,
    uint32_t sb, int tid, int lane, int wm, int wn, float acc[4][4][4])
{
    constexpr uint32_t ST  = KCH * 2 + 16;
    constexpr uint32_t TL  = 128u * ST;
    constexpr uint32_t BUF = (TERMS == 2 ? 3u : 2u) * TL;
    constexpr int LPR = KCH / 8;
    constexpr int PP  = (128 * LPR) / 256;

    auto stage = [&](int ch, int buf) {
        uint32_t base = sb + buf * BUF;
        #pragma unroll
        for (int it = 0; it < PP; it++) {
            int idx = tid + it * 256;
            int r = idx / LPR, f = idx % LPR;
            uint32_t off = r * ST + f * 16;
            size_t go = (size_t)r * K + ch * KCH + f * 8;
            cp16(base + off, Agh + go);
            cp16(base + TL + off, Bgh + go);
            if (TERMS == 2) cp16(base + 2 * TL + off, Agl + go);
        }
        asm volatile("cp.async.commit_group;" ::: "memory");
    };

    const int t8 = lane >> 3, rr = lane & 7;
    const uint32_t a_off = (uint32_t)((t8 & 1) * 8 + rr) * ST + (t8 >> 1) * 16;
    const uint32_t b_off = (uint32_t)((t8 >> 1) * 8 + rr) * ST + (t8 & 1) * 16;

    const int NC = K / KCH;
    stage(0, 0);
    for (int ch = 0; ch < NC; ch++) {
        const int buf = ch & 1;
        if (ch + 1 < NC) {
            stage(ch + 1, buf ^ 1);
            asm volatile("cp.async.wait_group 1;" ::: "memory");
        } else {
            asm volatile("cp.async.wait_group 0;" ::: "memory");
        }
        __syncthreads();

        const uint32_t ab = sb + buf * BUF;
        const uint32_t bb = ab + TL;

        #pragma unroll
        for (int k16 = 0; k16 < KCH / 16; k16++) {
            const uint32_t kb = k16 * 32;
            uint32_t bhf[4][2];
            #pragma unroll
            for (int pr = 0; pr < 2; pr++) {
                uint32_t r4[4];
                ldsm4(r4, bb + (uint32_t)(wn + pr * 16) * ST + b_off + kb);
                bhf[pr * 2][0] = r4[0]; bhf[pr * 2][1] = r4[1];
                bhf[pr * 2 + 1][0] = r4[2]; bhf[pr * 2 + 1][1] = r4[3];
            }
            #pragma unroll
            for (int im = 0; im < 4; im++) {
                uint32_t af[4];
                ldsm4(af, ab + (uint32_t)(wm + im * 16) * ST + a_off + kb);
                #pragma unroll
                for (int jn = 0; jn < 4; jn++)
                    mma16(acc[im][jn], af, bhf[jn]);
                if (TERMS == 2) {
                    uint32_t alf[4];
                    ldsm4(alf, ab + 2 * TL + (uint32_t)(wm + im * 16) * ST + a_off + kb);
                    #pragma unroll
                    for (int jn = 0; jn < 4; jn++)
                        mma16(acc[im][jn], alf, bhf[jn]);
                }
            }
        }
        __syncthreads();
    }
}

// ---------------- fused conv3: all three convs in one launch ----------------
// grid.z = 12: inp = z>>2 (0=F,1=G,2=H), b = z&3. TERMS=2, KCH=64.
// inp 0/1 -> half output [b][4096][512] (+bias); inp 2 -> Hcat interleaved.
__global__ __launch_bounds__(256, 2) void conv3_kernel(
    const half* __restrict__ XTh, const half* __restrict__ XTl,
    const half* __restrict__ Wh,
    const float* __restrict__ f_b, const float* __restrict__ g_b,
    const float* __restrict__ h_b,
    half* __restrict__ Fh, half* __restrict__ Gh, half* __restrict__ Hcat)
{
    extern __shared__ char smem[];
    const int tid = threadIdx.x, lane = tid & 31, wid = tid >> 5;
    const int inp = blockIdx.z >> 2, b = blockIdx.z & 3;
    const int n0 = blockIdx.x * 128, m0 = blockIdx.y * 128;
    const int K = 512, M = 4096;

    const size_t XN = 4ull * 4096 * 512;
    const half* Agh = XTh + inp * XN + (size_t)b * (4096ull * 512) + (size_t)m0 * K;
    const half* Agl = XTl + inp * XN + (size_t)b * (4096ull * 512) + (size_t)m0 * K;
    const half* Bgh = Wh + (size_t)inp * (512ull * 512) + (size_t)n0 * K;
    const float* bias = (inp == 0) ? f_b : (inp == 1) ? g_b : h_b;

    const uint32_t sb = smem_u32(smem);
    const int wm = (wid >> 2) * 64, wn = (wid & 3) * 32;

    float acc[4][4][4];
    #pragma unroll
    for (int i = 0; i < 4; i++)
        #pragma unroll
        for (int j = 0; j < 4; j++)
            #pragma unroll
            for (int r = 0; r < 4; r++) acc[i][j][r] = 0.f;

    gemm_core<2, 64>(Agh, Agl, Bgh, K, sb, tid, lane, wm, wn, acc);

    half* Chf = (inp == 0) ? Fh : Gh;
    #pragma unroll
    for (int im = 0; im < 4; im++) {
        int r = m0 + wm + im * 16 + (lane >> 2);
        #pragma unroll
        for (int jn = 0; jn < 4; jn++) {
            int cc = n0 + wn + jn * 8 + (lane & 3) * 2;
            float b0 = __ldg(&bias[cc]), b1 = __ldg(&bias[cc + 1]);
            float v00 = acc[im][jn][0] + b0, v01 = acc[im][jn][1] + b1;
            float v10 = acc[im][jn][2] + b0, v11 = acc[im][jn][3] + b1;
            if (inp == 2) {
                half* Hc = Hcat + (size_t)b * 1024ull * 4096ull;
                Hc[(size_t)(2 * cc)     * M + r]     = __float2half_rn(v00);
                Hc[(size_t)(2 * cc + 1) * M + r]     = __float2half_rn(v00 * v00);
                Hc[(size_t)(2 * cc + 2) * M + r]     = __float2half_rn(v01);
                Hc[(size_t)(2 * cc + 3) * M + r]     = __float2half_rn(v01 * v01);
                Hc[(size_t)(2 * cc)     * M + r + 8] = __float2half_rn(v10);
                Hc[(size_t)(2 * cc + 1) * M + r + 8] = __float2half_rn(v10 * v10);
                Hc[(size_t)(2 * cc + 2) * M + r + 8] = __float2half_rn(v11);
                Hc[(size_t)(2 * cc + 3) * M + r + 8] = __float2half_rn(v11 * v11);
            } else {
                size_t o0 = (size_t)b * (4096ull * 512) + (size_t)r * 512 + cc;
                size_t o1 = o0 + (size_t)8 * 512;
                *(half2*)(Chf + o0) = __floats2half2_rn(v00, v01);
                *(half2*)(Chf + o1) = __floats2half2_rn(v10, v11);
            }
        }
    }
}

// ---------------- GEMM (TERMS=1): attn + meansec ----------------
// OUTM: 1=half (Chf), 3=mean/std direct (Cf=meanT, Cf2=stdT [b][N/2][M]).
template<int KCH, int OUTM>
__global__ __launch_bounds__(256, 2) void gemm1(
    const half* __restrict__ Ah, const half* __restrict__ Bh,
    float* __restrict__ Cf, float* __restrict__ Cf2, half* __restrict__ Chf,
    int M, int N, int K, size_t sA, size_t sB)
{
    extern __shared__ char smem[];
    const int tid = threadIdx.x, lane = tid & 31, wid = tid >> 5;
    const int b = blockIdx.z;
    const int n0 = blockIdx.x * 128, m0 = blockIdx.y * 128;
    const half* Agh = Ah + (size_t)b * sA + (size_t)m0 * K;
    const half* Bgh = Bh + (size_t)b * sB + (size_t)n0 * K;

    const uint32_t sb = smem_u32(smem);
    const int wm = (wid >> 2) * 64, wn = (wid & 3) * 32;

    float acc[4][4][4];
    #pragma unroll
    for (int i = 0; i < 4; i++)
        #pragma unroll
        for (int j = 0; j < 4; j++)
            #pragma unroll
            for (int r = 0; r < 4; r++) acc[i][j][r] = 0.f;

    gemm_core<1, KCH>(Agh, nullptr, Bgh, K, sb, tid, lane, wm, wn, acc);

    #pragma unroll
    for (int im = 0; im < 4; im++) {
        int r = m0 + wm + im * 16 + (lane >> 2);
        #pragma unroll
        for (int jn = 0; jn < 4; jn++) {
            int cc = n0 + wn + jn * 8 + (lane & 3) * 2;
            float v00 = acc[im][jn][0], v01 = acc[im][jn][1];
            float v10 = acc[im][jn][2], v11 = acc[im][jn][3];
            if constexpr (OUTM == 3) {
                size_t base = ((size_t)b * (N >> 1) + (cc >> 1)) * (size_t)M;
                Cf [base + r]     = v00;
                Cf2[base + r]     = fast_sqrt(fmaxf(v01 - v00 * v00, 0.f));
                Cf [base + r + 8] = v10;
                Cf2[base + r + 8] = fast_sqrt(fmaxf(v11 - v10 * v10, 0.f));
            } else {
                size_t o0 = (size_t)b * (size_t)M * N + (size_t)r * N + cc;
                size_t o1 = o0 + (size_t)8 * N;
                *(half2*)(Chf + o0) = __floats2half2_rn(v00, v01);
                *(half2*)(Chf + o1) = __floats2half2_rn(v10, v11);
            }
        }
    }
}

// ---------------- transpose+split: fp32 -> hi/lo half, all inputs/batches ----------------
__global__ void transpose_split_all(const float* __restrict__ s0, const float* __restrict__ s1,
                                    const float* __restrict__ s2,
                                    half* __restrict__ dh, half* __restrict__ dl)
{
    __shared__ float t[32][33];
    int inp = blockIdx.z >> 2;
    int b = blockIdx.z & 3;
    const float* src = (inp == 0) ? s0 : (inp == 1) ? s1 : s2;
    const float* s = src + (size_t)b * 512ull * 4096ull;
    size_t dbo = ((size_t)inp * 4 + b) * 512ull * 4096ull;
    int c0 = blockIdx.x * 32, r0 = blockIdx.y * 32;
    int tx = threadIdx.x, ty = threadIdx.y;
    int tid = ty * 32 + tx;
    #pragma unroll
    for (int k = 0; k < 4; k++)
        t[ty + k * 8][tx] = s[(size_t)(r0 + ty + k * 8) * 4096 + c0 + tx];
    __syncthreads();
    #pragma unroll
    for (int ps = 0; ps < 2; ps++) {
        int idx = tid + ps * 256;
        int rr = idx >> 4;
        int cp = idx & 15;
        float v0 = t[2 * cp][rr];
        float v1 = t[2 * cp + 1][rr];
        size_t o = dbo + (size_t)(c0 + rr) * 512 + r0 + 2 * cp;
        half h0 = __float2half_rn(v0), h1 = __float2half_rn(v1);
        *(half2*)(dh + o) = half2(h0, h1);
        *(half2*)(dl + o) = half2(__float2half_rn(v0 - __half2float(h0)),
                                  __float2half_rn(v1 - __half2float(h1)));
    }
}

__global__ void weights_to_half(const float* __restrict__ w0, const float* __restrict__ w1,
                                const float* __restrict__ w2, half* __restrict__ wh)
{
    const float* w = (blockIdx.y == 0) ? w0 : (blockIdx.y == 1) ? w1 : w2;
    int i = blockIdx.x * 256 + threadIdx.x;
    wh[(size_t)blockIdx.y * 262144 + i] = __float2half_rn(w[i]);
}

// ---------------- block reductions ----------------
__device__ __forceinline__ float block_reduce_max(float v, float* red) {
    #pragma unroll
    for (int o = 16; o > 0; o >>= 1) v = fmaxf(v, __shfl_xor_sync(0xffffffffu, v, o));
    int wid = threadIdx.x >> 5, lid = threadIdx.x & 31;
    if (lid == 0) red[wid] = v;
    __syncthreads();
    if (wid == 0) {
        v = (lid < 8) ? red[lid] : -1e30f;
        #pragma unroll
        for (int o = 4; o > 0; o >>= 1) v = fmaxf(v, __shfl_xor_sync(0xffffffffu, v, o));
        if (lid == 0) red[0] = v;
    }
    __syncthreads();
    float r = red[0];
    __syncthreads();
    return r;
}
__device__ __forceinline__ float block_reduce_sum(float v, float* red) {
    #pragma unroll
    for (int o = 16; o > 0; o >>= 1) v += __shfl_xor_sync(0xffffffffu, v, o);
    int wid = threadIdx.x >> 5, lid = threadIdx.x & 31;
    if (lid == 0) red[wid] = v;
    __syncthreads();
    if (wid == 0) {
        v = (lid < 8) ? red[lid] : 0.f;
        #pragma unroll
        for (int o = 4; o > 0; o >>= 1) v += __shfl_xor_sync(0xffffffffu, v, o);
        if (lid == 0) red[0] = v;
    }
    __syncthreads();
    float r = red[0];
    __syncthreads();
    return r;
}
__device__ __forceinline__ void block_reduce_sum2(float& a, float& b, float* red) {
    #pragma unroll
    for (int o = 16; o > 0; o >>= 1) {
        a += __shfl_xor_sync(0xffffffffu, a, o);
        b += __shfl_xor_sync(0xffffffffu, b, o);
    }
    int wid = threadIdx.x >> 5, lid = threadIdx.x & 31;
    if (lid == 0) { red[wid] = a; red[32 + wid] = b; }
    __syncthreads();
    if (wid == 0) {
        a = (lid < 8) ? red[lid] : 0.f;
        b = (lid < 8) ? red[32 + lid] : 0.f;
        #pragma unroll
        for (int o = 4; o > 0; o >>= 1) {
            a += __shfl_xor_sync(0xffffffffu, a, o);
            b += __shfl_xor_sync(0xffffffffu, b, o);
        }
        if (lid == 0) { red[0] = a; red[32] = b; }
    }
    __syncthreads();
    a = red[0]; b = red[32];
    __syncthreads();
}
__device__ __forceinline__ void block_reduce_sum3(float& a, float& b, float& c, float* red) {
    #pragma unroll
    for (int o = 16; o > 0; o >>= 1) {
        a += __shfl_xor_sync(0xffffffffu, a, o);
        b += __shfl_xor_sync(0xffffffffu, b, o);
        c += __shfl_xor_sync(0xffffffffu, c, o);
    }
    int wid = threadIdx.x >> 5, lid = threadIdx.x & 31;
    if (lid == 0) { red[wid] = a; red[32 + wid] = b; red[64 + wid] = c; }
    __syncthreads();
    if (wid == 0) {
        a = (lid < 8) ? red[lid] : 0.f;
        b = (lid < 8) ? red[32 + lid] : 0.f;
        c = (lid < 8) ? red[64 + lid] : 0.f;
        #pragma unroll
        for (int o = 4; o > 0; o >>= 1) {
            a += __shfl_xor_sync(0xffffffffu, a, o);
            b += __shfl_xor_sync(0xffffffffu, b, o);
            c += __shfl_xor_sync(0xffffffffu, c, o);
        }
        if (lid == 0) { red[0] = a; red[32] = b; red[64] = c; }
    }
    __syncthreads();
    a = red[0]; b = red[32]; c = red[64];
    __syncthreads();
}

// ---------------- softmax mix: register-resident, half in/out, IN PLACE ----------------
__global__ __launch_bounds__(256) void softmax_mix_kernel(
    half* __restrict__ attn, const float* __restrict__ w_mix)
{
    __shared__ float red[96];
    half* p = attn + (size_t)blockIdx.x * 4096;
    int tid = threadIdx.x;

    uint4 u0 = ((const uint4*)p)[tid * 2];
    uint4 u1 = ((const uint4*)p)[tid * 2 + 1];
    float v[16];
    {
        const half2* h0 = (const half2*)&u0;
        const half2* h1 = (const half2*)&u1;
        #pragma unroll
        for (int k = 0; k < 4; k++) {
            float2 f0 = __half22float2(h0[k]);
            float2 f1 = __half22float2(h1[k]);
            v[2 * k] = f0.x; v[2 * k + 1] = f0.y;
            v[8 + 2 * k] = f1.x; v[8 + 2 * k + 1] = f1.y;
        }
    }

    float lmax = -1e30f;
    #pragma unroll
    for (int k = 0; k < 16; k++) lmax = fmaxf(lmax, v[k]);
    float m1 = block_reduce_max(lmax, red);
    float m2 = fmaxf(m1, 0.f);
    float Cneg = fast_exp(-m2);

    float z1 = 0.f, z2p = 0.f, nneg = 0.f;
    #pragma unroll
    for (int k = 0; k < 16; k++) {
        float x = v[k];
        float e1 = fast_exp(x - m1);
        bool pos = x > 0.f;
        z1 += e1;
        if (pos) z2p += e1; else nneg += 1.f;
        v[k] = pos ? e1 : -e1;
    }
    block_reduce_sum3(z1, z2p, nneg, red);
    float Z1 = z1;
    float Z2 = z2p + nneg * Cneg;

    float ew0 = fast_exp(w_mix[0]), ew1 = fast_exp(w_mix[1]);
    float inv = 1.f / (ew0 + ew1);
    float iz1 = (ew0 * inv) / Z1;
    float iz2 = (ew1 * inv) / Z2;
    float Cn2 = Cneg * iz2;

    float za = 0.f;
    #pragma unroll
    for (int k = 0; k < 16; k++) {
        float se = v[k];
        float e1 = fabsf(se);
        float A = (se > 0.f) ? e1 * (iz1 + iz2) : fmaf(e1, iz1, Cn2);
        float e = fast_exp(A);
        v[k] = e;
        za += e;
    }
    float ZA = block_reduce_sum(za, red);
    float izA = 1.f / ZA;

    half2 o[8];
    #pragma unroll
    for (int k = 0; k < 8; k++)
        o[k] = __floats2half2_rn(v[2 * k] * izA, v[2 * k + 1] * izA);
    ((uint4*)p)[tid * 2]     = *(uint4*)&o[0];
    ((uint4*)p)[tid * 2 + 1] = *(uint4*)&o[4];
}

// ---------------- finalize (register-resident): out = stdT * mvn(content) + meanT ----------------
__global__ __launch_bounds__(256) void finalize_kernel(
    const float* __restrict__ content, const float* __restrict__ meanT,
    const float* __restrict__ stdT, float* __restrict__ out)
{
    __shared__ float red[64];
    int c = blockIdx.x, b = blockIdx.y;
    size_t off = ((size_t)b * 512 + c) * 4096;
    const float4* x4 = (const float4*)(content + off);
    int tid = threadIdx.x;

    float v[16];
    float s = 0.f, ss = 0.f;
    #pragma unroll
    for (int k = 0; k < 4; k++) {
        float4 f = x4[tid * 4 + k];
        v[4 * k] = f.x; v[4 * k + 1] = f.y; v[4 * k + 2] = f.z; v[4 * k + 3] = f.w;
        s += f.x + f.y + f.z + f.w;
        ss += f.x * f.x + f.y * f.y + f.z * f.z + f.w * f.w;
    }
    block_reduce_sum2(s, ss, red);
    float mu = s * (1.f / 4096.f);
    float var = (ss - 4096.f * mu * mu) * (1.f / 4095.f);
    float rstd = rsqrtf(var + 1e-5f);

    const float4* m4 = (const float4*)(meanT + off);
    const float4* s4 = (const float4*)(stdT + off);
    float4* o4 = (float4*)(out + off);
    #pragma unroll
    for (int k = 0; k < 4; k++) {
        float4 mn = m4[tid * 4 + k];
        float4 sd = s4[tid * 4 + k];
        float4 o;
        o.x = sd.x * ((v[4 * k]     - mu) * rstd) + mn.x;
        o.y = sd.y * ((v[4 * k + 1] - mu) * rstd) + mn.y;
        o.z = sd.z * ((v[4 * k + 2] - mu) * rstd) + mn.z;
        o.w = sd.w * ((v[4 * k + 3] - mu) * rstd) + mn.w;
        o4[tid * 4 + k] = o;
    }
}

// ---------------- launch ----------------
extern "C" void kernel_launch(void* const* d_in, const int* in_sizes, int n_in,
                              void* d_out, int out_size)
{
    const float* content     = (const float*)d_in[0];
    const float* style       = (const float*)d_in[1];
    const float* content_key = (const float*)d_in[2];
    const float* style_key   = (const float*)d_in[3];
    const float* f_w = (const float*)d_in[4];
    const float* f_b = (const float*)d_in[5];
    const float* g_w = (const float*)d_in[6];
    const float* g_b = (const float*)d_in[7];
    const float* h_w = (const float*)d_in[8];
    const float* h_b = (const float*)d_in[9];
    const float* w_mix = (const float*)d_in[10];
    float* out = (float*)d_out;

    void *p;
    cudaGetSymbolAddress(&p, g_attn4);  half*  attn = (half*)p;   // logits & S, in place
    cudaGetSymbolAddress(&p, g_xth4);   half*  XTh  = (half*)p;
    cudaGetSymbolAddress(&p, g_xtl4);   half*  XTl  = (half*)p;
    cudaGetSymbolAddress(&p, g_wh4);    half*  Wh   = (half*)p;
    cudaGetSymbolAddress(&p, g_Fh4);    half*  Fh   = (half*)p;
    cudaGetSymbolAddress(&p, g_Gh4);    half*  Gh   = (half*)p;
    cudaGetSymbolAddress(&p, g_Hcat4);  half*  Hcat = (half*)p;
    cudaGetSymbolAddress(&p, g_meanT4); float* meanT= (float*)p;
    cudaGetSymbolAddress(&p, g_stdT4);  float* stdT = (float*)p;

    const int SM2 = 2 * 3 * (128 * 144);   // 110592 (TERMS=2, KCH=64) — conv3
    const int SM1 = 2 * 2 * (128 * 144);   // 73728  (TERMS=1, KCH=64) — attn + meansec
    cudaFuncSetAttribute(conv3_kernel, cudaFuncAttributeMaxDynamicSharedMemorySize, SM2);
    cudaFuncSetAttribute((gemm1<64,1>), cudaFuncAttributeMaxDynamicSharedMemorySize, SM1);
    cudaFuncSetAttribute((gemm1<64,3>), cudaFuncAttributeMaxDynamicSharedMemorySize, SM1);

    // prep (2 launches)
    weights_to_half<<<dim3(1024, 3), 256>>>(f_w, g_w, h_w, Wh);
    transpose_split_all<<<dim3(128, 16, 12), dim3(32, 8)>>>(content_key, style_key, style,
                                                            XTh, XTl);

    // all three convs in ONE launch (fp16 2-term); F,G -> half hi; H -> Hcat
    conv3_kernel<<<dim3(4, 32, 12), 256, SM2>>>(XTh, XTl, Wh, f_b, g_b, h_b, Fh, Gh, Hcat);

    // attention logits (fp16 1-term: Fh.Gh) -> half attn buffer
    gemm1<64,1><<<dim3(32, 32, 4), 256, SM1>>>(Fh, Gh, nullptr, nullptr, attn,
        4096, 4096, 512, 4096ull * 512, 4096ull * 512);

    // triple-softmax mix, in place (register-resident)
    softmax_mix_kernel<<<16384, 256>>>(attn, w_mix);

    // mean/second GEMM (fp16, KCH=64) -> meanT/stdT directly
    gemm1<64,3><<<dim3(8, 32, 4), 256, SM1>>>(attn, Hcat, meanT, stdT, nullptr,
        4096, 1024, 4096, 4096ull * 4096, 1024ull * 4096);

    // finalize (register-resident)
    finalize_kernel<<<dim3(512, 4), 256>>>(content, meanT, stdT, out);
}